// round 13
// baseline (speedup 1.0000x reference)
#include <cuda_runtime.h>
#include <cuda_bf16.h>
#include <math.h>
#include <stdint.h>

#define Bz   32
#define Vz   512
#define Tz   12
#define DGz  20
#define CHz  16
#define HORz 12
#define RFz  13
#define NLz  8
#define EPSz 0.3f

// ---------------- scratch ----------------
__device__ float g_real[Bz*Vz*DGz];
__device__ float g_img [Bz*Vz*DGz];
__device__ float g_iffp[16*Bz*Vz*DGz];
__device__ float g_AA2 [2*Vz*Vz];
__device__ __align__(16) __nv_bfloat16 g_Fh[Bz*Vz*64];
__device__ __align__(16) __nv_bfloat16 g_Fl[Bz*Vz*64];
__device__ __align__(16) __nv_bfloat16 g_Wh[Vz*64];
__device__ __align__(16) __nv_bfloat16 g_Wl[Vz*64];
__device__ float g_bs[Vz];
__device__ __align__(16) __nv_bfloat16 g_Bth[Vz*1024];
__device__ __align__(16) __nv_bfloat16 g_Btl[Vz*1024];
__device__ float g_xa  [Bz*CHz*RFz*Vz];
__device__ float g_xb  [Bz*CHz*RFz*Vz];
__device__ __align__(16) __nv_bfloat16 g_PQh[Bz*CHz*Tz*1024];
__device__ __align__(16) __nv_bfloat16 g_PQl[Bz*CHz*Tz*1024];
__device__ float g_idt [Bz*CHz*Tz*Vz];
__device__ float g_skip[Bz*CHz*Vz];

// ---------------- PTX helpers ----------------
__device__ __forceinline__ void cpasync16(uint32_t s, const void* g) {
    asm volatile("cp.async.cg.shared.global [%0], [%1], 16;\n" :: "r"(s), "l"(g));
}
#define CP_COMMIT() asm volatile("cp.async.commit_group;\n" ::)
#define CP_WAIT0()  asm volatile("cp.async.wait_group 0;\n" ::)
#define CP_WAIT1()  asm volatile("cp.async.wait_group 1;\n" ::)
#define CP_WAIT4()  asm volatile("cp.async.wait_group 4;\n" ::)

#define LDSM4(R, addr) \
    asm volatile("ldmatrix.sync.aligned.m8n8.x4.shared.b16 {%0,%1,%2,%3}, [%4];" \
        : "=r"((R)[0]), "=r"((R)[1]), "=r"((R)[2]), "=r"((R)[3]) : "r"(addr))

#define MMA16816(C, A, B0, B1) \
    asm volatile("mma.sync.aligned.m16n8k16.row.col.f32.bf16.bf16.f32 " \
        "{%0,%1,%2,%3},{%4,%5,%6,%7},{%8,%9},{%0,%1,%2,%3};" \
        : "+f"((C)[0]), "+f"((C)[1]), "+f"((C)[2]), "+f"((C)[3]) \
        : "r"((A)[0]), "r"((A)[1]), "r"((A)[2]), "r"((A)[3]), "r"(B0), "r"(B1))

__device__ __forceinline__ void split2(float a, float b,
                                       __nv_bfloat162& hi, __nv_bfloat162& lo) {
    __nv_bfloat16 ha = __float2bfloat16(a), hb = __float2bfloat16(b);
    hi = __halves2bfloat162(ha, hb);
    lo = __floats2bfloat162_rn(a - __bfloat162float(ha), b - __bfloat162float(hb));
}

// ---------------- K0: DFT(24) + lin projection ----------------
__global__ void __launch_bounds__(64) k_dft(
    const float* __restrict__ input, const float* __restrict__ lW,
    const float* __restrict__ lb, float* __restrict__ re, float* __restrict__ im,
    __nv_bfloat16* __restrict__ Fh, __nv_bfloat16* __restrict__ Fl)
{
    __shared__ float ct[24], st[24];
    if (threadIdx.x < 24) {
        ct[threadIdx.x] = cospif(threadIdx.x / 12.f);
        st[threadIdx.x] = sinpif(threadIdx.x / 12.f);
    }
    __syncthreads();
    int tid = blockIdx.x * 64 + threadIdx.x;
    int b = tid >> 9, v = tid & 511;
    float xr[24];
#pragma unroll
    for (int t = 0; t < 12; t++) {
        int base = ((t * 32 + b) * 512 + v) * 2;
        xr[2 * t] = input[base];
        xr[2 * t + 1] = input[base + 1];
    }
    float fr[24], fi[24];
#pragma unroll
    for (int n = 0; n < 24; n++) {
        float sr = 0.f, si = 0.f;
        int idx = 0;
#pragma unroll
        for (int k = 0; k < 24; k++) {
            sr += xr[k] * ct[idx];
            si -= xr[k] * st[idx];
            idx += n; if (idx >= 24) idx -= 24;
        }
        fr[n] = sr; fi[n] = si;
    }
    int go = (b * 512 + v) * 20;
    int frow = (v * 32 + b) * 64;
#pragma unroll
    for (int d = 0; d < 20; d += 2) {
        float r0 = lb[d], q0 = lb[d], r1 = lb[d + 1], q1 = lb[d + 1];
#pragma unroll
        for (int n = 0; n < 24; n++) {
            float w0 = lW[d * 24 + n], w1 = lW[(d + 1) * 24 + n];
            r0 += fr[n] * w0; q0 += fi[n] * w0;
            r1 += fr[n] * w1; q1 += fi[n] * w1;
        }
        re[go + d] = r0; re[go + d + 1] = r1;
        im[go + d] = q0; im[go + d + 1] = q1;
        float am0 = sqrtf(r0 * r0 + q0 * q0), am1 = sqrtf(r1 * r1 + q1 * q1);
        float ss0 = atanf(r0 / (q0 + 1e-4f)), ss1 = atanf(r1 / (q1 + 1e-4f));
        __nv_bfloat162 h2, l2;
        split2(am0, am1, h2, l2);
        *reinterpret_cast<__nv_bfloat162*>(Fh + frow + 20 + d) = h2;
        *reinterpret_cast<__nv_bfloat162*>(Fl + frow + 20 + d) = l2;
        split2(ss0, ss1, h2, l2);
        *reinterpret_cast<__nv_bfloat162*>(Fh + frow + 40 + d) = h2;
        *reinterpret_cast<__nv_bfloat162*>(Fl + frow + 40 + d) = l2;
    }
    *reinterpret_cast<uint32_t*>(Fh + frow + 60) = 0u;
    *reinterpret_cast<uint32_t*>(Fh + frow + 62) = 0u;
    *reinterpret_cast<uint32_t*>(Fl + frow + 60) = 0u;
    *reinterpret_cast<uint32_t*>(Fl + frow + 62) = 0u;
}

// ---------------- K1a: irfft partials ----------------
__global__ void __launch_bounds__(512) k_iff_part(
    const float* __restrict__ re, const float* __restrict__ im, float* __restrict__ iffp)
{
    __shared__ float ct[512], st[512];
    int m = threadIdx.x;
    ct[m] = cospif(m / 256.f);
    st[m] = sinpif(m / 256.f);
    __syncthreads();
    int b = blockIdx.x, c = blockIdx.y;
    const float* R = re + b * 512 * 20;
    const float* I = im + b * 512 * 20;
    float acc[20];
    if (c == 0) {
        float sg = (m & 1) ? -1.f : 1.f;
#pragma unroll
        for (int d = 0; d < 20; d++) acc[d] = R[d] + sg * R[256 * 20 + d];
    } else {
#pragma unroll
        for (int d = 0; d < 20; d++) acc[d] = 0.f;
    }
    int k0 = (c == 0) ? 1 : c * 16;
    int k1 = c * 16 + 16;
    int idx = (k0 * m) & 511;
    for (int k = k0; k < k1; k++) {
        float cc = 2.f * ct[idx], ss = -2.f * st[idx];
#pragma unroll
        for (int d = 0; d < 20; d++)
            acc[d] += cc * R[k * 20 + d] + ss * I[k * 20 + d];
        idx = (idx + m) & 511;
    }
    int go = ((c * 32 + b) * 512 + m) * 20;
#pragma unroll
    for (int d = 0; d < 20; d++) iffp[go + d] = acc[d];
}

// ---------------- K1b: reduce -> feat cols 0..19 ----------------
__global__ void k_iff_red(const float* __restrict__ iffp,
                          __nv_bfloat16* __restrict__ Fh, __nv_bfloat16* __restrict__ Fl)
{
    int i = blockIdx.x * 256 + threadIdx.x;
    const int Sz = Bz * Vz * DGz;
    int d = i % 20;
    int r = i / 20;
    int v = r & 511, b = r >> 9;
    float s = 0.f;
#pragma unroll
    for (int c = 0; c < 16; c++) s += iffp[c * Sz + i];
    s *= (1.f / 512.f);
    __nv_bfloat16 h = __float2bfloat16(s);
    int o = (v * 32 + b) * 64 + d;
    Fh[o] = h;
    Fl[o] = __float2bfloat16(s - __bfloat162float(h));
}

// ---------------- Wprep (parallel: 16384 threads) ----------------
__global__ void k_wprep(const float* __restrict__ f1W, const float* __restrict__ f1b,
                        const float* __restrict__ f2W, const float* __restrict__ f2b,
                        const float* __restrict__ f3W, const float* __restrict__ f3b,
                        __nv_bfloat16* __restrict__ Wh, __nv_bfloat16* __restrict__ Wl,
                        float* __restrict__ bs)
{
    int t = blockIdx.x * 256 + threadIdx.x;   // 16384
    int w = t >> 5, d = t & 31;
    const float inv3 = 1.f / 3.f;
    if (d < 20) {
        float a = f1W[w * 20 + d] * inv3;
        __nv_bfloat16 h = __float2bfloat16(a);
        Wh[w * 64 + d] = h; Wl[w * 64 + d] = __float2bfloat16(a - __bfloat162float(h));
        a = f2W[w * 20 + d] * inv3;
        h = __float2bfloat16(a);
        Wh[w * 64 + 20 + d] = h; Wl[w * 64 + 20 + d] = __float2bfloat16(a - __bfloat162float(h));
        a = f3W[w * 20 + d] * inv3;
        h = __float2bfloat16(a);
        Wh[w * 64 + 40 + d] = h; Wl[w * 64 + 40 + d] = __float2bfloat16(a - __bfloat162float(h));
    } else if (d < 24) {
        Wh[w * 64 + 40 + d] = __float2bfloat16(0.f);
        Wl[w * 64 + 40 + d] = __float2bfloat16(0.f);
    } else if (d == 24) {
        bs[w] = (f1b[w] + f2b[w] + f3b[w]) * inv3;
    }
}

// ---------------- K2: adj via MMA + sigmoid + batch-reduce ----------------
#define ADJ_SMEM 73728
__global__ void __launch_bounds__(256) k_adjmma(
    const __nv_bfloat16* __restrict__ Fh, const __nv_bfloat16* __restrict__ Fl,
    const __nv_bfloat16* __restrict__ Wh, const __nv_bfloat16* __restrict__ Wl,
    const float* __restrict__ bs, float* __restrict__ AA2, float* __restrict__ adj_out)
{
    extern __shared__ __align__(16) char smem_raw[];
    __shared__ float sbs[128];
    uint32_t sbase = (uint32_t)__cvta_generic_to_shared(smem_raw);
    float* Stile = (float*)smem_raw;
    int t = threadIdx.x;
    int row0 = blockIdx.y * 128, col0 = blockIdx.x * 128;
    if (t < 128) sbs[t] = bs[col0 + t];
#pragma unroll
    for (int i = 0; i < 4; i++) {
        int c = t + i * 256;
        int row = c >> 3, col8 = (c & 7) * 8;
        uint32_t so = (uint32_t)(row * 72 + col8) * 2;
        const __nv_bfloat16* gA = Fh + (size_t)(row0 + row) * 64 + col8;
        const __nv_bfloat16* gB = Wh + (size_t)(col0 + row) * 64 + col8;
        cpasync16(sbase + so,           gA);
        cpasync16(sbase + 18432u + so,  Fl + (gA - Fh));
        cpasync16(sbase + 36864u + so,  gB);
        cpasync16(sbase + 55296u + so,  Wl + (gB - Wh));
    }
    CP_COMMIT();
    CP_WAIT0();
    __syncthreads();

    int warp = t >> 5, lane = t & 31;
    int wm = warp >> 2, wn = warp & 3;
    float acc[4][4][4];
#pragma unroll
    for (int i = 0; i < 4; i++)
#pragma unroll
        for (int j = 0; j < 4; j++)
#pragma unroll
            for (int r = 0; r < 4; r++) acc[i][j][r] = 0.f;

    int ar = lane & 15, ah8 = (lane >> 4) << 3;
    int bq = lane >> 3, br = lane & 7;
    int bro = ((bq >> 1) << 3) + br, bco = (bq & 1) << 3;
    uint32_t aH = sbase, aL = sbase + 18432u, bH = sbase + 36864u, bL = sbase + 55296u;
#pragma unroll
    for (int kc = 0; kc < 4; kc++) {
        uint32_t a_h[4][4], a_l[4][4], b_h[4][2], b_l[4][2];
#pragma unroll
        for (int mf = 0; mf < 4; mf++) {
            uint32_t off = (uint32_t)((wm * 64 + mf * 16 + ar) * 72 + kc * 16 + ah8) * 2;
            LDSM4(a_h[mf], aH + off);
            LDSM4(a_l[mf], aL + off);
        }
#pragma unroll
        for (int nb = 0; nb < 2; nb++) {
            uint32_t off = (uint32_t)((wn * 32 + nb * 16 + bro) * 72 + kc * 16 + bco) * 2;
            uint32_t rh[4], rl[4];
            LDSM4(rh, bH + off);
            LDSM4(rl, bL + off);
            b_h[2 * nb][0] = rh[0]; b_h[2 * nb][1] = rh[1];
            b_h[2 * nb + 1][0] = rh[2]; b_h[2 * nb + 1][1] = rh[3];
            b_l[2 * nb][0] = rl[0]; b_l[2 * nb][1] = rl[1];
            b_l[2 * nb + 1][0] = rl[2]; b_l[2 * nb + 1][1] = rl[3];
        }
#pragma unroll
        for (int mf = 0; mf < 4; mf++)
#pragma unroll
            for (int nf = 0; nf < 4; nf++) {
                MMA16816(acc[mf][nf], a_h[mf], b_h[nf][0], b_h[nf][1]);
                MMA16816(acc[mf][nf], a_h[mf], b_l[nf][0], b_l[nf][1]);
                MMA16816(acc[mf][nf], a_l[mf], b_h[nf][0], b_h[nf][1]);
            }
    }
    __syncthreads();

    int g = lane >> 2, tig = lane & 3;
#pragma unroll
    for (int mf = 0; mf < 4; mf++)
#pragma unroll
        for (int h = 0; h < 2; h++) {
            int r = wm * 64 + mf * 16 + g + h * 8;
#pragma unroll
            for (int nf = 0; nf < 4; nf++) {
                int cl = wn * 32 + nf * 8 + tig * 2;
                float l0 = acc[mf][nf][2 * h]     + sbs[cl];
                float l1 = acc[mf][nf][2 * h + 1] + sbs[cl + 1];
                Stile[r * 132 + cl]     = 1.f / (1.f + __expf(-l0));
                Stile[r * 132 + cl + 1] = 1.f / (1.f + __expf(-l1));
            }
        }
    __syncthreads();

    int v0 = row0 >> 5;
#pragma unroll
    for (int o = t; o < 512; o += 256) {
        int vi = o >> 7, w = o & 127;
        float s = 0.f;
#pragma unroll
        for (int b2 = 0; b2 < 32; b2++) s += Stile[(vi * 32 + b2) * 132 + w];
        float a = 1.f / (1.f + __expf(-s * (1.f / 32.f)));
        int vv = v0 + vi, ww = col0 + w;
        AA2[vv * 512 + ww] = a;
        if (adj_out) adj_out[vv * 512 + ww] = a;
    }
}

// ---------------- SGEMM adj@adj (fp32, small) ----------------
__global__ void __launch_bounds__(256) k_gemm_plain(
    const float* __restrict__ Aq, const float* __restrict__ Bq, float* __restrict__ C, int K)
{
    __shared__ float As[16][65];
    __shared__ float Bs[16][64];
    int t = threadIdx.x;
    int tx = t & 15, ty = t >> 4;
    int row0 = blockIdx.y * 64, col0 = blockIdx.x * 64;
    float acc[4][4] = {};
    int mA = t >> 2, kA = (t & 3) << 2;
    int kB = t >> 4, nB = (t & 15) << 2;
    const float* aptr = Aq + (row0 + mA) * K + kA;
    const float* bptr = Bq + kB * 512 + col0 + nB;
    for (int k0 = 0; k0 < K; k0 += 16) {
        float4 a4 = *reinterpret_cast<const float4*>(aptr + k0);
        float4 b4 = *reinterpret_cast<const float4*>(bptr + k0 * 512);
        As[kA + 0][mA] = a4.x; As[kA + 1][mA] = a4.y;
        As[kA + 2][mA] = a4.z; As[kA + 3][mA] = a4.w;
        *reinterpret_cast<float4*>(&Bs[kB][nB]) = b4;
        __syncthreads();
#pragma unroll
        for (int kk = 0; kk < 16; kk++) {
            float a0 = As[kk][ty * 4 + 0], a1 = As[kk][ty * 4 + 1];
            float a2 = As[kk][ty * 4 + 2], a3 = As[kk][ty * 4 + 3];
            float4 br = *reinterpret_cast<const float4*>(&Bs[kk][tx * 4]);
            acc[0][0] += a0 * br.x; acc[0][1] += a0 * br.y; acc[0][2] += a0 * br.z; acc[0][3] += a0 * br.w;
            acc[1][0] += a1 * br.x; acc[1][1] += a1 * br.y; acc[1][2] += a1 * br.z; acc[1][3] += a1 * br.w;
            acc[2][0] += a2 * br.x; acc[2][1] += a2 * br.y; acc[2][2] += a2 * br.z; acc[2][3] += a2 * br.w;
            acc[3][0] += a3 * br.x; acc[3][1] += a3 * br.y; acc[3][2] += a3 * br.z; acc[3][3] += a3 * br.w;
        }
        __syncthreads();
    }
#pragma unroll
    for (int i = 0; i < 4; i++)
#pragma unroll
        for (int j = 0; j < 4; j++)
            C[(row0 + ty * 4 + i) * 512 + col0 + tx * 4 + j] = acc[i][j];
}

// ---------------- prepB: transpose AA2 [1024x512] -> Bt hi/lo [512x1024] ----------------
__global__ void k_prepB(const float* __restrict__ AA2,
                        __nv_bfloat16* __restrict__ Bth, __nv_bfloat16* __restrict__ Btl)
{
    __shared__ float tile[32][33];
    int k0 = blockIdx.y * 32, n0 = blockIdx.x * 32;
    int tx = threadIdx.x, ty = threadIdx.y;
#pragma unroll
    for (int i = 0; i < 4; i++)
        tile[ty + i * 8][tx] = AA2[(k0 + ty + i * 8) * 512 + n0 + tx];
    __syncthreads();
#pragma unroll
    for (int i = 0; i < 4; i++) {
        int r = ty + i * 8;
        float v = tile[tx][r];
        __nv_bfloat16 hi = __float2bfloat16(v);
        __nv_bfloat16 lo = __float2bfloat16(v - __bfloat162float(hi));
        int o = (n0 + r) * 1024 + k0 + tx;
        Bth[o] = hi; Btl[o] = lo;
    }
}

// ---------------- fused producer (layer 1 computes start conv inline) ----------------
__global__ void __launch_bounds__(256) k_fused(
    const float* __restrict__ x, const float* __restrict__ input,
    const float* __restrict__ sW0, const float* __restrict__ sb0,
    const float* __restrict__ fW, const float* __restrict__ fb,
    const float* __restrict__ gW, const float* __restrict__ gb,
    const float* __restrict__ gcW,
    const float* __restrict__ sW, const float* __restrict__ sb,
    __nv_bfloat16* __restrict__ PQh, __nv_bfloat16* __restrict__ PQl,
    float* __restrict__ idt, float* __restrict__ skip, float* __restrict__ xout,
    int L, int d, int first)
{
    __shared__ float sf[512], sg2[512], sfb[16], sgb[16];
    __shared__ float Pw[256], Qw[256], Ew[256], sWt[256], sbs2[16];
    __shared__ float sst[32], ssb[16];
    int tid = threadIdx.x;
    for (int i = tid; i < 512; i += 256) { sf[i] = fW[i]; sg2[i] = gW[i]; }
    {
        int i = tid;
        int co = i >> 4, ci = i & 15;
        float a0 = gcW[co * 64 + ci];
        float a1 = gcW[co * 64 + 16 + ci];
        float a2 = gcW[co * 64 + 32 + ci];
        float a3 = gcW[co * 64 + 48 + ci];
        Pw[i] = a0 + 2.f * EPSz * a1 - a2 - 2.f * EPSz * a3;
        Qw[i] = a1 + a3;
        Ew[i] = EPSz * (a0 + a2) + EPSz * EPSz * (a1 + a3);
        sWt[i] = sW[i];
    }
    if (tid < 16) { sfb[tid] = fb[tid]; sgb[tid] = gb[tid]; sbs2[tid] = sb[tid]; }
    if (first) {
        if (tid < 32) sst[tid] = sW0[tid];
        if (tid >= 32 && tid < 48) ssb[tid - 32] = sb0[tid - 32];
    }
    __syncthreads();
    int Lp = L - d;
    int b = blockIdx.x / Lp, l = blockIdx.x % Lp;
    int v = tid * 2;
    float2 x0v[16], x1v[16];
    if (first) {
        // layer 1 (d==1): x(l) and x(l+1) computed inline from input + start conv
        float4 in0 = make_float4(0.f, 0.f, 0.f, 0.f), in1;
        bool has0 = (l > 0);
        if (has0)
            in0 = *reinterpret_cast<const float4*>(input + (size_t)(((l - 1) * 32 + b) * 512 + v) * 2);
        in1 = *reinterpret_cast<const float4*>(input + (size_t)((l * 32 + b) * 512 + v) * 2);
#pragma unroll
        for (int ci = 0; ci < 16; ci++) {
            float w0 = sst[ci * 2], w1 = sst[ci * 2 + 1], bb = ssb[ci];
            x0v[ci].x = has0 ? (bb + w0 * in0.x + w1 * in0.y) : bb;
            x0v[ci].y = has0 ? (bb + w0 * in0.z + w1 * in0.w) : bb;
            x1v[ci].x = bb + w0 * in1.x + w1 * in1.y;
            x1v[ci].y = bb + w0 * in1.z + w1 * in1.w;
            // materialize x at position l+1 (positions 1..12; pos 0 never read by k_mma)
            *reinterpret_cast<float2*>(xout + (size_t)((b * 16 + ci) * RFz + l + 1) * 512 + v) = x1v[ci];
        }
    } else {
#pragma unroll
        for (int ci = 0; ci < 16; ci++) {
            const float* xp = x + (size_t)((b * 16 + ci) * L + l) * 512 + v;
            x0v[ci] = *reinterpret_cast<const float2*>(xp);
            x1v[ci] = *reinterpret_cast<const float2*>(xp + d * 512);
        }
    }
    float2 xg[16];
#pragma unroll
    for (int co = 0; co < 16; co++) {
        float f0 = sfb[co], f1 = sfb[co], g0 = sgb[co], g1 = sgb[co];
#pragma unroll
        for (int ci = 0; ci < 16; ci++) {
            int wi = (co * 16 + ci) * 2;
            float w0 = sf[wi], w1 = sf[wi + 1];
            float u0 = sg2[wi], u1 = sg2[wi + 1];
            f0 += w0 * x0v[ci].x + w1 * x1v[ci].x;
            f1 += w0 * x0v[ci].y + w1 * x1v[ci].y;
            g0 += u0 * x0v[ci].x + u1 * x1v[ci].x;
            g1 += u0 * x0v[ci].y + u1 * x1v[ci].y;
        }
        xg[co].x = tanhf(f0) * (1.f / (1.f + __expf(-g0)));
        xg[co].y = tanhf(f1) * (1.f / (1.f + __expf(-g1)));
    }
    if (l == Lp - 1) {
#pragma unroll
        for (int co = 0; co < 16; co++) {
            float a0 = sbs2[co], a1 = sbs2[co];
#pragma unroll
            for (int ci = 0; ci < 16; ci++) {
                a0 += sWt[co * 16 + ci] * xg[ci].x;
                a1 += sWt[co * 16 + ci] * xg[ci].y;
            }
            int si = (b * 16 + co) * 512 + v;
            if (first) { skip[si] = a0; skip[si + 1] = a1; }
            else       { skip[si] += a0; skip[si + 1] += a1; }
        }
    }
#pragma unroll
    for (int co = 0; co < 16; co++) {
        float p0 = 0.f, p1 = 0.f, q0 = 0.f, q1 = 0.f, e0 = 0.f, e1 = 0.f;
#pragma unroll
        for (int ci = 0; ci < 16; ci++) {
            float pw = Pw[co * 16 + ci], qw = Qw[co * 16 + ci], ew = Ew[co * 16 + ci];
            p0 += pw * xg[ci].x; p1 += pw * xg[ci].y;
            q0 += qw * xg[ci].x; q1 += qw * xg[ci].y;
            e0 += ew * xg[ci].x; e1 += ew * xg[ci].y;
        }
        int row = (b * 16 + co) * Lp + l;
        __nv_bfloat162 h2, l2;
        split2(p0, p1, h2, l2);
        *reinterpret_cast<__nv_bfloat162*>(PQh + row * 1024 + v) = h2;
        *reinterpret_cast<__nv_bfloat162*>(PQl + row * 1024 + v) = l2;
        split2(q0, q1, h2, l2);
        *reinterpret_cast<__nv_bfloat162*>(PQh + row * 1024 + 512 + v) = h2;
        *reinterpret_cast<__nv_bfloat162*>(PQl + row * 1024 + 512 + v) = l2;
        *reinterpret_cast<float2*>(idt + row * 512 + v) = make_float2(e0, e1);
    }
}

// ---------------- main MMA GEMM (big layers): 64(M)x128(N) tiles, 3-stage ----------------
// per stage: Ahi[64][40] (5120B) | Alo (5120B) | Bhi[128][40] (10240B) | Blo (10240B) = 30720B
#define MMA_SMEM_BYTES 92160

__global__ void __launch_bounds__(256) k_mma(
    const __nv_bfloat16* __restrict__ Ah, const __nv_bfloat16* __restrict__ Al,
    const __nv_bfloat16* __restrict__ Bh, const __nv_bfloat16* __restrict__ Bl,
    const float* __restrict__ idt, const float* __restrict__ xprev, float* __restrict__ xnew,
    const float* __restrict__ gcb, const float* __restrict__ bng, const float* __restrict__ bnb,
    const float* __restrict__ bnm, const float* __restrict__ bnv,
    int Lp, int dil, int Lprev)
{
    extern __shared__ __align__(16) char smem_raw[];
    __shared__ float s_scale[16], s_shift[16], s_gb[16];
    uint32_t sbase = (uint32_t)__cvta_generic_to_shared(smem_raw);

    int t = threadIdx.x;
    if (t < 16) {
        float sc = bng[t] * rsqrtf(bnv[t] + 1e-5f);
        s_scale[t] = sc;
        s_shift[t] = bnb[t] - bnm[t] * sc;
        s_gb[t] = gcb[t];
    }

    int row0 = blockIdx.y * 64, col0 = blockIdx.x * 128;
    int warp = t >> 5, lane = t & 31;
    int wm = warp >> 2, wn = warp & 3;      // 2 x 4; warp tile 32(M) x 32(N)

    float acc[2][4][4];
#pragma unroll
    for (int i = 0; i < 2; i++)
#pragma unroll
        for (int j = 0; j < 4; j++)
#pragma unroll
            for (int r = 0; r < 4; r++) acc[i][j][r] = 0.f;

    int rA = t >> 2, kA = (t & 3) * 8;
    int rB0 = t >> 2, kB0 = (t & 3) * 8;
    int rB1 = 64 + (t >> 2), kB1 = (t & 3) * 8;

#define LOAD_STAGE(S, K0)                                                          \
    do {                                                                           \
        uint32_t sb_ = sbase + (uint32_t)(S) * 30720u;                             \
        const __nv_bfloat16* ga  = Ah + (size_t)(row0 + rA) * 1024 + (K0) + kA;    \
        const __nv_bfloat16* gb0 = Bh + (size_t)(col0 + rB0) * 1024 + (K0) + kB0;  \
        const __nv_bfloat16* gb1 = Bh + (size_t)(col0 + rB1) * 1024 + (K0) + kB1;  \
        uint32_t sa  = sb_ + (uint32_t)(rA * 40 + kA) * 2;                         \
        uint32_t sb0 = sb_ + 10240u + (uint32_t)(rB0 * 40 + kB0) * 2;              \
        uint32_t sb1 = sb_ + 10240u + (uint32_t)(rB1 * 40 + kB1) * 2;              \
        cpasync16(sa,          ga);                                                \
        cpasync16(sa + 5120u,  Al + (ga - Ah));                                    \
        cpasync16(sb0,          gb0);                                              \
        cpasync16(sb0 + 10240u, Bl + (gb0 - Bh));                                  \
        cpasync16(sb1,          gb1);                                              \
        cpasync16(sb1 + 10240u, Bl + (gb1 - Bh));                                  \
    } while (0)

    LOAD_STAGE(0, 0);
    CP_COMMIT();
    LOAD_STAGE(1, 32);
    CP_COMMIT();

    int ar = lane & 15, ah8 = (lane >> 4) << 3;
    int bq = lane >> 3, br = lane & 7;
    int bro = ((bq >> 1) << 3) + br, bco = (bq & 1) << 3;

    for (int it = 0; it < 32; it++) {
        CP_WAIT1();
        __syncthreads();
        int p = it % 3;
        uint32_t aH = sbase + (uint32_t)p * 30720u;
        uint32_t aL = aH + 5120u;
        uint32_t bH = aH + 10240u;
        uint32_t bL = aH + 20480u;
#pragma unroll
        for (int kc = 0; kc < 2; kc++) {
            uint32_t a_h[2][4], a_l[2][4], b_h[4][2], b_l[4][2];
#pragma unroll
            for (int mf = 0; mf < 2; mf++) {
                uint32_t off = (uint32_t)((wm * 32 + mf * 16 + ar) * 40 + kc * 16 + ah8) * 2;
                LDSM4(a_h[mf], aH + off);
                LDSM4(a_l[mf], aL + off);
            }
#pragma unroll
            for (int nb = 0; nb < 2; nb++) {
                uint32_t off = (uint32_t)((wn * 32 + nb * 16 + bro) * 40 + kc * 16 + bco) * 2;
                uint32_t rh[4], rl[4];
                LDSM4(rh, bH + off);
                LDSM4(rl, bL + off);
                b_h[2 * nb][0] = rh[0]; b_h[2 * nb][1] = rh[1];
                b_h[2 * nb + 1][0] = rh[2]; b_h[2 * nb + 1][1] = rh[3];
                b_l[2 * nb][0] = rl[0]; b_l[2 * nb][1] = rl[1];
                b_l[2 * nb + 1][0] = rl[2]; b_l[2 * nb + 1][1] = rl[3];
            }
#pragma unroll
            for (int mf = 0; mf < 2; mf++)
#pragma unroll
                for (int nf = 0; nf < 4; nf++) {
                    MMA16816(acc[mf][nf], a_h[mf], b_h[nf][0], b_h[nf][1]);
                    MMA16816(acc[mf][nf], a_h[mf], b_l[nf][0], b_l[nf][1]);
                    MMA16816(acc[mf][nf], a_l[mf], b_h[nf][0], b_h[nf][1]);
                }
        }
        if (it < 30) LOAD_STAGE((it + 2) % 3, (it + 2) * 32);
        CP_COMMIT();
    }

    int g = lane >> 2, tig = lane & 3;
#pragma unroll
    for (int mf = 0; mf < 2; mf++) {
#pragma unroll
        for (int h = 0; h < 2; h++) {
            int m = row0 + wm * 32 + mf * 16 + g + h * 8;
            int l = m % Lp;
            int bc = m / Lp;
            int co = bc & 15;
            float scale = s_scale[co], shift = s_shift[co], gb = s_gb[co];
            const float* idp  = idt + (size_t)m * 512;
            const float* resp = xprev + (size_t)(bc * Lprev + l + dil) * 512;
            float* op = xnew + (size_t)m * 512;
#pragma unroll
            for (int nf = 0; nf < 4; nf++) {
                int n = col0 + wn * 32 + nf * 8 + tig * 2;
                float v0 = acc[mf][nf][2 * h]     + idp[n]     + gb + resp[n];
                float v1 = acc[mf][nf][2 * h + 1] + idp[n + 1] + gb + resp[n + 1];
                op[n]     = v0 * scale + shift;
                op[n + 1] = v1 * scale + shift;
            }
        }
    }
}

// ---------------- tail MMA GEMM (small layers, Lp<=4): 32(M)x128(N) tiles, 6-stage ----------------
// per stage: Ahi[32][40] (2560B) | Alo (2560B) | Bhi[128][40] (10240B) | Blo (10240B) = 25600B
#define MMA32_SMEM_BYTES 153600

__global__ void __launch_bounds__(256) k_mma32(
    const __nv_bfloat16* __restrict__ Ah, const __nv_bfloat16* __restrict__ Al,
    const __nv_bfloat16* __restrict__ Bh, const __nv_bfloat16* __restrict__ Bl,
    const float* __restrict__ idt, const float* __restrict__ xprev, float* __restrict__ xnew,
    const float* __restrict__ gcb, const float* __restrict__ bng, const float* __restrict__ bnb,
    const float* __restrict__ bnm, const float* __restrict__ bnv,
    int Lp, int dil, int Lprev)
{
    extern __shared__ __align__(16) char smem_raw[];
    __shared__ float s_scale[16], s_shift[16], s_gb[16];
    uint32_t sbase = (uint32_t)__cvta_generic_to_shared(smem_raw);

    int t = threadIdx.x;
    if (t < 16) {
        float sc = bng[t] * rsqrtf(bnv[t] + 1e-5f);
        s_scale[t] = sc;
        s_shift[t] = bnb[t] - bnm[t] * sc;
        s_gb[t] = gcb[t];
    }

    int row0 = blockIdx.y * 32, col0 = blockIdx.x * 128;
    int warp = t >> 5, lane = t & 31;
    int wn = warp;                       // 1 x 8 warps; warp tile 32(M) x 16(N)

    float acc[2][2][4];
#pragma unroll
    for (int i = 0; i < 2; i++)
#pragma unroll
        for (int j = 0; j < 2; j++)
#pragma unroll
            for (int r = 0; r < 4; r++) acc[i][j][r] = 0.f;

    int tA = t & 127;
    int rA = tA >> 2, kA = (tA & 3) * 8;
    uint32_t aSel = (t < 128) ? 0u : 2560u;
    int rB0 = t >> 2, kB0 = (t & 3) * 8;
    int rB1 = 64 + (t >> 2), kB1 = (t & 3) * 8;

#define LOAD_STAGE32(S, K0)                                                        \
    do {                                                                           \
        uint32_t sb_ = sbase + (uint32_t)(S) * 25600u;                             \
        const __nv_bfloat16* gsrcA = (t < 128) ? Ah : Al;                          \
        cpasync16(sb_ + aSel + (uint32_t)(rA * 40 + kA) * 2,                       \
                  gsrcA + (size_t)(row0 + rA) * 1024 + (K0) + kA);                 \
        const __nv_bfloat16* gb0 = Bh + (size_t)(col0 + rB0) * 1024 + (K0) + kB0;  \
        const __nv_bfloat16* gb1 = Bh + (size_t)(col0 + rB1) * 1024 + (K0) + kB1;  \
        uint32_t sb0 = sb_ + 5120u + (uint32_t)(rB0 * 40 + kB0) * 2;               \
        uint32_t sb1 = sb_ + 5120u + (uint32_t)(rB1 * 40 + kB1) * 2;               \
        cpasync16(sb0,          gb0);                                              \
        cpasync16(sb0 + 10240u, Bl + (gb0 - Bh));                                  \
        cpasync16(sb1,          gb1);                                              \
        cpasync16(sb1 + 10240u, Bl + (gb1 - Bh));                                  \
    } while (0)

    LOAD_STAGE32(0, 0);
    CP_COMMIT();
    LOAD_STAGE32(1, 32);
    CP_COMMIT();
    LOAD_STAGE32(2, 64);
    CP_COMMIT();
    LOAD_STAGE32(3, 96);
    CP_COMMIT();
    LOAD_STAGE32(4, 128);
    CP_COMMIT();

    int ar = lane & 15, ah8 = (lane >> 4) << 3;
    int bq = lane >> 3, br = lane & 7;
    int bro = ((bq >> 1) << 3) + br, bco = (bq & 1) << 3;

    for (int it = 0; it < 32; it++) {
        CP_WAIT4();
        __syncthreads();
        int p = it % 6;
        uint32_t aH = sbase + (uint32_t)p * 25600u;
        uint32_t aL = aH + 2560u;
        uint32_t bH = aH + 5120u;
        uint32_t bL = aH + 15360u;
#pragma unroll
        for (int kc = 0; kc < 2; kc++) {
            uint32_t a_h[2][4], a_l[2][4], b_h[2][2], b_l[2][2];
#pragma unroll
            for (int mf = 0; mf < 2; mf++) {
                uint32_t off = (uint32_t)((mf * 16 + ar) * 40 + kc * 16 + ah8) * 2;
                LDSM4(a_h[mf], aH + off);
                LDSM4(a_l[mf], aL + off);
            }
            {
                uint32_t off = (uint32_t)((wn * 16 + bro) * 40 + kc * 16 + bco) * 2;
                uint32_t rh[4], rl[4];
                LDSM4(rh, bH + off);
                LDSM4(rl, bL + off);
                b_h[0][0] = rh[0]; b_h[0][1] = rh[1];
                b_h[1][0] = rh[2]; b_h[1][1] = rh[3];
                b_l[0][0] = rl[0]; b_l[0][1] = rl[1];
                b_l[1][0] = rl[2]; b_l[1][1] = rl[3];
            }
#pragma unroll
            for (int mf = 0; mf < 2; mf++)
#pragma unroll
                for (int nf = 0; nf < 2; nf++) {
                    MMA16816(acc[mf][nf], a_h[mf], b_h[nf][0], b_h[nf][1]);
                    MMA16816(acc[mf][nf], a_h[mf], b_l[nf][0], b_l[nf][1]);
                    MMA16816(acc[mf][nf], a_l[mf], b_h[nf][0], b_h[nf][1]);
                }
        }
        if (it < 27) LOAD_STAGE32((it + 5) % 6, (it + 5) * 32);
        CP_COMMIT();
    }

    int g = lane >> 2, tig = lane & 3;
#pragma unroll
    for (int mf = 0; mf < 2; mf++) {
#pragma unroll
        for (int h = 0; h < 2; h++) {
            int m = row0 + mf * 16 + g + h * 8;
            int l = m % Lp;
            int bc = m / Lp;
            int co = bc & 15;
            float scale = s_scale[co], shift = s_shift[co], gb = s_gb[co];
            const float* idp  = idt + (size_t)m * 512;
            const float* resp = xprev + (size_t)(bc * Lprev + l + dil) * 512;
            float* op = xnew + (size_t)m * 512;
#pragma unroll
            for (int nf = 0; nf < 2; nf++) {
                int n = col0 + wn * 16 + nf * 8 + tig * 2;
                float v0 = acc[mf][nf][2 * h]     + idp[n]     + gb + resp[n];
                float v1 = acc[mf][nf][2 * h + 1] + idp[n + 1] + gb + resp[n + 1];
                op[n]     = v0 * scale + shift;
                op[n + 1] = v1 * scale + shift;
            }
        }
    }
}

// ---------------- K9: end convs ----------------
__global__ void k_end(const float* __restrict__ skip,
                      const float* __restrict__ w1, const float* __restrict__ b1,
                      const float* __restrict__ w2, const float* __restrict__ b2,
                      float* __restrict__ out)
{
    int tid = blockIdx.x * 128 + threadIdx.x;
    int b = tid >> 9, v = tid & 511;
    float s[16];
#pragma unroll
    for (int c = 0; c < 16; c++) s[c] = fmaxf(skip[(b * 16 + c) * 512 + v], 0.f);
    float e1[16];
#pragma unroll
    for (int c = 0; c < 16; c++) {
        float a = b1[c];
#pragma unroll
        for (int ci = 0; ci < 16; ci++) a += w1[c * 16 + ci] * s[ci];
        e1[c] = fmaxf(a, 0.f);
    }
#pragma unroll
    for (int h = 0; h < 12; h++) {
        float a = b2[h];
#pragma unroll
        for (int c = 0; c < 16; c++) a += w2[h * 16 + c] * e1[c];
        out[(b * 12 + h) * 512 + v] = a;
    }
}

// ======================== host orchestration ========================
extern "C" void kernel_launch(void* const* d_in, const int* in_sizes, int n_in,
                              void* d_out, int out_size)
{
    const float* input  = (const float*)d_in[0];
    const float* startW = (const float*)d_in[1];
    const float* startb = (const float*)d_in[2];
    const float* filtW  = (const float*)d_in[3];
    const float* filtb  = (const float*)d_in[4];
    const float* gateW  = (const float*)d_in[5];
    const float* gateb  = (const float*)d_in[6];
    const float* skipW  = (const float*)d_in[7];
    const float* skipb  = (const float*)d_in[8];
    const float* gconvW = (const float*)d_in[9];
    const float* gconvb = (const float*)d_in[10];
    const float* bng    = (const float*)d_in[11];
    const float* bnb    = (const float*)d_in[12];
    const float* bnm    = (const float*)d_in[13];
    const float* bnv    = (const float*)d_in[14];
    const float* e1W    = (const float*)d_in[15];
    const float* e1b    = (const float*)d_in[16];
    const float* e2W    = (const float*)d_in[17];
    const float* e2b    = (const float*)d_in[18];
    const float* linW   = (const float*)d_in[19];
    const float* linb   = (const float*)d_in[20];
    const float* f1W    = (const float*)d_in[21];
    const float* f1b    = (const float*)d_in[22];
    const float* f2W    = (const float*)d_in[23];
    const float* f2b    = (const float*)d_in[24];
    const float* f3W    = (const float*)d_in[25];
    const float* f3b    = (const float*)d_in[26];
    float* out = (float*)d_out;

    float *p_real, *p_img, *p_iffp, *p_AA2, *p_bs;
    float *p_xa, *p_xb, *p_idt, *p_skip;
    __nv_bfloat16 *p_Fh, *p_Fl, *p_Wh, *p_Wl, *p_Bth, *p_Btl, *p_PQh, *p_PQl;
    cudaGetSymbolAddress((void**)&p_real, g_real);
    cudaGetSymbolAddress((void**)&p_img,  g_img);
    cudaGetSymbolAddress((void**)&p_iffp, g_iffp);
    cudaGetSymbolAddress((void**)&p_AA2,  g_AA2);
    cudaGetSymbolAddress((void**)&p_Fh,   g_Fh);
    cudaGetSymbolAddress((void**)&p_Fl,   g_Fl);
    cudaGetSymbolAddress((void**)&p_Wh,   g_Wh);
    cudaGetSymbolAddress((void**)&p_Wl,   g_Wl);
    cudaGetSymbolAddress((void**)&p_bs,   g_bs);
    cudaGetSymbolAddress((void**)&p_Bth,  g_Bth);
    cudaGetSymbolAddress((void**)&p_Btl,  g_Btl);
    cudaGetSymbolAddress((void**)&p_xa,   g_xa);
    cudaGetSymbolAddress((void**)&p_xb,   g_xb);
    cudaGetSymbolAddress((void**)&p_PQh,  g_PQh);
    cudaGetSymbolAddress((void**)&p_PQl,  g_PQl);
    cudaGetSymbolAddress((void**)&p_idt,  g_idt);
    cudaGetSymbolAddress((void**)&p_skip, g_skip);

    static int smem_set = 0;
    if (!smem_set) {
        cudaFuncSetAttribute(k_mma, cudaFuncAttributeMaxDynamicSharedMemorySize, MMA_SMEM_BYTES);
        cudaFuncSetAttribute(k_mma32, cudaFuncAttributeMaxDynamicSharedMemorySize, MMA32_SMEM_BYTES);
        cudaFuncSetAttribute(k_adjmma, cudaFuncAttributeMaxDynamicSharedMemorySize, ADJ_SMEM);
        smem_set = 1;
    }

    // ---- graph learner ----
    k_dft<<<256, 64>>>(input, linW, linb, p_real, p_img, p_Fh, p_Fl);
    k_iff_part<<<dim3(32, 16), 512>>>(p_real, p_img, p_iffp);
    k_iff_red<<<1280, 256>>>(p_iffp, p_Fh, p_Fl);
    k_wprep<<<64, 256>>>(f1W, f1b, f2W, f2b, f3W, f3b, p_Wh, p_Wl, p_bs);
    float* adj_out = (out_size >= Bz * HORz * Vz + Vz * Vz) ? out + Bz * HORz * Vz : nullptr;
    k_adjmma<<<dim3(4, 128), 256, ADJ_SMEM>>>(p_Fh, p_Fl, p_Wh, p_Wl, p_bs, p_AA2, adj_out);
    k_gemm_plain<<<dim3(8, 8), 256>>>(p_AA2, p_AA2, p_AA2 + Vz * Vz, 512);
    k_prepB<<<dim3(16, 32), dim3(32, 8)>>>(p_AA2, p_Bth, p_Btl);

    // ---- trunk (k_start fused into layer-1 k_fused) ----
    float* xc = p_xa;
    float* xn = p_xb;
    int L = RFz;
    const int dils[NLz] = {1, 2, 1, 2, 1, 2, 1, 2};
    for (int i = 0; i < NLz; i++) {
        int d = dils[i];
        int Lp = L - d;
        k_fused<<<Bz * Lp, 256>>>(xc, input, startW, startb,
                                  filtW + i * 512, filtb + i * 16,
                                  gateW + i * 512, gateb + i * 16,
                                  gconvW + i * 1024, skipW + i * 256, skipb + i * 16,
                                  p_PQh, p_PQl, p_idt, p_skip, p_xa, L, d, (i == 0) ? 1 : 0);
        int M = Bz * CHz * Lp;
        if (Lp > 4) {
            k_mma<<<dim3(4, M / 64), 256, MMA_SMEM_BYTES>>>(p_PQh, p_PQl, p_Bth, p_Btl,
                                                            p_idt, xc, xn,
                                                            gconvb + i * 16, bng + i * 16, bnb + i * 16,
                                                            bnm + i * 16, bnv + i * 16, Lp, d, L);
        } else {
            k_mma32<<<dim3(4, M / 32), 256, MMA32_SMEM_BYTES>>>(p_PQh, p_PQl, p_Bth, p_Btl,
                                                                p_idt, xc, xn,
                                                                gconvb + i * 16, bng + i * 16, bnb + i * 16,
                                                                bnm + i * 16, bnv + i * 16, Lp, d, L);
        }
        float* tmp = xc; xc = xn; xn = tmp;
        L = Lp;
    }

    k_end<<<128, 128>>>(p_skip, e1W, e1b, e2W, e2b, out);
}

// round 14
// speedup vs baseline: 1.0388x; 1.0388x over previous
#include <cuda_runtime.h>
#include <cuda_bf16.h>
#include <math.h>
#include <stdint.h>

#define Bz   32
#define Vz   512
#define Tz   12
#define DGz  20
#define CHz  16
#define HORz 12
#define RFz  13
#define NLz  8
#define EPSz 0.3f

// ---------------- scratch ----------------
__device__ float g_real[Bz*Vz*DGz];
__device__ float g_img [Bz*Vz*DGz];
__device__ float g_iffp[16*Bz*Vz*DGz];
__device__ float g_AA2 [2*Vz*Vz];
__device__ __align__(16) __nv_bfloat16 g_Fh[Bz*Vz*64];
__device__ __align__(16) __nv_bfloat16 g_Fl[Bz*Vz*64];
__device__ __align__(16) __nv_bfloat16 g_Wh[Vz*64];
__device__ __align__(16) __nv_bfloat16 g_Wl[Vz*64];
__device__ float g_bs[Vz];
__device__ __align__(16) __nv_bfloat16 g_Bth[Vz*1024];
__device__ __align__(16) __nv_bfloat16 g_Btl[Vz*1024];
__device__ float g_xa  [Bz*CHz*RFz*Vz];
__device__ float g_xb  [Bz*CHz*RFz*Vz];
__device__ __align__(16) __nv_bfloat16 g_PQh[Bz*CHz*Tz*1024];
__device__ __align__(16) __nv_bfloat16 g_PQl[Bz*CHz*Tz*1024];
__device__ float g_idt [Bz*CHz*Tz*Vz];
__device__ float g_skip[Bz*CHz*Vz];

// ---------------- PTX helpers ----------------
__device__ __forceinline__ void cpasync16(uint32_t s, const void* g) {
    asm volatile("cp.async.cg.shared.global [%0], [%1], 16;\n" :: "r"(s), "l"(g));
}
#define CP_COMMIT() asm volatile("cp.async.commit_group;\n" ::)
#define CP_WAIT0()  asm volatile("cp.async.wait_group 0;\n" ::)
#define CP_WAIT1()  asm volatile("cp.async.wait_group 1;\n" ::)

#define LDSM4(R, addr) \
    asm volatile("ldmatrix.sync.aligned.m8n8.x4.shared.b16 {%0,%1,%2,%3}, [%4];" \
        : "=r"((R)[0]), "=r"((R)[1]), "=r"((R)[2]), "=r"((R)[3]) : "r"(addr))

#define MMA16816(C, A, B0, B1) \
    asm volatile("mma.sync.aligned.m16n8k16.row.col.f32.bf16.bf16.f32 " \
        "{%0,%1,%2,%3},{%4,%5,%6,%7},{%8,%9},{%0,%1,%2,%3};" \
        : "+f"((C)[0]), "+f"((C)[1]), "+f"((C)[2]), "+f"((C)[3]) \
        : "r"((A)[0]), "r"((A)[1]), "r"((A)[2]), "r"((A)[3]), "r"(B0), "r"(B1))

// packed f32x2 fma: d = a*b + c (per 32-bit lane)
#define FMA2(D, A, B, C) \
    asm("fma.rn.f32x2 %0, %1, %2, %3;" : "=l"(D) : "l"(A), "l"(B), "l"(C))

__device__ __forceinline__ unsigned long long pack2(float a, float b) {
    unsigned long long r;
    asm("mov.b64 %0, {%1, %2};" : "=l"(r) : "f"(a), "f"(b));
    return r;
}
__device__ __forceinline__ void unpack2(unsigned long long p, float& a, float& b) {
    asm("mov.b64 {%0, %1}, %2;" : "=f"(a), "=f"(b) : "l"(p));
}

__device__ __forceinline__ void split2(float a, float b,
                                       __nv_bfloat162& hi, __nv_bfloat162& lo) {
    __nv_bfloat16 ha = __float2bfloat16(a), hb = __float2bfloat16(b);
    hi = __halves2bfloat162(ha, hb);
    lo = __floats2bfloat162_rn(a - __bfloat162float(ha), b - __bfloat162float(hb));
}

// ---------------- K0: DFT(24) + lin projection ----------------
__global__ void __launch_bounds__(64) k_dft(
    const float* __restrict__ input, const float* __restrict__ lW,
    const float* __restrict__ lb, float* __restrict__ re, float* __restrict__ im,
    __nv_bfloat16* __restrict__ Fh, __nv_bfloat16* __restrict__ Fl)
{
    __shared__ float ct[24], st[24];
    if (threadIdx.x < 24) {
        ct[threadIdx.x] = cospif(threadIdx.x / 12.f);
        st[threadIdx.x] = sinpif(threadIdx.x / 12.f);
    }
    __syncthreads();
    int tid = blockIdx.x * 64 + threadIdx.x;
    int b = tid >> 9, v = tid & 511;
    float xr[24];
#pragma unroll
    for (int t = 0; t < 12; t++) {
        int base = ((t * 32 + b) * 512 + v) * 2;
        xr[2 * t] = input[base];
        xr[2 * t + 1] = input[base + 1];
    }
    float fr[24], fi[24];
#pragma unroll
    for (int n = 0; n < 24; n++) {
        float sr = 0.f, si = 0.f;
        int idx = 0;
#pragma unroll
        for (int k = 0; k < 24; k++) {
            sr += xr[k] * ct[idx];
            si -= xr[k] * st[idx];
            idx += n; if (idx >= 24) idx -= 24;
        }
        fr[n] = sr; fi[n] = si;
    }
    int go = (b * 512 + v) * 20;
    int frow = (v * 32 + b) * 64;
#pragma unroll
    for (int d = 0; d < 20; d += 2) {
        float r0 = lb[d], q0 = lb[d], r1 = lb[d + 1], q1 = lb[d + 1];
#pragma unroll
        for (int n = 0; n < 24; n++) {
            float w0 = lW[d * 24 + n], w1 = lW[(d + 1) * 24 + n];
            r0 += fr[n] * w0; q0 += fi[n] * w0;
            r1 += fr[n] * w1; q1 += fi[n] * w1;
        }
        re[go + d] = r0; re[go + d + 1] = r1;
        im[go + d] = q0; im[go + d + 1] = q1;
        float am0 = sqrtf(r0 * r0 + q0 * q0), am1 = sqrtf(r1 * r1 + q1 * q1);
        float ss0 = atanf(r0 / (q0 + 1e-4f)), ss1 = atanf(r1 / (q1 + 1e-4f));
        __nv_bfloat162 h2, l2;
        split2(am0, am1, h2, l2);
        *reinterpret_cast<__nv_bfloat162*>(Fh + frow + 20 + d) = h2;
        *reinterpret_cast<__nv_bfloat162*>(Fl + frow + 20 + d) = l2;
        split2(ss0, ss1, h2, l2);
        *reinterpret_cast<__nv_bfloat162*>(Fh + frow + 40 + d) = h2;
        *reinterpret_cast<__nv_bfloat162*>(Fl + frow + 40 + d) = l2;
    }
    *reinterpret_cast<uint32_t*>(Fh + frow + 60) = 0u;
    *reinterpret_cast<uint32_t*>(Fh + frow + 62) = 0u;
    *reinterpret_cast<uint32_t*>(Fl + frow + 60) = 0u;
    *reinterpret_cast<uint32_t*>(Fl + frow + 62) = 0u;
}

// ---------------- K1a: irfft partials ----------------
__global__ void __launch_bounds__(512) k_iff_part(
    const float* __restrict__ re, const float* __restrict__ im, float* __restrict__ iffp)
{
    __shared__ float ct[512], st[512];
    int m = threadIdx.x;
    ct[m] = cospif(m / 256.f);
    st[m] = sinpif(m / 256.f);
    __syncthreads();
    int b = blockIdx.x, c = blockIdx.y;
    const float* R = re + b * 512 * 20;
    const float* I = im + b * 512 * 20;
    float acc[20];
    if (c == 0) {
        float sg = (m & 1) ? -1.f : 1.f;
#pragma unroll
        for (int d = 0; d < 20; d++) acc[d] = R[d] + sg * R[256 * 20 + d];
    } else {
#pragma unroll
        for (int d = 0; d < 20; d++) acc[d] = 0.f;
    }
    int k0 = (c == 0) ? 1 : c * 16;
    int k1 = c * 16 + 16;
    int idx = (k0 * m) & 511;
    for (int k = k0; k < k1; k++) {
        float cc = 2.f * ct[idx], ss = -2.f * st[idx];
#pragma unroll
        for (int d = 0; d < 20; d++)
            acc[d] += cc * R[k * 20 + d] + ss * I[k * 20 + d];
        idx = (idx + m) & 511;
    }
    int go = ((c * 32 + b) * 512 + m) * 20;
#pragma unroll
    for (int d = 0; d < 20; d++) iffp[go + d] = acc[d];
}

// ---------------- K1b: reduce -> feat cols 0..19 ----------------
__global__ void k_iff_red(const float* __restrict__ iffp,
                          __nv_bfloat16* __restrict__ Fh, __nv_bfloat16* __restrict__ Fl)
{
    int i = blockIdx.x * 256 + threadIdx.x;
    const int Sz = Bz * Vz * DGz;
    int d = i % 20;
    int r = i / 20;
    int v = r & 511, b = r >> 9;
    float s = 0.f;
#pragma unroll
    for (int c = 0; c < 16; c++) s += iffp[c * Sz + i];
    s *= (1.f / 512.f);
    __nv_bfloat16 h = __float2bfloat16(s);
    int o = (v * 32 + b) * 64 + d;
    Fh[o] = h;
    Fl[o] = __float2bfloat16(s - __bfloat162float(h));
}

// ---------------- Wprep (parallel: 16384 threads) ----------------
__global__ void k_wprep(const float* __restrict__ f1W, const float* __restrict__ f1b,
                        const float* __restrict__ f2W, const float* __restrict__ f2b,
                        const float* __restrict__ f3W, const float* __restrict__ f3b,
                        __nv_bfloat16* __restrict__ Wh, __nv_bfloat16* __restrict__ Wl,
                        float* __restrict__ bs)
{
    int t = blockIdx.x * 256 + threadIdx.x;   // 16384
    int w = t >> 5, d = t & 31;
    const float inv3 = 1.f / 3.f;
    if (d < 20) {
        float a = f1W[w * 20 + d] * inv3;
        __nv_bfloat16 h = __float2bfloat16(a);
        Wh[w * 64 + d] = h; Wl[w * 64 + d] = __float2bfloat16(a - __bfloat162float(h));
        a = f2W[w * 20 + d] * inv3;
        h = __float2bfloat16(a);
        Wh[w * 64 + 20 + d] = h; Wl[w * 64 + 20 + d] = __float2bfloat16(a - __bfloat162float(h));
        a = f3W[w * 20 + d] * inv3;
        h = __float2bfloat16(a);
        Wh[w * 64 + 40 + d] = h; Wl[w * 64 + 40 + d] = __float2bfloat16(a - __bfloat162float(h));
    } else if (d < 24) {
        Wh[w * 64 + 40 + d] = __float2bfloat16(0.f);
        Wl[w * 64 + 40 + d] = __float2bfloat16(0.f);
    } else if (d == 24) {
        bs[w] = (f1b[w] + f2b[w] + f3b[w]) * inv3;
    }
}

// ---------------- K2: adj via MMA + sigmoid + batch-reduce ----------------
#define ADJ_SMEM 73728
__global__ void __launch_bounds__(256) k_adjmma(
    const __nv_bfloat16* __restrict__ Fh, const __nv_bfloat16* __restrict__ Fl,
    const __nv_bfloat16* __restrict__ Wh, const __nv_bfloat16* __restrict__ Wl,
    const float* __restrict__ bs, float* __restrict__ AA2, float* __restrict__ adj_out)
{
    extern __shared__ __align__(16) char smem_raw[];
    __shared__ float sbs[128];
    uint32_t sbase = (uint32_t)__cvta_generic_to_shared(smem_raw);
    float* Stile = (float*)smem_raw;
    int t = threadIdx.x;
    int row0 = blockIdx.y * 128, col0 = blockIdx.x * 128;
    if (t < 128) sbs[t] = bs[col0 + t];
#pragma unroll
    for (int i = 0; i < 4; i++) {
        int c = t + i * 256;
        int row = c >> 3, col8 = (c & 7) * 8;
        uint32_t so = (uint32_t)(row * 72 + col8) * 2;
        const __nv_bfloat16* gA = Fh + (size_t)(row0 + row) * 64 + col8;
        const __nv_bfloat16* gB = Wh + (size_t)(col0 + row) * 64 + col8;
        cpasync16(sbase + so,           gA);
        cpasync16(sbase + 18432u + so,  Fl + (gA - Fh));
        cpasync16(sbase + 36864u + so,  gB);
        cpasync16(sbase + 55296u + so,  Wl + (gB - Wh));
    }
    CP_COMMIT();
    CP_WAIT0();
    __syncthreads();

    int warp = t >> 5, lane = t & 31;
    int wm = warp >> 2, wn = warp & 3;
    float acc[4][4][4];
#pragma unroll
    for (int i = 0; i < 4; i++)
#pragma unroll
        for (int j = 0; j < 4; j++)
#pragma unroll
            for (int r = 0; r < 4; r++) acc[i][j][r] = 0.f;

    int ar = lane & 15, ah8 = (lane >> 4) << 3;
    int bq = lane >> 3, br = lane & 7;
    int bro = ((bq >> 1) << 3) + br, bco = (bq & 1) << 3;
    uint32_t aH = sbase, aL = sbase + 18432u, bH = sbase + 36864u, bL = sbase + 55296u;
#pragma unroll
    for (int kc = 0; kc < 4; kc++) {
        uint32_t a_h[4][4], a_l[4][4], b_h[4][2], b_l[4][2];
#pragma unroll
        for (int mf = 0; mf < 4; mf++) {
            uint32_t off = (uint32_t)((wm * 64 + mf * 16 + ar) * 72 + kc * 16 + ah8) * 2;
            LDSM4(a_h[mf], aH + off);
            LDSM4(a_l[mf], aL + off);
        }
#pragma unroll
        for (int nb = 0; nb < 2; nb++) {
            uint32_t off = (uint32_t)((wn * 32 + nb * 16 + bro) * 72 + kc * 16 + bco) * 2;
            uint32_t rh[4], rl[4];
            LDSM4(rh, bH + off);
            LDSM4(rl, bL + off);
            b_h[2 * nb][0] = rh[0]; b_h[2 * nb][1] = rh[1];
            b_h[2 * nb + 1][0] = rh[2]; b_h[2 * nb + 1][1] = rh[3];
            b_l[2 * nb][0] = rl[0]; b_l[2 * nb][1] = rl[1];
            b_l[2 * nb + 1][0] = rl[2]; b_l[2 * nb + 1][1] = rl[3];
        }
#pragma unroll
        for (int mf = 0; mf < 4; mf++)
#pragma unroll
            for (int nf = 0; nf < 4; nf++) {
                MMA16816(acc[mf][nf], a_h[mf], b_h[nf][0], b_h[nf][1]);
                MMA16816(acc[mf][nf], a_h[mf], b_l[nf][0], b_l[nf][1]);
                MMA16816(acc[mf][nf], a_l[mf], b_h[nf][0], b_h[nf][1]);
            }
    }
    __syncthreads();

    int g = lane >> 2, tig = lane & 3;
#pragma unroll
    for (int mf = 0; mf < 4; mf++)
#pragma unroll
        for (int h = 0; h < 2; h++) {
            int r = wm * 64 + mf * 16 + g + h * 8;
#pragma unroll
            for (int nf = 0; nf < 4; nf++) {
                int cl = wn * 32 + nf * 8 + tig * 2;
                float l0 = acc[mf][nf][2 * h]     + sbs[cl];
                float l1 = acc[mf][nf][2 * h + 1] + sbs[cl + 1];
                Stile[r * 132 + cl]     = 1.f / (1.f + __expf(-l0));
                Stile[r * 132 + cl + 1] = 1.f / (1.f + __expf(-l1));
            }
        }
    __syncthreads();

    int v0 = row0 >> 5;
#pragma unroll
    for (int o = t; o < 512; o += 256) {
        int vi = o >> 7, w = o & 127;
        float s = 0.f;
#pragma unroll
        for (int b2 = 0; b2 < 32; b2++) s += Stile[(vi * 32 + b2) * 132 + w];
        float a = 1.f / (1.f + __expf(-s * (1.f / 32.f)));
        int vv = v0 + vi, ww = col0 + w;
        AA2[vv * 512 + ww] = a;
        if (adj_out) adj_out[vv * 512 + ww] = a;
    }
}

// ---------------- SGEMM adj@adj (fp32, small) ----------------
__global__ void __launch_bounds__(256) k_gemm_plain(
    const float* __restrict__ Aq, const float* __restrict__ Bq, float* __restrict__ C, int K)
{
    __shared__ float As[16][65];
    __shared__ float Bs[16][64];
    int t = threadIdx.x;
    int tx = t & 15, ty = t >> 4;
    int row0 = blockIdx.y * 64, col0 = blockIdx.x * 64;
    float acc[4][4] = {};
    int mA = t >> 2, kA = (t & 3) << 2;
    int kB = t >> 4, nB = (t & 15) << 2;
    const float* aptr = Aq + (row0 + mA) * K + kA;
    const float* bptr = Bq + kB * 512 + col0 + nB;
    for (int k0 = 0; k0 < K; k0 += 16) {
        float4 a4 = *reinterpret_cast<const float4*>(aptr + k0);
        float4 b4 = *reinterpret_cast<const float4*>(bptr + k0 * 512);
        As[kA + 0][mA] = a4.x; As[kA + 1][mA] = a4.y;
        As[kA + 2][mA] = a4.z; As[kA + 3][mA] = a4.w;
        *reinterpret_cast<float4*>(&Bs[kB][nB]) = b4;
        __syncthreads();
#pragma unroll
        for (int kk = 0; kk < 16; kk++) {
            float a0 = As[kk][ty * 4 + 0], a1 = As[kk][ty * 4 + 1];
            float a2 = As[kk][ty * 4 + 2], a3 = As[kk][ty * 4 + 3];
            float4 br = *reinterpret_cast<const float4*>(&Bs[kk][tx * 4]);
            acc[0][0] += a0 * br.x; acc[0][1] += a0 * br.y; acc[0][2] += a0 * br.z; acc[0][3] += a0 * br.w;
            acc[1][0] += a1 * br.x; acc[1][1] += a1 * br.y; acc[1][2] += a1 * br.z; acc[1][3] += a1 * br.w;
            acc[2][0] += a2 * br.x; acc[2][1] += a2 * br.y; acc[2][2] += a2 * br.z; acc[2][3] += a2 * br.w;
            acc[3][0] += a3 * br.x; acc[3][1] += a3 * br.y; acc[3][2] += a3 * br.z; acc[3][3] += a3 * br.w;
        }
        __syncthreads();
    }
#pragma unroll
    for (int i = 0; i < 4; i++)
#pragma unroll
        for (int j = 0; j < 4; j++)
            C[(row0 + ty * 4 + i) * 512 + col0 + tx * 4 + j] = acc[i][j];
}

// ---------------- prepB: transpose AA2 [1024x512] -> Bt hi/lo [512x1024] ----------------
__global__ void k_prepB(const float* __restrict__ AA2,
                        __nv_bfloat16* __restrict__ Bth, __nv_bfloat16* __restrict__ Btl)
{
    __shared__ float tile[32][33];
    int k0 = blockIdx.y * 32, n0 = blockIdx.x * 32;
    int tx = threadIdx.x, ty = threadIdx.y;
#pragma unroll
    for (int i = 0; i < 4; i++)
        tile[ty + i * 8][tx] = AA2[(k0 + ty + i * 8) * 512 + n0 + tx];
    __syncthreads();
#pragma unroll
    for (int i = 0; i < 4; i++) {
        int r = ty + i * 8;
        float v = tile[tx][r];
        __nv_bfloat16 hi = __float2bfloat16(v);
        __nv_bfloat16 lo = __float2bfloat16(v - __bfloat162float(hi));
        int o = (n0 + r) * 1024 + k0 + tx;
        Bth[o] = hi; Btl[o] = lo;
    }
}

// ---------------- K4: pad + start 1x1 conv ----------------
__global__ void k_start(const float* __restrict__ input, const float* __restrict__ sW,
                        const float* __restrict__ sb, float* __restrict__ x0)
{
    int idx = blockIdx.x * 256 + threadIdx.x;
    int v = idx & 511;
    int r = idx >> 9;
    int l = r % 13; r /= 13;
    int c = r & 15; int b = r >> 4;
    float val = sb[c];
    if (l > 0) {
        int t = l - 1;
        const float* ip = input + ((t * 32 + b) * 512 + v) * 2;
        val += sW[c * 2] * ip[0] + sW[c * 2 + 1] * ip[1];
    }
    x0[idx] = val;
}

// ---------------- fused producer (f32x2 packed FMA) ----------------
__global__ void __launch_bounds__(256) k_fused(
    const float* __restrict__ x,
    const float* __restrict__ fW, const float* __restrict__ fb,
    const float* __restrict__ gW, const float* __restrict__ gb,
    const float* __restrict__ gcW,
    const float* __restrict__ sW, const float* __restrict__ sb,
    __nv_bfloat16* __restrict__ PQh, __nv_bfloat16* __restrict__ PQl,
    float* __restrict__ idt, float* __restrict__ skip,
    int L, int d, int first)
{
    __shared__ unsigned long long sfp[512], sgp[512];
    __shared__ unsigned long long Pwp[256], Qwp[256], Ewp[256];
    __shared__ float sWt[256], sfb[16], sgb[16], sbs2[16];
    int tid = threadIdx.x;
    for (int i = tid; i < 512; i += 256) {
        float w = fW[i]; sfp[i] = pack2(w, w);
        float u = gW[i]; sgp[i] = pack2(u, u);
    }
    {
        int i = tid;
        int co = i >> 4, ci = i & 15;
        float a0 = gcW[co * 64 + ci];
        float a1 = gcW[co * 64 + 16 + ci];
        float a2 = gcW[co * 64 + 32 + ci];
        float a3 = gcW[co * 64 + 48 + ci];
        float pw = a0 + 2.f * EPSz * a1 - a2 - 2.f * EPSz * a3;
        float qw = a1 + a3;
        float ew = EPSz * (a0 + a2) + EPSz * EPSz * (a1 + a3);
        Pwp[i] = pack2(pw, pw);
        Qwp[i] = pack2(qw, qw);
        Ewp[i] = pack2(ew, ew);
        sWt[i] = sW[i];
    }
    if (tid < 16) { sfb[tid] = fb[tid]; sgb[tid] = gb[tid]; sbs2[tid] = sb[tid]; }
    __syncthreads();
    int Lp = L - d;
    int b = blockIdx.x / Lp, l = blockIdx.x % Lp;
    int v = tid * 2;
    unsigned long long x0p[16], x1p[16];
#pragma unroll
    for (int ci = 0; ci < 16; ci++) {
        const float* xp = x + (size_t)((b * 16 + ci) * L + l) * 512 + v;
        x0p[ci] = *reinterpret_cast<const unsigned long long*>(xp);
        x1p[ci] = *reinterpret_cast<const unsigned long long*>(xp + d * 512);
    }
    unsigned long long xgp[16];
#pragma unroll
    for (int co = 0; co < 16; co++) {
        unsigned long long f = pack2(sfb[co], sfb[co]);
        unsigned long long g = pack2(sgb[co], sgb[co]);
#pragma unroll
        for (int ci = 0; ci < 16; ci++) {
            int wi = (co * 16 + ci) * 2;
            FMA2(f, sfp[wi],     x0p[ci], f);
            FMA2(f, sfp[wi + 1], x1p[ci], f);
            FMA2(g, sgp[wi],     x0p[ci], g);
            FMA2(g, sgp[wi + 1], x1p[ci], g);
        }
        float f0, f1, g0, g1;
        unpack2(f, f0, f1);
        unpack2(g, g0, g1);
        float xg0 = tanhf(f0) * (1.f / (1.f + __expf(-g0)));
        float xg1 = tanhf(f1) * (1.f / (1.f + __expf(-g1)));
        xgp[co] = pack2(xg0, xg1);
    }
    if (l == Lp - 1) {
#pragma unroll
        for (int co = 0; co < 16; co++) {
            unsigned long long a = pack2(sbs2[co], sbs2[co]);
#pragma unroll
            for (int ci = 0; ci < 16; ci++) {
                unsigned long long wv = pack2(sWt[co * 16 + ci], sWt[co * 16 + ci]);
                FMA2(a, wv, xgp[ci], a);
            }
            float a0, a1;
            unpack2(a, a0, a1);
            int si = (b * 16 + co) * 512 + v;
            if (first) { skip[si] = a0; skip[si + 1] = a1; }
            else       { skip[si] += a0; skip[si + 1] += a1; }
        }
    }
#pragma unroll
    for (int co = 0; co < 16; co++) {
        unsigned long long p = 0ull, q = 0ull, e = 0ull;
#pragma unroll
        for (int ci = 0; ci < 16; ci++) {
            int wi = co * 16 + ci;
            FMA2(p, Pwp[wi], xgp[ci], p);
            FMA2(q, Qwp[wi], xgp[ci], q);
            FMA2(e, Ewp[wi], xgp[ci], e);
        }
        float p0, p1, q0, q1, e0, e1;
        unpack2(p, p0, p1);
        unpack2(q, q0, q1);
        unpack2(e, e0, e1);
        int row = (b * 16 + co) * Lp + l;
        __nv_bfloat162 h2, l2;
        split2(p0, p1, h2, l2);
        *reinterpret_cast<__nv_bfloat162*>(PQh + row * 1024 + v) = h2;
        *reinterpret_cast<__nv_bfloat162*>(PQl + row * 1024 + v) = l2;
        split2(q0, q1, h2, l2);
        *reinterpret_cast<__nv_bfloat162*>(PQh + row * 1024 + 512 + v) = h2;
        *reinterpret_cast<__nv_bfloat162*>(PQl + row * 1024 + 512 + v) = l2;
        *reinterpret_cast<float2*>(idt + row * 512 + v) = make_float2(e0, e1);
    }
}

// ---------------- main MMA GEMM (big layers): 64(M)x128(N) tiles, 3-stage ----------------
#define MMA_SMEM_BYTES 92160

__global__ void __launch_bounds__(256) k_mma(
    const __nv_bfloat16* __restrict__ Ah, const __nv_bfloat16* __restrict__ Al,
    const __nv_bfloat16* __restrict__ Bh, const __nv_bfloat16* __restrict__ Bl,
    const float* __restrict__ idt, const float* __restrict__ xprev, float* __restrict__ xnew,
    const float* __restrict__ gcb, const float* __restrict__ bng, const float* __restrict__ bnb,
    const float* __restrict__ bnm, const float* __restrict__ bnv,
    int Lp, int dil, int Lprev)
{
    extern __shared__ __align__(16) char smem_raw[];
    __shared__ float s_scale[16], s_shift[16], s_gb[16];
    uint32_t sbase = (uint32_t)__cvta_generic_to_shared(smem_raw);

    int t = threadIdx.x;
    if (t < 16) {
        float sc = bng[t] * rsqrtf(bnv[t] + 1e-5f);
        s_scale[t] = sc;
        s_shift[t] = bnb[t] - bnm[t] * sc;
        s_gb[t] = gcb[t];
    }

    int row0 = blockIdx.y * 64, col0 = blockIdx.x * 128;
    int warp = t >> 5, lane = t & 31;
    int wm = warp >> 2, wn = warp & 3;

    float acc[2][4][4];
#pragma unroll
    for (int i = 0; i < 2; i++)
#pragma unroll
        for (int j = 0; j < 4; j++)
#pragma unroll
            for (int r = 0; r < 4; r++) acc[i][j][r] = 0.f;

    int rA = t >> 2, kA = (t & 3) * 8;
    int rB0 = t >> 2, kB0 = (t & 3) * 8;
    int rB1 = 64 + (t >> 2), kB1 = (t & 3) * 8;

#define LOAD_STAGE(S, K0)                                                          \
    do {                                                                           \
        uint32_t sb_ = sbase + (uint32_t)(S) * 30720u;                             \
        const __nv_bfloat16* ga  = Ah + (size_t)(row0 + rA) * 1024 + (K0) + kA;    \
        const __nv_bfloat16* gb0 = Bh + (size_t)(col0 + rB0) * 1024 + (K0) + kB0;  \
        const __nv_bfloat16* gb1 = Bh + (size_t)(col0 + rB1) * 1024 + (K0) + kB1;  \
        uint32_t sa  = sb_ + (uint32_t)(rA * 40 + kA) * 2;                         \
        uint32_t sb0 = sb_ + 10240u + (uint32_t)(rB0 * 40 + kB0) * 2;              \
        uint32_t sb1 = sb_ + 10240u + (uint32_t)(rB1 * 40 + kB1) * 2;              \
        cpasync16(sa,          ga);                                                \
        cpasync16(sa + 5120u,  Al + (ga - Ah));                                    \
        cpasync16(sb0,          gb0);                                              \
        cpasync16(sb0 + 10240u, Bl + (gb0 - Bh));                                  \
        cpasync16(sb1,          gb1);                                              \
        cpasync16(sb1 + 10240u, Bl + (gb1 - Bh));                                  \
    } while (0)

    LOAD_STAGE(0, 0);
    CP_COMMIT();
    LOAD_STAGE(1, 32);
    CP_COMMIT();

    int ar = lane & 15, ah8 = (lane >> 4) << 3;
    int bq = lane >> 3, br = lane & 7;
    int bro = ((bq >> 1) << 3) + br, bco = (bq & 1) << 3;

    for (int it = 0; it < 32; it++) {
        CP_WAIT1();
        __syncthreads();
        int p = it % 3;
        uint32_t aH = sbase + (uint32_t)p * 30720u;
        uint32_t aL = aH + 5120u;
        uint32_t bH = aH + 10240u;
        uint32_t bL = aH + 20480u;
#pragma unroll
        for (int kc = 0; kc < 2; kc++) {
            uint32_t a_h[2][4], a_l[2][4], b_h[4][2], b_l[4][2];
#pragma unroll
            for (int mf = 0; mf < 2; mf++) {
                uint32_t off = (uint32_t)((wm * 32 + mf * 16 + ar) * 40 + kc * 16 + ah8) * 2;
                LDSM4(a_h[mf], aH + off);
                LDSM4(a_l[mf], aL + off);
            }
#pragma unroll
            for (int nb = 0; nb < 2; nb++) {
                uint32_t off = (uint32_t)((wn * 32 + nb * 16 + bro) * 40 + kc * 16 + bco) * 2;
                uint32_t rh[4], rl[4];
                LDSM4(rh, bH + off);
                LDSM4(rl, bL + off);
                b_h[2 * nb][0] = rh[0]; b_h[2 * nb][1] = rh[1];
                b_h[2 * nb + 1][0] = rh[2]; b_h[2 * nb + 1][1] = rh[3];
                b_l[2 * nb][0] = rl[0]; b_l[2 * nb][1] = rl[1];
                b_l[2 * nb + 1][0] = rl[2]; b_l[2 * nb + 1][1] = rl[3];
            }
#pragma unroll
            for (int mf = 0; mf < 2; mf++)
#pragma unroll
                for (int nf = 0; nf < 4; nf++) {
                    MMA16816(acc[mf][nf], a_h[mf], b_h[nf][0], b_h[nf][1]);
                    MMA16816(acc[mf][nf], a_h[mf], b_l[nf][0], b_l[nf][1]);
                    MMA16816(acc[mf][nf], a_l[mf], b_h[nf][0], b_h[nf][1]);
                }
        }
        if (it < 30) LOAD_STAGE((it + 2) % 3, (it + 2) * 32);
        CP_COMMIT();
    }

    int g = lane >> 2, tig = lane & 3;
#pragma unroll
    for (int mf = 0; mf < 2; mf++) {
#pragma unroll
        for (int h = 0; h < 2; h++) {
            int m = row0 + wm * 32 + mf * 16 + g + h * 8;
            int l = m % Lp;
            int bc = m / Lp;
            int co = bc & 15;
            float scale = s_scale[co], shift = s_shift[co], gb = s_gb[co];
            const float* idp  = idt + (size_t)m * 512;
            const float* resp = xprev + (size_t)(bc * Lprev + l + dil) * 512;
            float* op = xnew + (size_t)m * 512;
#pragma unroll
            for (int nf = 0; nf < 4; nf++) {
                int n = col0 + wn * 32 + nf * 8 + tig * 2;
                float v0 = acc[mf][nf][2 * h]     + idp[n]     + gb + resp[n];
                float v1 = acc[mf][nf][2 * h + 1] + idp[n + 1] + gb + resp[n + 1];
                op[n]     = v0 * scale + shift;
                op[n + 1] = v1 * scale + shift;
            }
        }
    }
}

// ---------------- tail MMA GEMM (small layers, Lp<=4): 32(M)x128(N) tiles, 3-stage ----------------
#define MMA32_SMEM_BYTES 76800

__global__ void __launch_bounds__(256) k_mma32(
    const __nv_bfloat16* __restrict__ Ah, const __nv_bfloat16* __restrict__ Al,
    const __nv_bfloat16* __restrict__ Bh, const __nv_bfloat16* __restrict__ Bl,
    const float* __restrict__ idt, const float* __restrict__ xprev, float* __restrict__ xnew,
    const float* __restrict__ gcb, const float* __restrict__ bng, const float* __restrict__ bnb,
    const float* __restrict__ bnm, const float* __restrict__ bnv,
    int Lp, int dil, int Lprev)
{
    extern __shared__ __align__(16) char smem_raw[];
    __shared__ float s_scale[16], s_shift[16], s_gb[16];
    uint32_t sbase = (uint32_t)__cvta_generic_to_shared(smem_raw);

    int t = threadIdx.x;
    if (t < 16) {
        float sc = bng[t] * rsqrtf(bnv[t] + 1e-5f);
        s_scale[t] = sc;
        s_shift[t] = bnb[t] - bnm[t] * sc;
        s_gb[t] = gcb[t];
    }

    int row0 = blockIdx.y * 32, col0 = blockIdx.x * 128;
    int warp = t >> 5, lane = t & 31;
    int wn = warp;

    float acc[2][2][4];
#pragma unroll
    for (int i = 0; i < 2; i++)
#pragma unroll
        for (int j = 0; j < 2; j++)
#pragma unroll
            for (int r = 0; r < 4; r++) acc[i][j][r] = 0.f;

    int tA = t & 127;
    int rA = tA >> 2, kA = (tA & 3) * 8;
    uint32_t aSel = (t < 128) ? 0u : 2560u;
    int rB0 = t >> 2, kB0 = (t & 3) * 8;
    int rB1 = 64 + (t >> 2), kB1 = (t & 3) * 8;

#define LOAD_STAGE32(S, K0)                                                        \
    do {                                                                           \
        uint32_t sb_ = sbase + (uint32_t)(S) * 25600u;                             \
        const __nv_bfloat16* gsrcA = (t < 128) ? Ah : Al;                          \
        cpasync16(sb_ + aSel + (uint32_t)(rA * 40 + kA) * 2,                       \
                  gsrcA + (size_t)(row0 + rA) * 1024 + (K0) + kA);                 \
        const __nv_bfloat16* gb0 = Bh + (size_t)(col0 + rB0) * 1024 + (K0) + kB0;  \
        const __nv_bfloat16* gb1 = Bh + (size_t)(col0 + rB1) * 1024 + (K0) + kB1;  \
        uint32_t sb0 = sb_ + 5120u + (uint32_t)(rB0 * 40 + kB0) * 2;               \
        uint32_t sb1 = sb_ + 5120u + (uint32_t)(rB1 * 40 + kB1) * 2;               \
        cpasync16(sb0,          gb0);                                              \
        cpasync16(sb0 + 10240u, Bl + (gb0 - Bh));                                  \
        cpasync16(sb1,          gb1);                                              \
        cpasync16(sb1 + 10240u, Bl + (gb1 - Bh));                                  \
    } while (0)

    LOAD_STAGE32(0, 0);
    CP_COMMIT();
    LOAD_STAGE32(1, 32);
    CP_COMMIT();

    int ar = lane & 15, ah8 = (lane >> 4) << 3;
    int bq = lane >> 3, br = lane & 7;
    int bro = ((bq >> 1) << 3) + br, bco = (bq & 1) << 3;

    for (int it = 0; it < 32; it++) {
        CP_WAIT1();
        __syncthreads();
        int p = it % 3;
        uint32_t aH = sbase + (uint32_t)p * 25600u;
        uint32_t aL = aH + 2560u;
        uint32_t bH = aH + 5120u;
        uint32_t bL = aH + 15360u;
#pragma unroll
        for (int kc = 0; kc < 2; kc++) {
            uint32_t a_h[2][4], a_l[2][4], b_h[2][2], b_l[2][2];
#pragma unroll
            for (int mf = 0; mf < 2; mf++) {
                uint32_t off = (uint32_t)((mf * 16 + ar) * 40 + kc * 16 + ah8) * 2;
                LDSM4(a_h[mf], aH + off);
                LDSM4(a_l[mf], aL + off);
            }
            {
                uint32_t off = (uint32_t)((wn * 16 + bro) * 40 + kc * 16 + bco) * 2;
                uint32_t rh[4], rl[4];
                LDSM4(rh, bH + off);
                LDSM4(rl, bL + off);
                b_h[0][0] = rh[0]; b_h[0][1] = rh[1];
                b_h[1][0] = rh[2]; b_h[1][1] = rh[3];
                b_l[0][0] = rl[0]; b_l[0][1] = rl[1];
                b_l[1][0] = rl[2]; b_l[1][1] = rl[3];
            }
#pragma unroll
            for (int mf = 0; mf < 2; mf++)
#pragma unroll
                for (int nf = 0; nf < 2; nf++) {
                    MMA16816(acc[mf][nf], a_h[mf], b_h[nf][0], b_h[nf][1]);
                    MMA16816(acc[mf][nf], a_h[mf], b_l[nf][0], b_l[nf][1]);
                    MMA16816(acc[mf][nf], a_l[mf], b_h[nf][0], b_h[nf][1]);
                }
        }
        if (it < 30) LOAD_STAGE32((it + 2) % 3, (it + 2) * 32);
        CP_COMMIT();
    }

    int g = lane >> 2, tig = lane & 3;
#pragma unroll
    for (int mf = 0; mf < 2; mf++) {
#pragma unroll
        for (int h = 0; h < 2; h++) {
            int m = row0 + mf * 16 + g + h * 8;
            int l = m % Lp;
            int bc = m / Lp;
            int co = bc & 15;
            float scale = s_scale[co], shift = s_shift[co], gb = s_gb[co];
            const float* idp  = idt + (size_t)m * 512;
            const float* resp = xprev + (size_t)(bc * Lprev + l + dil) * 512;
            float* op = xnew + (size_t)m * 512;
#pragma unroll
            for (int nf = 0; nf < 2; nf++) {
                int n = col0 + wn * 16 + nf * 8 + tig * 2;
                float v0 = acc[mf][nf][2 * h]     + idp[n]     + gb + resp[n];
                float v1 = acc[mf][nf][2 * h + 1] + idp[n + 1] + gb + resp[n + 1];
                op[n]     = v0 * scale + shift;
                op[n + 1] = v1 * scale + shift;
            }
        }
    }
}

// ---------------- K9: end convs ----------------
__global__ void k_end(const float* __restrict__ skip,
                      const float* __restrict__ w1, const float* __restrict__ b1,
                      const float* __restrict__ w2, const float* __restrict__ b2,
                      float* __restrict__ out)
{
    int tid = blockIdx.x * 128 + threadIdx.x;
    int b = tid >> 9, v = tid & 511;
    float s[16];
#pragma unroll
    for (int c = 0; c < 16; c++) s[c] = fmaxf(skip[(b * 16 + c) * 512 + v], 0.f);
    float e1[16];
#pragma unroll
    for (int c = 0; c < 16; c++) {
        float a = b1[c];
#pragma unroll
        for (int ci = 0; ci < 16; ci++) a += w1[c * 16 + ci] * s[ci];
        e1[c] = fmaxf(a, 0.f);
    }
#pragma unroll
    for (int h = 0; h < 12; h++) {
        float a = b2[h];
#pragma unroll
        for (int c = 0; c < 16; c++) a += w2[h * 16 + c] * e1[c];
        out[(b * 12 + h) * 512 + v] = a;
    }
}

// ======================== host orchestration ========================
extern "C" void kernel_launch(void* const* d_in, const int* in_sizes, int n_in,
                              void* d_out, int out_size)
{
    const float* input  = (const float*)d_in[0];
    const float* startW = (const float*)d_in[1];
    const float* startb = (const float*)d_in[2];
    const float* filtW  = (const float*)d_in[3];
    const float* filtb  = (const float*)d_in[4];
    const float* gateW  = (const float*)d_in[5];
    const float* gateb  = (const float*)d_in[6];
    const float* skipW  = (const float*)d_in[7];
    const float* skipb  = (const float*)d_in[8];
    const float* gconvW = (const float*)d_in[9];
    const float* gconvb = (const float*)d_in[10];
    const float* bng    = (const float*)d_in[11];
    const float* bnb    = (const float*)d_in[12];
    const float* bnm    = (const float*)d_in[13];
    const float* bnv    = (const float*)d_in[14];
    const float* e1W    = (const float*)d_in[15];
    const float* e1b    = (const float*)d_in[16];
    const float* e2W    = (const float*)d_in[17];
    const float* e2b    = (const float*)d_in[18];
    const float* linW   = (const float*)d_in[19];
    const float* linb   = (const float*)d_in[20];
    const float* f1W    = (const float*)d_in[21];
    const float* f1b    = (const float*)d_in[22];
    const float* f2W    = (const float*)d_in[23];
    const float* f2b    = (const float*)d_in[24];
    const float* f3W    = (const float*)d_in[25];
    const float* f3b    = (const float*)d_in[26];
    float* out = (float*)d_out;

    float *p_real, *p_img, *p_iffp, *p_AA2, *p_bs;
    float *p_xa, *p_xb, *p_idt, *p_skip;
    __nv_bfloat16 *p_Fh, *p_Fl, *p_Wh, *p_Wl, *p_Bth, *p_Btl, *p_PQh, *p_PQl;
    cudaGetSymbolAddress((void**)&p_real, g_real);
    cudaGetSymbolAddress((void**)&p_img,  g_img);
    cudaGetSymbolAddress((void**)&p_iffp, g_iffp);
    cudaGetSymbolAddress((void**)&p_AA2,  g_AA2);
    cudaGetSymbolAddress((void**)&p_Fh,   g_Fh);
    cudaGetSymbolAddress((void**)&p_Fl,   g_Fl);
    cudaGetSymbolAddress((void**)&p_Wh,   g_Wh);
    cudaGetSymbolAddress((void**)&p_Wl,   g_Wl);
    cudaGetSymbolAddress((void**)&p_bs,   g_bs);
    cudaGetSymbolAddress((void**)&p_Bth,  g_Bth);
    cudaGetSymbolAddress((void**)&p_Btl,  g_Btl);
    cudaGetSymbolAddress((void**)&p_xa,   g_xa);
    cudaGetSymbolAddress((void**)&p_xb,   g_xb);
    cudaGetSymbolAddress((void**)&p_PQh,  g_PQh);
    cudaGetSymbolAddress((void**)&p_PQl,  g_PQl);
    cudaGetSymbolAddress((void**)&p_idt,  g_idt);
    cudaGetSymbolAddress((void**)&p_skip, g_skip);

    static int smem_set = 0;
    if (!smem_set) {
        cudaFuncSetAttribute(k_mma, cudaFuncAttributeMaxDynamicSharedMemorySize, MMA_SMEM_BYTES);
        cudaFuncSetAttribute(k_mma32, cudaFuncAttributeMaxDynamicSharedMemorySize, MMA32_SMEM_BYTES);
        cudaFuncSetAttribute(k_adjmma, cudaFuncAttributeMaxDynamicSharedMemorySize, ADJ_SMEM);
        smem_set = 1;
    }

    // ---- graph learner ----
    k_dft<<<256, 64>>>(input, linW, linb, p_real, p_img, p_Fh, p_Fl);
    k_iff_part<<<dim3(32, 16), 512>>>(p_real, p_img, p_iffp);
    k_iff_red<<<1280, 256>>>(p_iffp, p_Fh, p_Fl);
    k_wprep<<<64, 256>>>(f1W, f1b, f2W, f2b, f3W, f3b, p_Wh, p_Wl, p_bs);
    float* adj_out = (out_size >= Bz * HORz * Vz + Vz * Vz) ? out + Bz * HORz * Vz : nullptr;
    k_adjmma<<<dim3(4, 128), 256, ADJ_SMEM>>>(p_Fh, p_Fl, p_Wh, p_Wl, p_bs, p_AA2, adj_out);
    k_gemm_plain<<<dim3(8, 8), 256>>>(p_AA2, p_AA2, p_AA2 + Vz * Vz, 512);
    k_prepB<<<dim3(16, 32), dim3(32, 8)>>>(p_AA2, p_Bth, p_Btl);

    // ---- trunk ----
    k_start<<<13312, 256>>>(input, startW, startb, p_xa);

    float* xc = p_xa;
    float* xn = p_xb;
    int L = RFz;
    const int dils[NLz] = {1, 2, 1, 2, 1, 2, 1, 2};
    for (int i = 0; i < NLz; i++) {
        int d = dils[i];
        int Lp = L - d;
        k_fused<<<Bz * Lp, 256>>>(xc, filtW + i * 512, filtb + i * 16,
                                  gateW + i * 512, gateb + i * 16,
                                  gconvW + i * 1024, skipW + i * 256, skipb + i * 16,
                                  p_PQh, p_PQl, p_idt, p_skip, L, d, (i == 0) ? 1 : 0);
        int M = Bz * CHz * Lp;
        if (Lp > 4) {
            k_mma<<<dim3(4, M / 64), 256, MMA_SMEM_BYTES>>>(p_PQh, p_PQl, p_Bth, p_Btl,
                                                            p_idt, xc, xn,
                                                            gconvb + i * 16, bng + i * 16, bnb + i * 16,
                                                            bnm + i * 16, bnv + i * 16, Lp, d, L);
        } else {
            k_mma32<<<dim3(4, M / 32), 256, MMA32_SMEM_BYTES>>>(p_PQh, p_PQl, p_Bth, p_Btl,
                                                                p_idt, xc, xn,
                                                                gconvb + i * 16, bng + i * 16, bnb + i * 16,
                                                                bnm + i * 16, bnv + i * 16, Lp, d, L);
        }
        float* tmp = xc; xc = xn; xn = tmp;
        L = Lp;
    }

    k_end<<<128, 128>>>(p_skip, e1W, e1b, e2W, e2b, out);
}

// round 15
// speedup vs baseline: 1.0528x; 1.0135x over previous
#include <cuda_runtime.h>
#include <cuda_bf16.h>
#include <math.h>
#include <stdint.h>

#define Bz   32
#define Vz   512
#define Tz   12
#define DGz  20
#define CHz  16
#define HORz 12
#define RFz  13
#define NLz  8
#define EPSz 0.3f

// ---------------- scratch ----------------
__device__ float g_real[Bz*Vz*DGz];
__device__ float g_img [Bz*Vz*DGz];
__device__ float g_iffp[16*Bz*Vz*DGz];
__device__ float g_AA2 [2*Vz*Vz];
__device__ __align__(16) __nv_bfloat16 g_Fh[Bz*Vz*64];
__device__ __align__(16) __nv_bfloat16 g_Fl[Bz*Vz*64];
__device__ __align__(16) __nv_bfloat16 g_Wh[Vz*64];
__device__ __align__(16) __nv_bfloat16 g_Wl[Vz*64];
__device__ float g_bs[Vz];
__device__ __align__(16) __nv_bfloat16 g_Bth[Vz*1024];
__device__ __align__(16) __nv_bfloat16 g_Btl[Vz*1024];
__device__ float g_xa  [Bz*CHz*RFz*Vz];
__device__ float g_xb  [Bz*CHz*RFz*Vz];
__device__ __align__(16) __nv_bfloat16 g_PQh[Bz*CHz*Tz*1024];
__device__ __align__(16) __nv_bfloat16 g_PQl[Bz*CHz*Tz*1024];
__device__ float g_idt [Bz*CHz*Tz*Vz];
__device__ float g_skip[Bz*CHz*Vz];

// ---------------- PTX helpers ----------------
__device__ __forceinline__ void cpasync16(uint32_t s, const void* g) {
    asm volatile("cp.async.cg.shared.global [%0], [%1], 16;\n" :: "r"(s), "l"(g));
}
#define CP_COMMIT() asm volatile("cp.async.commit_group;\n" ::)
#define CP_WAIT0()  asm volatile("cp.async.wait_group 0;\n" ::)
#define CP_WAIT1()  asm volatile("cp.async.wait_group 1;\n" ::)

#define LDSM4(R, addr) \
    asm volatile("ldmatrix.sync.aligned.m8n8.x4.shared.b16 {%0,%1,%2,%3}, [%4];" \
        : "=r"((R)[0]), "=r"((R)[1]), "=r"((R)[2]), "=r"((R)[3]) : "r"(addr))

#define MMA16816(C, A, B0, B1) \
    asm volatile("mma.sync.aligned.m16n8k16.row.col.f32.bf16.bf16.f32 " \
        "{%0,%1,%2,%3},{%4,%5,%6,%7},{%8,%9},{%0,%1,%2,%3};" \
        : "+f"((C)[0]), "+f"((C)[1]), "+f"((C)[2]), "+f"((C)[3]) \
        : "r"((A)[0]), "r"((A)[1]), "r"((A)[2]), "r"((A)[3]), "r"(B0), "r"(B1))

// packed f32x2 fma: d = a*b + c (per 32-bit lane)
#define FMA2(D, A, B, C) \
    asm("fma.rn.f32x2 %0, %1, %2, %3;" : "=l"(D) : "l"(A), "l"(B), "l"(C))

__device__ __forceinline__ unsigned long long pack2(float a, float b) {
    unsigned long long r;
    asm("mov.b64 %0, {%1, %2};" : "=l"(r) : "f"(a), "f"(b));
    return r;
}
__device__ __forceinline__ void unpack2(unsigned long long p, float& a, float& b) {
    asm("mov.b64 {%0, %1}, %2;" : "=f"(a), "=f"(b) : "l"(p));
}

__device__ __forceinline__ void split2(float a, float b,
                                       __nv_bfloat162& hi, __nv_bfloat162& lo) {
    __nv_bfloat16 ha = __float2bfloat16(a), hb = __float2bfloat16(b);
    hi = __halves2bfloat162(ha, hb);
    lo = __floats2bfloat162_rn(a - __bfloat162float(ha), b - __bfloat162float(hb));
}

// ---------------- K0: DFT(24) + lin projection (f32x2 packed) ----------------
__global__ void __launch_bounds__(64) k_dft(
    const float* __restrict__ input, const float* __restrict__ lW,
    const float* __restrict__ lb, float* __restrict__ re, float* __restrict__ im,
    __nv_bfloat16* __restrict__ Fh, __nv_bfloat16* __restrict__ Fl)
{
    __shared__ unsigned long long cst[24];   // (cos, -sin) packed
    if (threadIdx.x < 24) {
        float c = cospif(threadIdx.x / 12.f);
        float s = sinpif(threadIdx.x / 12.f);
        cst[threadIdx.x] = pack2(c, -s);
    }
    __syncthreads();
    int tid = blockIdx.x * 64 + threadIdx.x;
    int b = tid >> 9, v = tid & 511;
    unsigned long long xrp[24];
#pragma unroll
    for (int t = 0; t < 12; t++) {
        int base = ((t * 32 + b) * 512 + v) * 2;
        float a0 = input[base], a1 = input[base + 1];
        xrp[2 * t]     = pack2(a0, a0);
        xrp[2 * t + 1] = pack2(a1, a1);
    }
    unsigned long long fri[24];   // (fr, fi) packed per harmonic
#pragma unroll
    for (int n = 0; n < 24; n++) {
        unsigned long long s = 0ull;
        int idx = 0;
#pragma unroll
        for (int k = 0; k < 24; k++) {
            FMA2(s, xrp[k], cst[idx], s);
            idx += n; if (idx >= 24) idx -= 24;
        }
        fri[n] = s;
    }
    int go = (b * 512 + v) * 20;
    int frow = (v * 32 + b) * 64;
#pragma unroll
    for (int d = 0; d < 20; d += 2) {
        unsigned long long rq0 = pack2(lb[d], lb[d]);
        unsigned long long rq1 = pack2(lb[d + 1], lb[d + 1]);
#pragma unroll
        for (int n = 0; n < 24; n++) {
            float w0 = lW[d * 24 + n], w1 = lW[(d + 1) * 24 + n];
            FMA2(rq0, pack2(w0, w0), fri[n], rq0);
            FMA2(rq1, pack2(w1, w1), fri[n], rq1);
        }
        float r0, q0, r1, q1;
        unpack2(rq0, r0, q0);
        unpack2(rq1, r1, q1);
        re[go + d] = r0; re[go + d + 1] = r1;
        im[go + d] = q0; im[go + d + 1] = q1;
        float am0 = sqrtf(r0 * r0 + q0 * q0), am1 = sqrtf(r1 * r1 + q1 * q1);
        float ss0 = atanf(r0 / (q0 + 1e-4f)), ss1 = atanf(r1 / (q1 + 1e-4f));
        __nv_bfloat162 h2, l2;
        split2(am0, am1, h2, l2);
        *reinterpret_cast<__nv_bfloat162*>(Fh + frow + 20 + d) = h2;
        *reinterpret_cast<__nv_bfloat162*>(Fl + frow + 20 + d) = l2;
        split2(ss0, ss1, h2, l2);
        *reinterpret_cast<__nv_bfloat162*>(Fh + frow + 40 + d) = h2;
        *reinterpret_cast<__nv_bfloat162*>(Fl + frow + 40 + d) = l2;
    }
    *reinterpret_cast<uint32_t*>(Fh + frow + 60) = 0u;
    *reinterpret_cast<uint32_t*>(Fh + frow + 62) = 0u;
    *reinterpret_cast<uint32_t*>(Fl + frow + 60) = 0u;
    *reinterpret_cast<uint32_t*>(Fl + frow + 62) = 0u;
}

// ---------------- K1a: irfft partials (f32x2 packed over d-pairs) ----------------
__global__ void __launch_bounds__(512) k_iff_part(
    const float* __restrict__ re, const float* __restrict__ im, float* __restrict__ iffp)
{
    __shared__ float ct[512], st[512];
    int m = threadIdx.x;
    ct[m] = cospif(m / 256.f);
    st[m] = sinpif(m / 256.f);
    __syncthreads();
    int b = blockIdx.x, c = blockIdx.y;
    const float* R = re + b * 512 * 20;
    const float* I = im + b * 512 * 20;
    unsigned long long acc[10];
    if (c == 0) {
        float sg = (m & 1) ? -1.f : 1.f;
        unsigned long long sgp = pack2(sg, sg);
#pragma unroll
        for (int d = 0; d < 10; d++) {
            unsigned long long r0 = *reinterpret_cast<const unsigned long long*>(R + 2 * d);
            unsigned long long rN = *reinterpret_cast<const unsigned long long*>(R + 256 * 20 + 2 * d);
            FMA2(acc[d], sgp, rN, r0);
        }
    } else {
#pragma unroll
        for (int d = 0; d < 10; d++) acc[d] = 0ull;
    }
    int k0 = (c == 0) ? 1 : c * 16;
    int k1 = c * 16 + 16;
    int idx = (k0 * m) & 511;
    for (int k = k0; k < k1; k++) {
        float cc = 2.f * ct[idx], ss = -2.f * st[idx];
        unsigned long long ccp = pack2(cc, cc), ssp = pack2(ss, ss);
        const unsigned long long* Rp = reinterpret_cast<const unsigned long long*>(R + k * 20);
        const unsigned long long* Ip = reinterpret_cast<const unsigned long long*>(I + k * 20);
#pragma unroll
        for (int d = 0; d < 10; d++) {
            FMA2(acc[d], ccp, Rp[d], acc[d]);
            FMA2(acc[d], ssp, Ip[d], acc[d]);
        }
        idx = (idx + m) & 511;
    }
    int go = ((c * 32 + b) * 512 + m) * 20;
    unsigned long long* op = reinterpret_cast<unsigned long long*>(iffp + go);
#pragma unroll
    for (int d = 0; d < 10; d++) op[d] = acc[d];
}

// ---------------- K1b: reduce -> feat cols 0..19 ----------------
__global__ void k_iff_red(const float* __restrict__ iffp,
                          __nv_bfloat16* __restrict__ Fh, __nv_bfloat16* __restrict__ Fl)
{
    int i = blockIdx.x * 256 + threadIdx.x;
    const int Sz = Bz * Vz * DGz;
    int d = i % 20;
    int r = i / 20;
    int v = r & 511, b = r >> 9;
    float s = 0.f;
#pragma unroll
    for (int c = 0; c < 16; c++) s += iffp[c * Sz + i];
    s *= (1.f / 512.f);
    __nv_bfloat16 h = __float2bfloat16(s);
    int o = (v * 32 + b) * 64 + d;
    Fh[o] = h;
    Fl[o] = __float2bfloat16(s - __bfloat162float(h));
}

// ---------------- Wprep (parallel: 16384 threads) ----------------
__global__ void k_wprep(const float* __restrict__ f1W, const float* __restrict__ f1b,
                        const float* __restrict__ f2W, const float* __restrict__ f2b,
                        const float* __restrict__ f3W, const float* __restrict__ f3b,
                        __nv_bfloat16* __restrict__ Wh, __nv_bfloat16* __restrict__ Wl,
                        float* __restrict__ bs)
{
    int t = blockIdx.x * 256 + threadIdx.x;   // 16384
    int w = t >> 5, d = t & 31;
    const float inv3 = 1.f / 3.f;
    if (d < 20) {
        float a = f1W[w * 20 + d] * inv3;
        __nv_bfloat16 h = __float2bfloat16(a);
        Wh[w * 64 + d] = h; Wl[w * 64 + d] = __float2bfloat16(a - __bfloat162float(h));
        a = f2W[w * 20 + d] * inv3;
        h = __float2bfloat16(a);
        Wh[w * 64 + 20 + d] = h; Wl[w * 64 + 20 + d] = __float2bfloat16(a - __bfloat162float(h));
        a = f3W[w * 20 + d] * inv3;
        h = __float2bfloat16(a);
        Wh[w * 64 + 40 + d] = h; Wl[w * 64 + 40 + d] = __float2bfloat16(a - __bfloat162float(h));
    } else if (d < 24) {
        Wh[w * 64 + 40 + d] = __float2bfloat16(0.f);
        Wl[w * 64 + 40 + d] = __float2bfloat16(0.f);
    } else if (d == 24) {
        bs[w] = (f1b[w] + f2b[w] + f3b[w]) * inv3;
    }
}

// ---------------- K2: adj via MMA + sigmoid + batch-reduce ----------------
#define ADJ_SMEM 73728
__global__ void __launch_bounds__(256) k_adjmma(
    const __nv_bfloat16* __restrict__ Fh, const __nv_bfloat16* __restrict__ Fl,
    const __nv_bfloat16* __restrict__ Wh, const __nv_bfloat16* __restrict__ Wl,
    const float* __restrict__ bs, float* __restrict__ AA2, float* __restrict__ adj_out)
{
    extern __shared__ __align__(16) char smem_raw[];
    __shared__ float sbs[128];
    uint32_t sbase = (uint32_t)__cvta_generic_to_shared(smem_raw);
    float* Stile = (float*)smem_raw;
    int t = threadIdx.x;
    int row0 = blockIdx.y * 128, col0 = blockIdx.x * 128;
    if (t < 128) sbs[t] = bs[col0 + t];
#pragma unroll
    for (int i = 0; i < 4; i++) {
        int c = t + i * 256;
        int row = c >> 3, col8 = (c & 7) * 8;
        uint32_t so = (uint32_t)(row * 72 + col8) * 2;
        const __nv_bfloat16* gA = Fh + (size_t)(row0 + row) * 64 + col8;
        const __nv_bfloat16* gB = Wh + (size_t)(col0 + row) * 64 + col8;
        cpasync16(sbase + so,           gA);
        cpasync16(sbase + 18432u + so,  Fl + (gA - Fh));
        cpasync16(sbase + 36864u + so,  gB);
        cpasync16(sbase + 55296u + so,  Wl + (gB - Wh));
    }
    CP_COMMIT();
    CP_WAIT0();
    __syncthreads();

    int warp = t >> 5, lane = t & 31;
    int wm = warp >> 2, wn = warp & 3;
    float acc[4][4][4];
#pragma unroll
    for (int i = 0; i < 4; i++)
#pragma unroll
        for (int j = 0; j < 4; j++)
#pragma unroll
            for (int r = 0; r < 4; r++) acc[i][j][r] = 0.f;

    int ar = lane & 15, ah8 = (lane >> 4) << 3;
    int bq = lane >> 3, br = lane & 7;
    int bro = ((bq >> 1) << 3) + br, bco = (bq & 1) << 3;
    uint32_t aH = sbase, aL = sbase + 18432u, bH = sbase + 36864u, bL = sbase + 55296u;
#pragma unroll
    for (int kc = 0; kc < 4; kc++) {
        uint32_t a_h[4][4], a_l[4][4], b_h[4][2], b_l[4][2];
#pragma unroll
        for (int mf = 0; mf < 4; mf++) {
            uint32_t off = (uint32_t)((wm * 64 + mf * 16 + ar) * 72 + kc * 16 + ah8) * 2;
            LDSM4(a_h[mf], aH + off);
            LDSM4(a_l[mf], aL + off);
        }
#pragma unroll
        for (int nb = 0; nb < 2; nb++) {
            uint32_t off = (uint32_t)((wn * 32 + nb * 16 + bro) * 72 + kc * 16 + bco) * 2;
            uint32_t rh[4], rl[4];
            LDSM4(rh, bH + off);
            LDSM4(rl, bL + off);
            b_h[2 * nb][0] = rh[0]; b_h[2 * nb][1] = rh[1];
            b_h[2 * nb + 1][0] = rh[2]; b_h[2 * nb + 1][1] = rh[3];
            b_l[2 * nb][0] = rl[0]; b_l[2 * nb][1] = rl[1];
            b_l[2 * nb + 1][0] = rl[2]; b_l[2 * nb + 1][1] = rl[3];
        }
#pragma unroll
        for (int mf = 0; mf < 4; mf++)
#pragma unroll
            for (int nf = 0; nf < 4; nf++) {
                MMA16816(acc[mf][nf], a_h[mf], b_h[nf][0], b_h[nf][1]);
                MMA16816(acc[mf][nf], a_h[mf], b_l[nf][0], b_l[nf][1]);
                MMA16816(acc[mf][nf], a_l[mf], b_h[nf][0], b_h[nf][1]);
            }
    }
    __syncthreads();

    int g = lane >> 2, tig = lane & 3;
#pragma unroll
    for (int mf = 0; mf < 4; mf++)
#pragma unroll
        for (int h = 0; h < 2; h++) {
            int r = wm * 64 + mf * 16 + g + h * 8;
#pragma unroll
            for (int nf = 0; nf < 4; nf++) {
                int cl = wn * 32 + nf * 8 + tig * 2;
                float l0 = acc[mf][nf][2 * h]     + sbs[cl];
                float l1 = acc[mf][nf][2 * h + 1] + sbs[cl + 1];
                Stile[r * 132 + cl]     = 1.f / (1.f + __expf(-l0));
                Stile[r * 132 + cl + 1] = 1.f / (1.f + __expf(-l1));
            }
        }
    __syncthreads();

    int v0 = row0 >> 5;
#pragma unroll
    for (int o = t; o < 512; o += 256) {
        int vi = o >> 7, w = o & 127;
        float s = 0.f;
#pragma unroll
        for (int b2 = 0; b2 < 32; b2++) s += Stile[(vi * 32 + b2) * 132 + w];
        float a = 1.f / (1.f + __expf(-s * (1.f / 32.f)));
        int vv = v0 + vi, ww = col0 + w;
        AA2[vv * 512 + ww] = a;
        if (adj_out) adj_out[vv * 512 + ww] = a;
    }
}

// ---------------- SGEMM adj@adj (fp32, small) ----------------
__global__ void __launch_bounds__(256) k_gemm_plain(
    const float* __restrict__ Aq, const float* __restrict__ Bq, float* __restrict__ C, int K)
{
    __shared__ float As[16][65];
    __shared__ float Bs[16][64];
    int t = threadIdx.x;
    int tx = t & 15, ty = t >> 4;
    int row0 = blockIdx.y * 64, col0 = blockIdx.x * 64;
    float acc[4][4] = {};
    int mA = t >> 2, kA = (t & 3) << 2;
    int kB = t >> 4, nB = (t & 15) << 2;
    const float* aptr = Aq + (row0 + mA) * K + kA;
    const float* bptr = Bq + kB * 512 + col0 + nB;
    for (int k0 = 0; k0 < K; k0 += 16) {
        float4 a4 = *reinterpret_cast<const float4*>(aptr + k0);
        float4 b4 = *reinterpret_cast<const float4*>(bptr + k0 * 512);
        As[kA + 0][mA] = a4.x; As[kA + 1][mA] = a4.y;
        As[kA + 2][mA] = a4.z; As[kA + 3][mA] = a4.w;
        *reinterpret_cast<float4*>(&Bs[kB][nB]) = b4;
        __syncthreads();
#pragma unroll
        for (int kk = 0; kk < 16; kk++) {
            float a0 = As[kk][ty * 4 + 0], a1 = As[kk][ty * 4 + 1];
            float a2 = As[kk][ty * 4 + 2], a3 = As[kk][ty * 4 + 3];
            float4 br = *reinterpret_cast<const float4*>(&Bs[kk][tx * 4]);
            acc[0][0] += a0 * br.x; acc[0][1] += a0 * br.y; acc[0][2] += a0 * br.z; acc[0][3] += a0 * br.w;
            acc[1][0] += a1 * br.x; acc[1][1] += a1 * br.y; acc[1][2] += a1 * br.z; acc[1][3] += a1 * br.w;
            acc[2][0] += a2 * br.x; acc[2][1] += a2 * br.y; acc[2][2] += a2 * br.z; acc[2][3] += a2 * br.w;
            acc[3][0] += a3 * br.x; acc[3][1] += a3 * br.y; acc[3][2] += a3 * br.z; acc[3][3] += a3 * br.w;
        }
        __syncthreads();
    }
#pragma unroll
    for (int i = 0; i < 4; i++)
#pragma unroll
        for (int j = 0; j < 4; j++)
            C[(row0 + ty * 4 + i) * 512 + col0 + tx * 4 + j] = acc[i][j];
}

// ---------------- prepB: transpose AA2 [1024x512] -> Bt hi/lo [512x1024] ----------------
__global__ void k_prepB(const float* __restrict__ AA2,
                        __nv_bfloat16* __restrict__ Bth, __nv_bfloat16* __restrict__ Btl)
{
    __shared__ float tile[32][33];
    int k0 = blockIdx.y * 32, n0 = blockIdx.x * 32;
    int tx = threadIdx.x, ty = threadIdx.y;
#pragma unroll
    for (int i = 0; i < 4; i++)
        tile[ty + i * 8][tx] = AA2[(k0 + ty + i * 8) * 512 + n0 + tx];
    __syncthreads();
#pragma unroll
    for (int i = 0; i < 4; i++) {
        int r = ty + i * 8;
        float v = tile[tx][r];
        __nv_bfloat16 hi = __float2bfloat16(v);
        __nv_bfloat16 lo = __float2bfloat16(v - __bfloat162float(hi));
        int o = (n0 + r) * 1024 + k0 + tx;
        Bth[o] = hi; Btl[o] = lo;
    }
}

// ---------------- K4: pad + start 1x1 conv ----------------
__global__ void k_start(const float* __restrict__ input, const float* __restrict__ sW,
                        const float* __restrict__ sb, float* __restrict__ x0)
{
    int idx = blockIdx.x * 256 + threadIdx.x;
    int v = idx & 511;
    int r = idx >> 9;
    int l = r % 13; r /= 13;
    int c = r & 15; int b = r >> 4;
    float val = sb[c];
    if (l > 0) {
        int t = l - 1;
        const float* ip = input + ((t * 32 + b) * 512 + v) * 2;
        val += sW[c * 2] * ip[0] + sW[c * 2 + 1] * ip[1];
    }
    x0[idx] = val;
}

// ---------------- fused producer (f32x2 packed FMA) ----------------
__global__ void __launch_bounds__(256) k_fused(
    const float* __restrict__ x,
    const float* __restrict__ fW, const float* __restrict__ fb,
    const float* __restrict__ gW, const float* __restrict__ gb,
    const float* __restrict__ gcW,
    const float* __restrict__ sW, const float* __restrict__ sb,
    __nv_bfloat16* __restrict__ PQh, __nv_bfloat16* __restrict__ PQl,
    float* __restrict__ idt, float* __restrict__ skip,
    int L, int d, int first)
{
    __shared__ unsigned long long sfp[512], sgp[512];
    __shared__ unsigned long long Pwp[256], Qwp[256], Ewp[256];
    __shared__ float sWt[256], sfb[16], sgb[16], sbs2[16];
    int tid = threadIdx.x;
    for (int i = tid; i < 512; i += 256) {
        float w = fW[i]; sfp[i] = pack2(w, w);
        float u = gW[i]; sgp[i] = pack2(u, u);
    }
    {
        int i = tid;
        int co = i >> 4, ci = i & 15;
        float a0 = gcW[co * 64 + ci];
        float a1 = gcW[co * 64 + 16 + ci];
        float a2 = gcW[co * 64 + 32 + ci];
        float a3 = gcW[co * 64 + 48 + ci];
        float pw = a0 + 2.f * EPSz * a1 - a2 - 2.f * EPSz * a3;
        float qw = a1 + a3;
        float ew = EPSz * (a0 + a2) + EPSz * EPSz * (a1 + a3);
        Pwp[i] = pack2(pw, pw);
        Qwp[i] = pack2(qw, qw);
        Ewp[i] = pack2(ew, ew);
        sWt[i] = sW[i];
    }
    if (tid < 16) { sfb[tid] = fb[tid]; sgb[tid] = gb[tid]; sbs2[tid] = sb[tid]; }
    __syncthreads();
    int Lp = L - d;
    int b = blockIdx.x / Lp, l = blockIdx.x % Lp;
    int v = tid * 2;
    unsigned long long x0p[16], x1p[16];
#pragma unroll
    for (int ci = 0; ci < 16; ci++) {
        const float* xp = x + (size_t)((b * 16 + ci) * L + l) * 512 + v;
        x0p[ci] = *reinterpret_cast<const unsigned long long*>(xp);
        x1p[ci] = *reinterpret_cast<const unsigned long long*>(xp + d * 512);
    }
    unsigned long long xgp[16];
#pragma unroll
    for (int co = 0; co < 16; co++) {
        unsigned long long f = pack2(sfb[co], sfb[co]);
        unsigned long long g = pack2(sgb[co], sgb[co]);
#pragma unroll
        for (int ci = 0; ci < 16; ci++) {
            int wi = (co * 16 + ci) * 2;
            FMA2(f, sfp[wi],     x0p[ci], f);
            FMA2(f, sfp[wi + 1], x1p[ci], f);
            FMA2(g, sgp[wi],     x0p[ci], g);
            FMA2(g, sgp[wi + 1], x1p[ci], g);
        }
        float f0, f1, g0, g1;
        unpack2(f, f0, f1);
        unpack2(g, g0, g1);
        float xg0 = tanhf(f0) * (1.f / (1.f + __expf(-g0)));
        float xg1 = tanhf(f1) * (1.f / (1.f + __expf(-g1)));
        xgp[co] = pack2(xg0, xg1);
    }
    if (l == Lp - 1) {
#pragma unroll
        for (int co = 0; co < 16; co++) {
            unsigned long long a = pack2(sbs2[co], sbs2[co]);
#pragma unroll
            for (int ci = 0; ci < 16; ci++) {
                unsigned long long wv = pack2(sWt[co * 16 + ci], sWt[co * 16 + ci]);
                FMA2(a, wv, xgp[ci], a);
            }
            float a0, a1;
            unpack2(a, a0, a1);
            int si = (b * 16 + co) * 512 + v;
            if (first) { skip[si] = a0; skip[si + 1] = a1; }
            else       { skip[si] += a0; skip[si + 1] += a1; }
        }
    }
#pragma unroll
    for (int co = 0; co < 16; co++) {
        unsigned long long p = 0ull, q = 0ull, e = 0ull;
#pragma unroll
        for (int ci = 0; ci < 16; ci++) {
            int wi = co * 16 + ci;
            FMA2(p, Pwp[wi], xgp[ci], p);
            FMA2(q, Qwp[wi], xgp[ci], q);
            FMA2(e, Ewp[wi], xgp[ci], e);
        }
        float p0, p1, q0, q1, e0, e1;
        unpack2(p, p0, p1);
        unpack2(q, q0, q1);
        unpack2(e, e0, e1);
        int row = (b * 16 + co) * Lp + l;
        __nv_bfloat162 h2, l2;
        split2(p0, p1, h2, l2);
        *reinterpret_cast<__nv_bfloat162*>(PQh + row * 1024 + v) = h2;
        *reinterpret_cast<__nv_bfloat162*>(PQl + row * 1024 + v) = l2;
        split2(q0, q1, h2, l2);
        *reinterpret_cast<__nv_bfloat162*>(PQh + row * 1024 + 512 + v) = h2;
        *reinterpret_cast<__nv_bfloat162*>(PQl + row * 1024 + 512 + v) = l2;
        *reinterpret_cast<float2*>(idt + row * 512 + v) = make_float2(e0, e1);
    }
}

// ---------------- main MMA GEMM (big layers): 64(M)x128(N) tiles, 3-stage ----------------
#define MMA_SMEM_BYTES 92160

__global__ void __launch_bounds__(256) k_mma(
    const __nv_bfloat16* __restrict__ Ah, const __nv_bfloat16* __restrict__ Al,
    const __nv_bfloat16* __restrict__ Bh, const __nv_bfloat16* __restrict__ Bl,
    const float* __restrict__ idt, const float* __restrict__ xprev, float* __restrict__ xnew,
    const float* __restrict__ gcb, const float* __restrict__ bng, const float* __restrict__ bnb,
    const float* __restrict__ bnm, const float* __restrict__ bnv,
    int Lp, int dil, int Lprev)
{
    extern __shared__ __align__(16) char smem_raw[];
    __shared__ float s_scale[16], s_shift[16], s_gb[16];
    uint32_t sbase = (uint32_t)__cvta_generic_to_shared(smem_raw);

    int t = threadIdx.x;
    if (t < 16) {
        float sc = bng[t] * rsqrtf(bnv[t] + 1e-5f);
        s_scale[t] = sc;
        s_shift[t] = bnb[t] - bnm[t] * sc;
        s_gb[t] = gcb[t];
    }

    int row0 = blockIdx.y * 64, col0 = blockIdx.x * 128;
    int warp = t >> 5, lane = t & 31;
    int wm = warp >> 2, wn = warp & 3;

    float acc[2][4][4];
#pragma unroll
    for (int i = 0; i < 2; i++)
#pragma unroll
        for (int j = 0; j < 4; j++)
#pragma unroll
            for (int r = 0; r < 4; r++) acc[i][j][r] = 0.f;

    int rA = t >> 2, kA = (t & 3) * 8;
    int rB0 = t >> 2, kB0 = (t & 3) * 8;
    int rB1 = 64 + (t >> 2), kB1 = (t & 3) * 8;

#define LOAD_STAGE(S, K0)                                                          \
    do {                                                                           \
        uint32_t sb_ = sbase + (uint32_t)(S) * 30720u;                             \
        const __nv_bfloat16* ga  = Ah + (size_t)(row0 + rA) * 1024 + (K0) + kA;    \
        const __nv_bfloat16* gb0 = Bh + (size_t)(col0 + rB0) * 1024 + (K0) + kB0;  \
        const __nv_bfloat16* gb1 = Bh + (size_t)(col0 + rB1) * 1024 + (K0) + kB1;  \
        uint32_t sa  = sb_ + (uint32_t)(rA * 40 + kA) * 2;                         \
        uint32_t sb0 = sb_ + 10240u + (uint32_t)(rB0 * 40 + kB0) * 2;              \
        uint32_t sb1 = sb_ + 10240u + (uint32_t)(rB1 * 40 + kB1) * 2;              \
        cpasync16(sa,          ga);                                                \
        cpasync16(sa + 5120u,  Al + (ga - Ah));                                    \
        cpasync16(sb0,          gb0);                                              \
        cpasync16(sb0 + 10240u, Bl + (gb0 - Bh));                                  \
        cpasync16(sb1,          gb1);                                              \
        cpasync16(sb1 + 10240u, Bl + (gb1 - Bh));                                  \
    } while (0)

    LOAD_STAGE(0, 0);
    CP_COMMIT();
    LOAD_STAGE(1, 32);
    CP_COMMIT();

    int ar = lane & 15, ah8 = (lane >> 4) << 3;
    int bq = lane >> 3, br = lane & 7;
    int bro = ((bq >> 1) << 3) + br, bco = (bq & 1) << 3;

    for (int it = 0; it < 32; it++) {
        CP_WAIT1();
        __syncthreads();
        int p = it % 3;
        uint32_t aH = sbase + (uint32_t)p * 30720u;
        uint32_t aL = aH + 5120u;
        uint32_t bH = aH + 10240u;
        uint32_t bL = aH + 20480u;
#pragma unroll
        for (int kc = 0; kc < 2; kc++) {
            uint32_t a_h[2][4], a_l[2][4], b_h[4][2], b_l[4][2];
#pragma unroll
            for (int mf = 0; mf < 2; mf++) {
                uint32_t off = (uint32_t)((wm * 32 + mf * 16 + ar) * 40 + kc * 16 + ah8) * 2;
                LDSM4(a_h[mf], aH + off);
                LDSM4(a_l[mf], aL + off);
            }
#pragma unroll
            for (int nb = 0; nb < 2; nb++) {
                uint32_t off = (uint32_t)((wn * 32 + nb * 16 + bro) * 40 + kc * 16 + bco) * 2;
                uint32_t rh[4], rl[4];
                LDSM4(rh, bH + off);
                LDSM4(rl, bL + off);
                b_h[2 * nb][0] = rh[0]; b_h[2 * nb][1] = rh[1];
                b_h[2 * nb + 1][0] = rh[2]; b_h[2 * nb + 1][1] = rh[3];
                b_l[2 * nb][0] = rl[0]; b_l[2 * nb][1] = rl[1];
                b_l[2 * nb + 1][0] = rl[2]; b_l[2 * nb + 1][1] = rl[3];
            }
#pragma unroll
            for (int mf = 0; mf < 2; mf++)
#pragma unroll
                for (int nf = 0; nf < 4; nf++) {
                    MMA16816(acc[mf][nf], a_h[mf], b_h[nf][0], b_h[nf][1]);
                    MMA16816(acc[mf][nf], a_h[mf], b_l[nf][0], b_l[nf][1]);
                    MMA16816(acc[mf][nf], a_l[mf], b_h[nf][0], b_h[nf][1]);
                }
        }
        if (it < 30) LOAD_STAGE((it + 2) % 3, (it + 2) * 32);
        CP_COMMIT();
    }

    int g = lane >> 2, tig = lane & 3;
#pragma unroll
    for (int mf = 0; mf < 2; mf++) {
#pragma unroll
        for (int h = 0; h < 2; h++) {
            int m = row0 + wm * 32 + mf * 16 + g + h * 8;
            int l = m % Lp;
            int bc = m / Lp;
            int co = bc & 15;
            float scale = s_scale[co], shift = s_shift[co], gb = s_gb[co];
            const float* idp  = idt + (size_t)m * 512;
            const float* resp = xprev + (size_t)(bc * Lprev + l + dil) * 512;
            float* op = xnew + (size_t)m * 512;
#pragma unroll
            for (int nf = 0; nf < 4; nf++) {
                int n = col0 + wn * 32 + nf * 8 + tig * 2;
                float v0 = acc[mf][nf][2 * h]     + idp[n]     + gb + resp[n];
                float v1 = acc[mf][nf][2 * h + 1] + idp[n + 1] + gb + resp[n + 1];
                op[n]     = v0 * scale + shift;
                op[n + 1] = v1 * scale + shift;
            }
        }
    }
}

// ---------------- tail MMA GEMM (small layers, Lp<=4): 32(M)x128(N) tiles, 3-stage ----------------
#define MMA32_SMEM_BYTES 76800

__global__ void __launch_bounds__(256) k_mma32(
    const __nv_bfloat16* __restrict__ Ah, const __nv_bfloat16* __restrict__ Al,
    const __nv_bfloat16* __restrict__ Bh, const __nv_bfloat16* __restrict__ Bl,
    const float* __restrict__ idt, const float* __restrict__ xprev, float* __restrict__ xnew,
    const float* __restrict__ gcb, const float* __restrict__ bng, const float* __restrict__ bnb,
    const float* __restrict__ bnm, const float* __restrict__ bnv,
    int Lp, int dil, int Lprev)
{
    extern __shared__ __align__(16) char smem_raw[];
    __shared__ float s_scale[16], s_shift[16], s_gb[16];
    uint32_t sbase = (uint32_t)__cvta_generic_to_shared(smem_raw);

    int t = threadIdx.x;
    if (t < 16) {
        float sc = bng[t] * rsqrtf(bnv[t] + 1e-5f);
        s_scale[t] = sc;
        s_shift[t] = bnb[t] - bnm[t] * sc;
        s_gb[t] = gcb[t];
    }

    int row0 = blockIdx.y * 32, col0 = blockIdx.x * 128;
    int warp = t >> 5, lane = t & 31;
    int wn = warp;

    float acc[2][2][4];
#pragma unroll
    for (int i = 0; i < 2; i++)
#pragma unroll
        for (int j = 0; j < 2; j++)
#pragma unroll
            for (int r = 0; r < 4; r++) acc[i][j][r] = 0.f;

    int tA = t & 127;
    int rA = tA >> 2, kA = (tA & 3) * 8;
    uint32_t aSel = (t < 128) ? 0u : 2560u;
    int rB0 = t >> 2, kB0 = (t & 3) * 8;
    int rB1 = 64 + (t >> 2), kB1 = (t & 3) * 8;

#define LOAD_STAGE32(S, K0)                                                        \
    do {                                                                           \
        uint32_t sb_ = sbase + (uint32_t)(S) * 25600u;                             \
        const __nv_bfloat16* gsrcA = (t < 128) ? Ah : Al;                          \
        cpasync16(sb_ + aSel + (uint32_t)(rA * 40 + kA) * 2,                       \
                  gsrcA + (size_t)(row0 + rA) * 1024 + (K0) + kA);                 \
        const __nv_bfloat16* gb0 = Bh + (size_t)(col0 + rB0) * 1024 + (K0) + kB0;  \
        const __nv_bfloat16* gb1 = Bh + (size_t)(col0 + rB1) * 1024 + (K0) + kB1;  \
        uint32_t sb0 = sb_ + 5120u + (uint32_t)(rB0 * 40 + kB0) * 2;               \
        uint32_t sb1 = sb_ + 5120u + (uint32_t)(rB1 * 40 + kB1) * 2;               \
        cpasync16(sb0,          gb0);                                              \
        cpasync16(sb0 + 10240u, Bl + (gb0 - Bh));                                  \
        cpasync16(sb1,          gb1);                                              \
        cpasync16(sb1 + 10240u, Bl + (gb1 - Bh));                                  \
    } while (0)

    LOAD_STAGE32(0, 0);
    CP_COMMIT();
    LOAD_STAGE32(1, 32);
    CP_COMMIT();

    int ar = lane & 15, ah8 = (lane >> 4) << 3;
    int bq = lane >> 3, br = lane & 7;
    int bro = ((bq >> 1) << 3) + br, bco = (bq & 1) << 3;

    for (int it = 0; it < 32; it++) {
        CP_WAIT1();
        __syncthreads();
        int p = it % 3;
        uint32_t aH = sbase + (uint32_t)p * 25600u;
        uint32_t aL = aH + 2560u;
        uint32_t bH = aH + 5120u;
        uint32_t bL = aH + 15360u;
#pragma unroll
        for (int kc = 0; kc < 2; kc++) {
            uint32_t a_h[2][4], a_l[2][4], b_h[2][2], b_l[2][2];
#pragma unroll
            for (int mf = 0; mf < 2; mf++) {
                uint32_t off = (uint32_t)((mf * 16 + ar) * 40 + kc * 16 + ah8) * 2;
                LDSM4(a_h[mf], aH + off);
                LDSM4(a_l[mf], aL + off);
            }
            {
                uint32_t off = (uint32_t)((wn * 16 + bro) * 40 + kc * 16 + bco) * 2;
                uint32_t rh[4], rl[4];
                LDSM4(rh, bH + off);
                LDSM4(rl, bL + off);
                b_h[0][0] = rh[0]; b_h[0][1] = rh[1];
                b_h[1][0] = rh[2]; b_h[1][1] = rh[3];
                b_l[0][0] = rl[0]; b_l[0][1] = rl[1];
                b_l[1][0] = rl[2]; b_l[1][1] = rl[3];
            }
#pragma unroll
            for (int mf = 0; mf < 2; mf++)
#pragma unroll
                for (int nf = 0; nf < 2; nf++) {
                    MMA16816(acc[mf][nf], a_h[mf], b_h[nf][0], b_h[nf][1]);
                    MMA16816(acc[mf][nf], a_h[mf], b_l[nf][0], b_l[nf][1]);
                    MMA16816(acc[mf][nf], a_l[mf], b_h[nf][0], b_h[nf][1]);
                }
        }
        if (it < 30) LOAD_STAGE32((it + 2) % 3, (it + 2) * 32);
        CP_COMMIT();
    }

    int g = lane >> 2, tig = lane & 3;
#pragma unroll
    for (int mf = 0; mf < 2; mf++) {
#pragma unroll
        for (int h = 0; h < 2; h++) {
            int m = row0 + mf * 16 + g + h * 8;
            int l = m % Lp;
            int bc = m / Lp;
            int co = bc & 15;
            float scale = s_scale[co], shift = s_shift[co], gb = s_gb[co];
            const float* idp  = idt + (size_t)m * 512;
            const float* resp = xprev + (size_t)(bc * Lprev + l + dil) * 512;
            float* op = xnew + (size_t)m * 512;
#pragma unroll
            for (int nf = 0; nf < 2; nf++) {
                int n = col0 + wn * 16 + nf * 8 + tig * 2;
                float v0 = acc[mf][nf][2 * h]     + idp[n]     + gb + resp[n];
                float v1 = acc[mf][nf][2 * h + 1] + idp[n + 1] + gb + resp[n + 1];
                op[n]     = v0 * scale + shift;
                op[n + 1] = v1 * scale + shift;
            }
        }
    }
}

// ---------------- K9: end convs ----------------
__global__ void k_end(const float* __restrict__ skip,
                      const float* __restrict__ w1, const float* __restrict__ b1,
                      const float* __restrict__ w2, const float* __restrict__ b2,
                      float* __restrict__ out)
{
    int tid = blockIdx.x * 128 + threadIdx.x;
    int b = tid >> 9, v = tid & 511;
    float s[16];
#pragma unroll
    for (int c = 0; c < 16; c++) s[c] = fmaxf(skip[(b * 16 + c) * 512 + v], 0.f);
    float e1[16];
#pragma unroll
    for (int c = 0; c < 16; c++) {
        float a = b1[c];
#pragma unroll
        for (int ci = 0; ci < 16; ci++) a += w1[c * 16 + ci] * s[ci];
        e1[c] = fmaxf(a, 0.f);
    }
#pragma unroll
    for (int h = 0; h < 12; h++) {
        float a = b2[h];
#pragma unroll
        for (int c = 0; c < 16; c++) a += w2[h * 16 + c] * e1[c];
        out[(b * 12 + h) * 512 + v] = a;
    }
}

// ======================== host orchestration ========================
extern "C" void kernel_launch(void* const* d_in, const int* in_sizes, int n_in,
                              void* d_out, int out_size)
{
    const float* input  = (const float*)d_in[0];
    const float* startW = (const float*)d_in[1];
    const float* startb = (const float*)d_in[2];
    const float* filtW  = (const float*)d_in[3];
    const float* filtb  = (const float*)d_in[4];
    const float* gateW  = (const float*)d_in[5];
    const float* gateb  = (const float*)d_in[6];
    const float* skipW  = (const float*)d_in[7];
    const float* skipb  = (const float*)d_in[8];
    const float* gconvW = (const float*)d_in[9];
    const float* gconvb = (const float*)d_in[10];
    const float* bng    = (const float*)d_in[11];
    const float* bnb    = (const float*)d_in[12];
    const float* bnm    = (const float*)d_in[13];
    const float* bnv    = (const float*)d_in[14];
    const float* e1W    = (const float*)d_in[15];
    const float* e1b    = (const float*)d_in[16];
    const float* e2W    = (const float*)d_in[17];
    const float* e2b    = (const float*)d_in[18];
    const float* linW   = (const float*)d_in[19];
    const float* linb   = (const float*)d_in[20];
    const float* f1W    = (const float*)d_in[21];
    const float* f1b    = (const float*)d_in[22];
    const float* f2W    = (const float*)d_in[23];
    const float* f2b    = (const float*)d_in[24];
    const float* f3W    = (const float*)d_in[25];
    const float* f3b    = (const float*)d_in[26];
    float* out = (float*)d_out;

    float *p_real, *p_img, *p_iffp, *p_AA2, *p_bs;
    float *p_xa, *p_xb, *p_idt, *p_skip;
    __nv_bfloat16 *p_Fh, *p_Fl, *p_Wh, *p_Wl, *p_Bth, *p_Btl, *p_PQh, *p_PQl;
    cudaGetSymbolAddress((void**)&p_real, g_real);
    cudaGetSymbolAddress((void**)&p_img,  g_img);
    cudaGetSymbolAddress((void**)&p_iffp, g_iffp);
    cudaGetSymbolAddress((void**)&p_AA2,  g_AA2);
    cudaGetSymbolAddress((void**)&p_Fh,   g_Fh);
    cudaGetSymbolAddress((void**)&p_Fl,   g_Fl);
    cudaGetSymbolAddress((void**)&p_Wh,   g_Wh);
    cudaGetSymbolAddress((void**)&p_Wl,   g_Wl);
    cudaGetSymbolAddress((void**)&p_bs,   g_bs);
    cudaGetSymbolAddress((void**)&p_Bth,  g_Bth);
    cudaGetSymbolAddress((void**)&p_Btl,  g_Btl);
    cudaGetSymbolAddress((void**)&p_xa,   g_xa);
    cudaGetSymbolAddress((void**)&p_xb,   g_xb);
    cudaGetSymbolAddress((void**)&p_PQh,  g_PQh);
    cudaGetSymbolAddress((void**)&p_PQl,  g_PQl);
    cudaGetSymbolAddress((void**)&p_idt,  g_idt);
    cudaGetSymbolAddress((void**)&p_skip, g_skip);

    static int smem_set = 0;
    if (!smem_set) {
        cudaFuncSetAttribute(k_mma, cudaFuncAttributeMaxDynamicSharedMemorySize, MMA_SMEM_BYTES);
        cudaFuncSetAttribute(k_mma32, cudaFuncAttributeMaxDynamicSharedMemorySize, MMA32_SMEM_BYTES);
        cudaFuncSetAttribute(k_adjmma, cudaFuncAttributeMaxDynamicSharedMemorySize, ADJ_SMEM);
        smem_set = 1;
    }

    // ---- graph learner ----
    k_dft<<<256, 64>>>(input, linW, linb, p_real, p_img, p_Fh, p_Fl);
    k_iff_part<<<dim3(32, 16), 512>>>(p_real, p_img, p_iffp);
    k_iff_red<<<1280, 256>>>(p_iffp, p_Fh, p_Fl);
    k_wprep<<<64, 256>>>(f1W, f1b, f2W, f2b, f3W, f3b, p_Wh, p_Wl, p_bs);
    float* adj_out = (out_size >= Bz * HORz * Vz + Vz * Vz) ? out + Bz * HORz * Vz : nullptr;
    k_adjmma<<<dim3(4, 128), 256, ADJ_SMEM>>>(p_Fh, p_Fl, p_Wh, p_Wl, p_bs, p_AA2, adj_out);
    k_gemm_plain<<<dim3(8, 8), 256>>>(p_AA2, p_AA2, p_AA2 + Vz * Vz, 512);
    k_prepB<<<dim3(16, 32), dim3(32, 8)>>>(p_AA2, p_Bth, p_Btl);

    // ---- trunk ----
    k_start<<<13312, 256>>>(input, startW, startb, p_xa);

    float* xc = p_xa;
    float* xn = p_xb;
    int L = RFz;
    const int dils[NLz] = {1, 2, 1, 2, 1, 2, 1, 2};
    for (int i = 0; i < NLz; i++) {
        int d = dils[i];
        int Lp = L - d;
        k_fused<<<Bz * Lp, 256>>>(xc, filtW + i * 512, filtb + i * 16,
                                  gateW + i * 512, gateb + i * 16,
                                  gconvW + i * 1024, skipW + i * 256, skipb + i * 16,
                                  p_PQh, p_PQl, p_idt, p_skip, L, d, (i == 0) ? 1 : 0);
        int M = Bz * CHz * Lp;
        if (Lp > 4) {
            k_mma<<<dim3(4, M / 64), 256, MMA_SMEM_BYTES>>>(p_PQh, p_PQl, p_Bth, p_Btl,
                                                            p_idt, xc, xn,
                                                            gconvb + i * 16, bng + i * 16, bnb + i * 16,
                                                            bnm + i * 16, bnv + i * 16, Lp, d, L);
        } else {
            k_mma32<<<dim3(4, M / 32), 256, MMA32_SMEM_BYTES>>>(p_PQh, p_PQl, p_Bth, p_Btl,
                                                                p_idt, xc, xn,
                                                                gconvb + i * 16, bng + i * 16, bnb + i * 16,
                                                                bnm + i * 16, bnv + i * 16, Lp, d, L);
        }
        float* tmp = xc; xc = xn; xn = tmp;
        L = Lp;
    }

    k_end<<<128, 128>>>(p_skip, e1W, e1b, e2W, e2b, out);
}

// round 16
// speedup vs baseline: 1.2377x; 1.1756x over previous
#include <cuda_runtime.h>
#include <cuda_bf16.h>
#include <math.h>
#include <stdint.h>

#define Bz   32
#define Vz   512
#define Tz   12
#define DGz  20
#define CHz  16
#define HORz 12
#define RFz  13
#define NLz  8
#define EPSz 0.3f

// ---------------- scratch ----------------
__device__ float g_real[Bz*Vz*DGz];
__device__ float g_img [Bz*Vz*DGz];
__device__ float g_iffp[16*Bz*Vz*DGz];
__device__ float g_AA2 [2*Vz*Vz];
__device__ __align__(16) __nv_bfloat16 g_Fh[Bz*Vz*64];
__device__ __align__(16) __nv_bfloat16 g_Fl[Bz*Vz*64];
__device__ __align__(16) __nv_bfloat16 g_Wh[Vz*64];
__device__ __align__(16) __nv_bfloat16 g_Wl[Vz*64];
__device__ float g_bs[Vz];
__device__ __align__(16) __nv_bfloat16 g_Bth[Vz*1024];
__device__ __align__(16) __nv_bfloat16 g_Btl[Vz*1024];
__device__ float g_xa  [Bz*CHz*RFz*Vz];
__device__ float g_xb  [Bz*CHz*RFz*Vz];
__device__ __align__(16) __nv_bfloat16 g_PQh[Bz*CHz*Tz*1024];
__device__ __align__(16) __nv_bfloat16 g_PQl[Bz*CHz*Tz*1024];
__device__ float g_idt [Bz*CHz*Tz*Vz];
__device__ float g_skip[Bz*CHz*Vz];

// ---------------- PTX helpers ----------------
__device__ __forceinline__ void cpasync16(uint32_t s, const void* g) {
    asm volatile("cp.async.cg.shared.global [%0], [%1], 16;\n" :: "r"(s), "l"(g));
}
#define CP_COMMIT() asm volatile("cp.async.commit_group;\n" ::)
#define CP_WAIT0()  asm volatile("cp.async.wait_group 0;\n" ::)
#define CP_WAIT1()  asm volatile("cp.async.wait_group 1;\n" ::)

#define LDSM4(R, addr) \
    asm volatile("ldmatrix.sync.aligned.m8n8.x4.shared.b16 {%0,%1,%2,%3}, [%4];" \
        : "=r"((R)[0]), "=r"((R)[1]), "=r"((R)[2]), "=r"((R)[3]) : "r"(addr))

#define MMA16816(C, A, B0, B1) \
    asm volatile("mma.sync.aligned.m16n8k16.row.col.f32.bf16.bf16.f32 " \
        "{%0,%1,%2,%3},{%4,%5,%6,%7},{%8,%9},{%0,%1,%2,%3};" \
        : "+f"((C)[0]), "+f"((C)[1]), "+f"((C)[2]), "+f"((C)[3]) \
        : "r"((A)[0]), "r"((A)[1]), "r"((A)[2]), "r"((A)[3]), "r"(B0), "r"(B1))

// packed f32x2 fma: d = a*b + c (per 32-bit lane)
#define FMA2(D, A, B, C) \
    asm("fma.rn.f32x2 %0, %1, %2, %3;" : "=l"(D) : "l"(A), "l"(B), "l"(C))

__device__ __forceinline__ unsigned long long pack2(float a, float b) {
    unsigned long long r;
    asm("mov.b64 %0, {%1, %2};" : "=l"(r) : "f"(a), "f"(b));
    return r;
}
__device__ __forceinline__ void unpack2(unsigned long long p, float& a, float& b) {
    asm("mov.b64 {%0, %1}, %2;" : "=f"(a), "=f"(b) : "l"(p));
}

__device__ __forceinline__ void split2(float a, float b,
                                       __nv_bfloat162& hi, __nv_bfloat162& lo) {
    __nv_bfloat16 ha = __float2bfloat16(a), hb = __float2bfloat16(b);
    hi = __halves2bfloat162(ha, hb);
    lo = __floats2bfloat162_rn(a - __bfloat162float(ha), b - __bfloat162float(hb));
}

// ---------------- K0: DFT(24) + lin projection (f32x2 packed) ----------------
__global__ void __launch_bounds__(64) k_dft(
    const float* __restrict__ input, const float* __restrict__ lW,
    const float* __restrict__ lb, float* __restrict__ re, float* __restrict__ im,
    __nv_bfloat16* __restrict__ Fh, __nv_bfloat16* __restrict__ Fl)
{
    __shared__ unsigned long long cst[24];   // (cos, -sin) packed
    if (threadIdx.x < 24) {
        float c = cospif(threadIdx.x / 12.f);
        float s = sinpif(threadIdx.x / 12.f);
        cst[threadIdx.x] = pack2(c, -s);
    }
    __syncthreads();
    int tid = blockIdx.x * 64 + threadIdx.x;
    int b = tid >> 9, v = tid & 511;
    unsigned long long xrp[24];
#pragma unroll
    for (int t = 0; t < 12; t++) {
        int base = ((t * 32 + b) * 512 + v) * 2;
        float a0 = input[base], a1 = input[base + 1];
        xrp[2 * t]     = pack2(a0, a0);
        xrp[2 * t + 1] = pack2(a1, a1);
    }
    unsigned long long fri[24];   // (fr, fi) packed per harmonic
#pragma unroll
    for (int n = 0; n < 24; n++) {
        unsigned long long s = 0ull;
        int idx = 0;
#pragma unroll
        for (int k = 0; k < 24; k++) {
            FMA2(s, xrp[k], cst[idx], s);
            idx += n; if (idx >= 24) idx -= 24;
        }
        fri[n] = s;
    }
    int go = (b * 512 + v) * 20;
    int frow = (v * 32 + b) * 64;
#pragma unroll
    for (int d = 0; d < 20; d += 2) {
        unsigned long long rq0 = pack2(lb[d], lb[d]);
        unsigned long long rq1 = pack2(lb[d + 1], lb[d + 1]);
#pragma unroll
        for (int n = 0; n < 24; n++) {
            float w0 = lW[d * 24 + n], w1 = lW[(d + 1) * 24 + n];
            FMA2(rq0, pack2(w0, w0), fri[n], rq0);
            FMA2(rq1, pack2(w1, w1), fri[n], rq1);
        }
        float r0, q0, r1, q1;
        unpack2(rq0, r0, q0);
        unpack2(rq1, r1, q1);
        re[go + d] = r0; re[go + d + 1] = r1;
        im[go + d] = q0; im[go + d + 1] = q1;
        float am0 = sqrtf(r0 * r0 + q0 * q0), am1 = sqrtf(r1 * r1 + q1 * q1);
        float ss0 = atanf(r0 / (q0 + 1e-4f)), ss1 = atanf(r1 / (q1 + 1e-4f));
        __nv_bfloat162 h2, l2;
        split2(am0, am1, h2, l2);
        *reinterpret_cast<__nv_bfloat162*>(Fh + frow + 20 + d) = h2;
        *reinterpret_cast<__nv_bfloat162*>(Fl + frow + 20 + d) = l2;
        split2(ss0, ss1, h2, l2);
        *reinterpret_cast<__nv_bfloat162*>(Fh + frow + 40 + d) = h2;
        *reinterpret_cast<__nv_bfloat162*>(Fl + frow + 40 + d) = l2;
    }
    *reinterpret_cast<uint32_t*>(Fh + frow + 60) = 0u;
    *reinterpret_cast<uint32_t*>(Fh + frow + 62) = 0u;
    *reinterpret_cast<uint32_t*>(Fl + frow + 60) = 0u;
    *reinterpret_cast<uint32_t*>(Fl + frow + 62) = 0u;
}

// ---------------- K1a: irfft partials (f32x2 packed over d-pairs) ----------------
__global__ void __launch_bounds__(512) k_iff_part(
    const float* __restrict__ re, const float* __restrict__ im, float* __restrict__ iffp)
{
    __shared__ float ct[512], st[512];
    int m = threadIdx.x;
    ct[m] = cospif(m / 256.f);
    st[m] = sinpif(m / 256.f);
    __syncthreads();
    int b = blockIdx.x, c = blockIdx.y;
    const float* R = re + b * 512 * 20;
    const float* I = im + b * 512 * 20;
    unsigned long long acc[10];
    if (c == 0) {
        float sg = (m & 1) ? -1.f : 1.f;
        unsigned long long sgp = pack2(sg, sg);
#pragma unroll
        for (int d = 0; d < 10; d++) {
            unsigned long long r0 = *reinterpret_cast<const unsigned long long*>(R + 2 * d);
            unsigned long long rN = *reinterpret_cast<const unsigned long long*>(R + 256 * 20 + 2 * d);
            FMA2(acc[d], sgp, rN, r0);
        }
    } else {
#pragma unroll
        for (int d = 0; d < 10; d++) acc[d] = 0ull;
    }
    int k0 = (c == 0) ? 1 : c * 16;
    int k1 = c * 16 + 16;
    int idx = (k0 * m) & 511;
    for (int k = k0; k < k1; k++) {
        float cc = 2.f * ct[idx], ss = -2.f * st[idx];
        unsigned long long ccp = pack2(cc, cc), ssp = pack2(ss, ss);
        const unsigned long long* Rp = reinterpret_cast<const unsigned long long*>(R + k * 20);
        const unsigned long long* Ip = reinterpret_cast<const unsigned long long*>(I + k * 20);
#pragma unroll
        for (int d = 0; d < 10; d++) {
            FMA2(acc[d], ccp, Rp[d], acc[d]);
            FMA2(acc[d], ssp, Ip[d], acc[d]);
        }
        idx = (idx + m) & 511;
    }
    int go = ((c * 32 + b) * 512 + m) * 20;
    unsigned long long* op = reinterpret_cast<unsigned long long*>(iffp + go);
#pragma unroll
    for (int d = 0; d < 10; d++) op[d] = acc[d];
}

// ---------------- K1b: reduce -> feat cols 0..19 ----------------
__global__ void k_iff_red(const float* __restrict__ iffp,
                          __nv_bfloat16* __restrict__ Fh, __nv_bfloat16* __restrict__ Fl)
{
    int i = blockIdx.x * 256 + threadIdx.x;
    const int Sz = Bz * Vz * DGz;
    int d = i % 20;
    int r = i / 20;
    int v = r & 511, b = r >> 9;
    float s = 0.f;
#pragma unroll
    for (int c = 0; c < 16; c++) s += iffp[c * Sz + i];
    s *= (1.f / 512.f);
    __nv_bfloat16 h = __float2bfloat16(s);
    int o = (v * 32 + b) * 64 + d;
    Fh[o] = h;
    Fl[o] = __float2bfloat16(s - __bfloat162float(h));
}

// ---------------- Wprep (parallel: 16384 threads) ----------------
__global__ void k_wprep(const float* __restrict__ f1W, const float* __restrict__ f1b,
                        const float* __restrict__ f2W, const float* __restrict__ f2b,
                        const float* __restrict__ f3W, const float* __restrict__ f3b,
                        __nv_bfloat16* __restrict__ Wh, __nv_bfloat16* __restrict__ Wl,
                        float* __restrict__ bs)
{
    int t = blockIdx.x * 256 + threadIdx.x;   // 16384
    int w = t >> 5, d = t & 31;
    const float inv3 = 1.f / 3.f;
    if (d < 20) {
        float a = f1W[w * 20 + d] * inv3;
        __nv_bfloat16 h = __float2bfloat16(a);
        Wh[w * 64 + d] = h; Wl[w * 64 + d] = __float2bfloat16(a - __bfloat162float(h));
        a = f2W[w * 20 + d] * inv3;
        h = __float2bfloat16(a);
        Wh[w * 64 + 20 + d] = h; Wl[w * 64 + 20 + d] = __float2bfloat16(a - __bfloat162float(h));
        a = f3W[w * 20 + d] * inv3;
        h = __float2bfloat16(a);
        Wh[w * 64 + 40 + d] = h; Wl[w * 64 + 40 + d] = __float2bfloat16(a - __bfloat162float(h));
    } else if (d < 24) {
        Wh[w * 64 + 40 + d] = __float2bfloat16(0.f);
        Wl[w * 64 + 40 + d] = __float2bfloat16(0.f);
    } else if (d == 24) {
        bs[w] = (f1b[w] + f2b[w] + f3b[w]) * inv3;
    }
}

// ---------------- K2: adj via MMA + sigmoid + batch-reduce ----------------
#define ADJ_SMEM 73728
__global__ void __launch_bounds__(256) k_adjmma(
    const __nv_bfloat16* __restrict__ Fh, const __nv_bfloat16* __restrict__ Fl,
    const __nv_bfloat16* __restrict__ Wh, const __nv_bfloat16* __restrict__ Wl,
    const float* __restrict__ bs, float* __restrict__ AA2, float* __restrict__ adj_out)
{
    extern __shared__ __align__(16) char smem_raw[];
    __shared__ float sbs[128];
    uint32_t sbase = (uint32_t)__cvta_generic_to_shared(smem_raw);
    float* Stile = (float*)smem_raw;
    int t = threadIdx.x;
    int row0 = blockIdx.y * 128, col0 = blockIdx.x * 128;
    if (t < 128) sbs[t] = bs[col0 + t];
#pragma unroll
    for (int i = 0; i < 4; i++) {
        int c = t + i * 256;
        int row = c >> 3, col8 = (c & 7) * 8;
        uint32_t so = (uint32_t)(row * 72 + col8) * 2;
        const __nv_bfloat16* gA = Fh + (size_t)(row0 + row) * 64 + col8;
        const __nv_bfloat16* gB = Wh + (size_t)(col0 + row) * 64 + col8;
        cpasync16(sbase + so,           gA);
        cpasync16(sbase + 18432u + so,  Fl + (gA - Fh));
        cpasync16(sbase + 36864u + so,  gB);
        cpasync16(sbase + 55296u + so,  Wl + (gB - Wh));
    }
    CP_COMMIT();
    CP_WAIT0();
    __syncthreads();

    int warp = t >> 5, lane = t & 31;
    int wm = warp >> 2, wn = warp & 3;
    float acc[4][4][4];
#pragma unroll
    for (int i = 0; i < 4; i++)
#pragma unroll
        for (int j = 0; j < 4; j++)
#pragma unroll
            for (int r = 0; r < 4; r++) acc[i][j][r] = 0.f;

    int ar = lane & 15, ah8 = (lane >> 4) << 3;
    int bq = lane >> 3, br = lane & 7;
    int bro = ((bq >> 1) << 3) + br, bco = (bq & 1) << 3;
    uint32_t aH = sbase, aL = sbase + 18432u, bH = sbase + 36864u, bL = sbase + 55296u;
#pragma unroll
    for (int kc = 0; kc < 4; kc++) {
        uint32_t a_h[4][4], a_l[4][4], b_h[4][2], b_l[4][2];
#pragma unroll
        for (int mf = 0; mf < 4; mf++) {
            uint32_t off = (uint32_t)((wm * 64 + mf * 16 + ar) * 72 + kc * 16 + ah8) * 2;
            LDSM4(a_h[mf], aH + off);
            LDSM4(a_l[mf], aL + off);
        }
#pragma unroll
        for (int nb = 0; nb < 2; nb++) {
            uint32_t off = (uint32_t)((wn * 32 + nb * 16 + bro) * 72 + kc * 16 + bco) * 2;
            uint32_t rh[4], rl[4];
            LDSM4(rh, bH + off);
            LDSM4(rl, bL + off);
            b_h[2 * nb][0] = rh[0]; b_h[2 * nb][1] = rh[1];
            b_h[2 * nb + 1][0] = rh[2]; b_h[2 * nb + 1][1] = rh[3];
            b_l[2 * nb][0] = rl[0]; b_l[2 * nb][1] = rl[1];
            b_l[2 * nb + 1][0] = rl[2]; b_l[2 * nb + 1][1] = rl[3];
        }
#pragma unroll
        for (int mf = 0; mf < 4; mf++)
#pragma unroll
            for (int nf = 0; nf < 4; nf++) {
                MMA16816(acc[mf][nf], a_h[mf], b_h[nf][0], b_h[nf][1]);
                MMA16816(acc[mf][nf], a_h[mf], b_l[nf][0], b_l[nf][1]);
                MMA16816(acc[mf][nf], a_l[mf], b_h[nf][0], b_h[nf][1]);
            }
    }
    __syncthreads();

    int g = lane >> 2, tig = lane & 3;
#pragma unroll
    for (int mf = 0; mf < 4; mf++)
#pragma unroll
        for (int h = 0; h < 2; h++) {
            int r = wm * 64 + mf * 16 + g + h * 8;
#pragma unroll
            for (int nf = 0; nf < 4; nf++) {
                int cl = wn * 32 + nf * 8 + tig * 2;
                float l0 = acc[mf][nf][2 * h]     + sbs[cl];
                float l1 = acc[mf][nf][2 * h + 1] + sbs[cl + 1];
                Stile[r * 132 + cl]     = 1.f / (1.f + __expf(-l0));
                Stile[r * 132 + cl + 1] = 1.f / (1.f + __expf(-l1));
            }
        }
    __syncthreads();

    int v0 = row0 >> 5;
#pragma unroll
    for (int o = t; o < 512; o += 256) {
        int vi = o >> 7, w = o & 127;
        float s = 0.f;
#pragma unroll
        for (int b2 = 0; b2 < 32; b2++) s += Stile[(vi * 32 + b2) * 132 + w];
        float a = 1.f / (1.f + __expf(-s * (1.f / 32.f)));
        int vv = v0 + vi, ww = col0 + w;
        AA2[vv * 512 + ww] = a;
        if (adj_out) adj_out[vv * 512 + ww] = a;
    }
}

// ---------------- SGEMM adj@adj (fp32, small) ----------------
__global__ void __launch_bounds__(256) k_gemm_plain(
    const float* __restrict__ Aq, const float* __restrict__ Bq, float* __restrict__ C, int K)
{
    __shared__ float As[16][65];
    __shared__ float Bs[16][64];
    int t = threadIdx.x;
    int tx = t & 15, ty = t >> 4;
    int row0 = blockIdx.y * 64, col0 = blockIdx.x * 64;
    float acc[4][4] = {};
    int mA = t >> 2, kA = (t & 3) << 2;
    int kB = t >> 4, nB = (t & 15) << 2;
    const float* aptr = Aq + (row0 + mA) * K + kA;
    const float* bptr = Bq + kB * 512 + col0 + nB;
    for (int k0 = 0; k0 < K; k0 += 16) {
        float4 a4 = *reinterpret_cast<const float4*>(aptr + k0);
        float4 b4 = *reinterpret_cast<const float4*>(bptr + k0 * 512);
        As[kA + 0][mA] = a4.x; As[kA + 1][mA] = a4.y;
        As[kA + 2][mA] = a4.z; As[kA + 3][mA] = a4.w;
        *reinterpret_cast<float4*>(&Bs[kB][nB]) = b4;
        __syncthreads();
#pragma unroll
        for (int kk = 0; kk < 16; kk++) {
            float a0 = As[kk][ty * 4 + 0], a1 = As[kk][ty * 4 + 1];
            float a2 = As[kk][ty * 4 + 2], a3 = As[kk][ty * 4 + 3];
            float4 br = *reinterpret_cast<const float4*>(&Bs[kk][tx * 4]);
            acc[0][0] += a0 * br.x; acc[0][1] += a0 * br.y; acc[0][2] += a0 * br.z; acc[0][3] += a0 * br.w;
            acc[1][0] += a1 * br.x; acc[1][1] += a1 * br.y; acc[1][2] += a1 * br.z; acc[1][3] += a1 * br.w;
            acc[2][0] += a2 * br.x; acc[2][1] += a2 * br.y; acc[2][2] += a2 * br.z; acc[2][3] += a2 * br.w;
            acc[3][0] += a3 * br.x; acc[3][1] += a3 * br.y; acc[3][2] += a3 * br.z; acc[3][3] += a3 * br.w;
        }
        __syncthreads();
    }
#pragma unroll
    for (int i = 0; i < 4; i++)
#pragma unroll
        for (int j = 0; j < 4; j++)
            C[(row0 + ty * 4 + i) * 512 + col0 + tx * 4 + j] = acc[i][j];
}

// ---------------- prepB: transpose AA2 [1024x512] -> Bt hi/lo [512x1024] ----------------
__global__ void k_prepB(const float* __restrict__ AA2,
                        __nv_bfloat16* __restrict__ Bth, __nv_bfloat16* __restrict__ Btl)
{
    __shared__ float tile[32][33];
    int k0 = blockIdx.y * 32, n0 = blockIdx.x * 32;
    int tx = threadIdx.x, ty = threadIdx.y;
#pragma unroll
    for (int i = 0; i < 4; i++)
        tile[ty + i * 8][tx] = AA2[(k0 + ty + i * 8) * 512 + n0 + tx];
    __syncthreads();
#pragma unroll
    for (int i = 0; i < 4; i++) {
        int r = ty + i * 8;
        float v = tile[tx][r];
        __nv_bfloat16 hi = __float2bfloat16(v);
        __nv_bfloat16 lo = __float2bfloat16(v - __bfloat162float(hi));
        int o = (n0 + r) * 1024 + k0 + tx;
        Bth[o] = hi; Btl[o] = lo;
    }
}

// ---------------- K4: pad + start 1x1 conv ----------------
__global__ void k_start(const float* __restrict__ input, const float* __restrict__ sW,
                        const float* __restrict__ sb, float* __restrict__ x0)
{
    int idx = blockIdx.x * 256 + threadIdx.x;
    int v = idx & 511;
    int r = idx >> 9;
    int l = r % 13; r /= 13;
    int c = r & 15; int b = r >> 4;
    float val = sb[c];
    if (l > 0) {
        int t = l - 1;
        const float* ip = input + ((t * 32 + b) * 512 + v) * 2;
        val += sW[c * 2] * ip[0] + sW[c * 2 + 1] * ip[1];
    }
    x0[idx] = val;
}

// ---------------- fused producer (f32x2 packed FMA) ----------------
__global__ void __launch_bounds__(256) k_fused(
    const float* __restrict__ x,
    const float* __restrict__ fW, const float* __restrict__ fb,
    const float* __restrict__ gW, const float* __restrict__ gb,
    const float* __restrict__ gcW,
    const float* __restrict__ sW, const float* __restrict__ sb,
    __nv_bfloat16* __restrict__ PQh, __nv_bfloat16* __restrict__ PQl,
    float* __restrict__ idt, float* __restrict__ skip,
    int L, int d, int first)
{
    __shared__ unsigned long long sfp[512], sgp[512];
    __shared__ unsigned long long Pwp[256], Qwp[256], Ewp[256];
    __shared__ float sWt[256], sfb[16], sgb[16], sbs2[16];
    int tid = threadIdx.x;
    for (int i = tid; i < 512; i += 256) {
        float w = fW[i]; sfp[i] = pack2(w, w);
        float u = gW[i]; sgp[i] = pack2(u, u);
    }
    {
        int i = tid;
        int co = i >> 4, ci = i & 15;
        float a0 = gcW[co * 64 + ci];
        float a1 = gcW[co * 64 + 16 + ci];
        float a2 = gcW[co * 64 + 32 + ci];
        float a3 = gcW[co * 64 + 48 + ci];
        float pw = a0 + 2.f * EPSz * a1 - a2 - 2.f * EPSz * a3;
        float qw = a1 + a3;
        float ew = EPSz * (a0 + a2) + EPSz * EPSz * (a1 + a3);
        Pwp[i] = pack2(pw, pw);
        Qwp[i] = pack2(qw, qw);
        Ewp[i] = pack2(ew, ew);
        sWt[i] = sW[i];
    }
    if (tid < 16) { sfb[tid] = fb[tid]; sgb[tid] = gb[tid]; sbs2[tid] = sb[tid]; }
    __syncthreads();
    int Lp = L - d;
    int b = blockIdx.x / Lp, l = blockIdx.x % Lp;
    int v = tid * 2;
    unsigned long long x0p[16], x1p[16];
#pragma unroll
    for (int ci = 0; ci < 16; ci++) {
        const float* xp = x + (size_t)((b * 16 + ci) * L + l) * 512 + v;
        x0p[ci] = *reinterpret_cast<const unsigned long long*>(xp);
        x1p[ci] = *reinterpret_cast<const unsigned long long*>(xp + d * 512);
    }
    unsigned long long xgp[16];
#pragma unroll
    for (int co = 0; co < 16; co++) {
        unsigned long long f = pack2(sfb[co], sfb[co]);
        unsigned long long g = pack2(sgb[co], sgb[co]);
#pragma unroll
        for (int ci = 0; ci < 16; ci++) {
            int wi = (co * 16 + ci) * 2;
            FMA2(f, sfp[wi],     x0p[ci], f);
            FMA2(f, sfp[wi + 1], x1p[ci], f);
            FMA2(g, sgp[wi],     x0p[ci], g);
            FMA2(g, sgp[wi + 1], x1p[ci], g);
        }
        float f0, f1, g0, g1;
        unpack2(f, f0, f1);
        unpack2(g, g0, g1);
        float xg0 = tanhf(f0) * (1.f / (1.f + __expf(-g0)));
        float xg1 = tanhf(f1) * (1.f / (1.f + __expf(-g1)));
        xgp[co] = pack2(xg0, xg1);
    }
    if (l == Lp - 1) {
#pragma unroll
        for (int co = 0; co < 16; co++) {
            unsigned long long a = pack2(sbs2[co], sbs2[co]);
#pragma unroll
            for (int ci = 0; ci < 16; ci++) {
                unsigned long long wv = pack2(sWt[co * 16 + ci], sWt[co * 16 + ci]);
                FMA2(a, wv, xgp[ci], a);
            }
            float a0, a1;
            unpack2(a, a0, a1);
            int si = (b * 16 + co) * 512 + v;
            if (first) { skip[si] = a0; skip[si + 1] = a1; }
            else       { skip[si] += a0; skip[si + 1] += a1; }
        }
    }
#pragma unroll
    for (int co = 0; co < 16; co++) {
        unsigned long long p = 0ull, q = 0ull, e = 0ull;
#pragma unroll
        for (int ci = 0; ci < 16; ci++) {
            int wi = co * 16 + ci;
            FMA2(p, Pwp[wi], xgp[ci], p);
            FMA2(q, Qwp[wi], xgp[ci], q);
            FMA2(e, Ewp[wi], xgp[ci], e);
        }
        float p0, p1, q0, q1, e0, e1;
        unpack2(p, p0, p1);
        unpack2(q, q0, q1);
        unpack2(e, e0, e1);
        int row = (b * 16 + co) * Lp + l;
        __nv_bfloat162 h2, l2;
        split2(p0, p1, h2, l2);
        *reinterpret_cast<__nv_bfloat162*>(PQh + row * 1024 + v) = h2;
        *reinterpret_cast<__nv_bfloat162*>(PQl + row * 1024 + v) = l2;
        split2(q0, q1, h2, l2);
        *reinterpret_cast<__nv_bfloat162*>(PQh + row * 1024 + 512 + v) = h2;
        *reinterpret_cast<__nv_bfloat162*>(PQl + row * 1024 + 512 + v) = l2;
        *reinterpret_cast<float2*>(idt + row * 512 + v) = make_float2(e0, e1);
    }
}

// ---------------- main MMA GEMM (big layers): 64(M)x128(N) tiles, 3-stage ----------------
// Asymmetric precision: K<512 (adj half, |p@A| << |q@A^2|) hi-term only;
// K>=512 (adj^2 half) full 3-term bf16 split.
#define MMA_SMEM_BYTES 92160

__global__ void __launch_bounds__(256) k_mma(
    const __nv_bfloat16* __restrict__ Ah, const __nv_bfloat16* __restrict__ Al,
    const __nv_bfloat16* __restrict__ Bh, const __nv_bfloat16* __restrict__ Bl,
    const float* __restrict__ idt, const float* __restrict__ xprev, float* __restrict__ xnew,
    const float* __restrict__ gcb, const float* __restrict__ bng, const float* __restrict__ bnb,
    const float* __restrict__ bnm, const float* __restrict__ bnv,
    int Lp, int dil, int Lprev)
{
    extern __shared__ __align__(16) char smem_raw[];
    __shared__ float s_scale[16], s_shift[16], s_gb[16];
    uint32_t sbase = (uint32_t)__cvta_generic_to_shared(smem_raw);

    int t = threadIdx.x;
    if (t < 16) {
        float sc = bng[t] * rsqrtf(bnv[t] + 1e-5f);
        s_scale[t] = sc;
        s_shift[t] = bnb[t] - bnm[t] * sc;
        s_gb[t] = gcb[t];
    }

    int row0 = blockIdx.y * 64, col0 = blockIdx.x * 128;
    int warp = t >> 5, lane = t & 31;
    int wm = warp >> 2, wn = warp & 3;

    float acc[2][4][4];
#pragma unroll
    for (int i = 0; i < 2; i++)
#pragma unroll
        for (int j = 0; j < 4; j++)
#pragma unroll
            for (int r = 0; r < 4; r++) acc[i][j][r] = 0.f;

    int rA = t >> 2, kA = (t & 3) * 8;
    int rB0 = t >> 2, kB0 = (t & 3) * 8;
    int rB1 = 64 + (t >> 2), kB1 = (t & 3) * 8;

#define LOAD_STAGE(S, K0)                                                          \
    do {                                                                           \
        uint32_t sb_ = sbase + (uint32_t)(S) * 30720u;                             \
        const __nv_bfloat16* ga  = Ah + (size_t)(row0 + rA) * 1024 + (K0) + kA;    \
        const __nv_bfloat16* gb0 = Bh + (size_t)(col0 + rB0) * 1024 + (K0) + kB0;  \
        const __nv_bfloat16* gb1 = Bh + (size_t)(col0 + rB1) * 1024 + (K0) + kB1;  \
        uint32_t sa  = sb_ + (uint32_t)(rA * 40 + kA) * 2;                         \
        uint32_t sb0 = sb_ + 10240u + (uint32_t)(rB0 * 40 + kB0) * 2;              \
        uint32_t sb1 = sb_ + 10240u + (uint32_t)(rB1 * 40 + kB1) * 2;              \
        cpasync16(sa,  ga);                                                        \
        cpasync16(sb0, gb0);                                                       \
        cpasync16(sb1, gb1);                                                       \
        if ((K0) >= 512) {                                                         \
            cpasync16(sa + 5120u,   Al + (ga - Ah));                               \
            cpasync16(sb0 + 10240u, Bl + (gb0 - Bh));                              \
            cpasync16(sb1 + 10240u, Bl + (gb1 - Bh));                              \
        }                                                                          \
    } while (0)

    LOAD_STAGE(0, 0);
    CP_COMMIT();
    LOAD_STAGE(1, 32);
    CP_COMMIT();

    int ar = lane & 15, ah8 = (lane >> 4) << 3;
    int bq = lane >> 3, br = lane & 7;
    int bro = ((bq >> 1) << 3) + br, bco = (bq & 1) << 3;

    for (int it = 0; it < 32; it++) {
        CP_WAIT1();
        __syncthreads();
        int p = it % 3;
        uint32_t aH = sbase + (uint32_t)p * 30720u;
        uint32_t aL = aH + 5120u;
        uint32_t bH = aH + 10240u;
        uint32_t bL = aH + 20480u;
#pragma unroll
        for (int kc = 0; kc < 2; kc++) {
            uint32_t a_h[2][4], b_h[4][2];
#pragma unroll
            for (int mf = 0; mf < 2; mf++) {
                uint32_t off = (uint32_t)((wm * 32 + mf * 16 + ar) * 40 + kc * 16 + ah8) * 2;
                LDSM4(a_h[mf], aH + off);
            }
#pragma unroll
            for (int nb = 0; nb < 2; nb++) {
                uint32_t off = (uint32_t)((wn * 32 + nb * 16 + bro) * 40 + kc * 16 + bco) * 2;
                uint32_t rh[4];
                LDSM4(rh, bH + off);
                b_h[2 * nb][0] = rh[0]; b_h[2 * nb][1] = rh[1];
                b_h[2 * nb + 1][0] = rh[2]; b_h[2 * nb + 1][1] = rh[3];
            }
#pragma unroll
            for (int mf = 0; mf < 2; mf++)
#pragma unroll
                for (int nf = 0; nf < 4; nf++)
                    MMA16816(acc[mf][nf], a_h[mf], b_h[nf][0], b_h[nf][1]);
            if (it >= 16) {   // adj^2 half: add bf16 correction terms
                uint32_t a_l[2][4], b_l[4][2];
#pragma unroll
                for (int mf = 0; mf < 2; mf++) {
                    uint32_t off = (uint32_t)((wm * 32 + mf * 16 + ar) * 40 + kc * 16 + ah8) * 2;
                    LDSM4(a_l[mf], aL + off);
                }
#pragma unroll
                for (int nb = 0; nb < 2; nb++) {
                    uint32_t off = (uint32_t)((wn * 32 + nb * 16 + bro) * 40 + kc * 16 + bco) * 2;
                    uint32_t rl[4];
                    LDSM4(rl, bL + off);
                    b_l[2 * nb][0] = rl[0]; b_l[2 * nb][1] = rl[1];
                    b_l[2 * nb + 1][0] = rl[2]; b_l[2 * nb + 1][1] = rl[3];
                }
#pragma unroll
                for (int mf = 0; mf < 2; mf++)
#pragma unroll
                    for (int nf = 0; nf < 4; nf++) {
                        MMA16816(acc[mf][nf], a_h[mf], b_l[nf][0], b_l[nf][1]);
                        MMA16816(acc[mf][nf], a_l[mf], b_h[nf][0], b_h[nf][1]);
                    }
            }
        }
        if (it < 30) LOAD_STAGE((it + 2) % 3, (it + 2) * 32);
        CP_COMMIT();
    }

    int g = lane >> 2, tig = lane & 3;
#pragma unroll
    for (int mf = 0; mf < 2; mf++) {
#pragma unroll
        for (int h = 0; h < 2; h++) {
            int m = row0 + wm * 32 + mf * 16 + g + h * 8;
            int l = m % Lp;
            int bc = m / Lp;
            int co = bc & 15;
            float scale = s_scale[co], shift = s_shift[co], gb = s_gb[co];
            const float* idp  = idt + (size_t)m * 512;
            const float* resp = xprev + (size_t)(bc * Lprev + l + dil) * 512;
            float* op = xnew + (size_t)m * 512;
#pragma unroll
            for (int nf = 0; nf < 4; nf++) {
                int n = col0 + wn * 32 + nf * 8 + tig * 2;
                float v0 = acc[mf][nf][2 * h]     + idp[n]     + gb + resp[n];
                float v1 = acc[mf][nf][2 * h + 1] + idp[n + 1] + gb + resp[n + 1];
                op[n]     = v0 * scale + shift;
                op[n + 1] = v1 * scale + shift;
            }
        }
    }
}

// ---------------- tail MMA GEMM (small layers, Lp<=4): 32(M)x128(N) tiles, 3-stage ----------------
#define MMA32_SMEM_BYTES 76800

__global__ void __launch_bounds__(256) k_mma32(
    const __nv_bfloat16* __restrict__ Ah, const __nv_bfloat16* __restrict__ Al,
    const __nv_bfloat16* __restrict__ Bh, const __nv_bfloat16* __restrict__ Bl,
    const float* __restrict__ idt, const float* __restrict__ xprev, float* __restrict__ xnew,
    const float* __restrict__ gcb, const float* __restrict__ bng, const float* __restrict__ bnb,
    const float* __restrict__ bnm, const float* __restrict__ bnv,
    int Lp, int dil, int Lprev)
{
    extern __shared__ __align__(16) char smem_raw[];
    __shared__ float s_scale[16], s_shift[16], s_gb[16];
    uint32_t sbase = (uint32_t)__cvta_generic_to_shared(smem_raw);

    int t = threadIdx.x;
    if (t < 16) {
        float sc = bng[t] * rsqrtf(bnv[t] + 1e-5f);
        s_scale[t] = sc;
        s_shift[t] = bnb[t] - bnm[t] * sc;
        s_gb[t] = gcb[t];
    }

    int row0 = blockIdx.y * 32, col0 = blockIdx.x * 128;
    int warp = t >> 5, lane = t & 31;
    int wn = warp;

    float acc[2][2][4];
#pragma unroll
    for (int i = 0; i < 2; i++)
#pragma unroll
        for (int j = 0; j < 2; j++)
#pragma unroll
            for (int r = 0; r < 4; r++) acc[i][j][r] = 0.f;

    int tA = t & 127;
    int rA = tA >> 2, kA = (tA & 3) * 8;
    uint32_t aSel = (t < 128) ? 0u : 2560u;
    int rB0 = t >> 2, kB0 = (t & 3) * 8;
    int rB1 = 64 + (t >> 2), kB1 = (t & 3) * 8;

#define LOAD_STAGE32(S, K0)                                                        \
    do {                                                                           \
        uint32_t sb_ = sbase + (uint32_t)(S) * 25600u;                             \
        const __nv_bfloat16* gsrcA = (t < 128) ? Ah : Al;                          \
        if (t < 128 || (K0) >= 512)                                                \
            cpasync16(sb_ + aSel + (uint32_t)(rA * 40 + kA) * 2,                   \
                      gsrcA + (size_t)(row0 + rA) * 1024 + (K0) + kA);             \
        const __nv_bfloat16* gb0 = Bh + (size_t)(col0 + rB0) * 1024 + (K0) + kB0;  \
        const __nv_bfloat16* gb1 = Bh + (size_t)(col0 + rB1) * 1024 + (K0) + kB1;  \
        uint32_t sb0 = sb_ + 5120u + (uint32_t)(rB0 * 40 + kB0) * 2;               \
        uint32_t sb1 = sb_ + 5120u + (uint32_t)(rB1 * 40 + kB1) * 2;               \
        cpasync16(sb0, gb0);                                                       \
        cpasync16(sb1, gb1);                                                       \
        if ((K0) >= 512) {                                                         \
            cpasync16(sb0 + 10240u, Bl + (gb0 - Bh));                              \
            cpasync16(sb1 + 10240u, Bl + (gb1 - Bh));                              \
        }                                                                          \
    } while (0)

    LOAD_STAGE32(0, 0);
    CP_COMMIT();
    LOAD_STAGE32(1, 32);
    CP_COMMIT();

    int ar = lane & 15, ah8 = (lane >> 4) << 3;
    int bq = lane >> 3, br = lane & 7;
    int bro = ((bq >> 1) << 3) + br, bco = (bq & 1) << 3;

    for (int it = 0; it < 32; it++) {
        CP_WAIT1();
        __syncthreads();
        int p = it % 3;
        uint32_t aH = sbase + (uint32_t)p * 25600u;
        uint32_t aL = aH + 2560u;
        uint32_t bH = aH + 5120u;
        uint32_t bL = aH + 15360u;
#pragma unroll
        for (int kc = 0; kc < 2; kc++) {
            uint32_t a_h[2][4], b_h[2][2];
#pragma unroll
            for (int mf = 0; mf < 2; mf++) {
                uint32_t off = (uint32_t)((mf * 16 + ar) * 40 + kc * 16 + ah8) * 2;
                LDSM4(a_h[mf], aH + off);
            }
            {
                uint32_t off = (uint32_t)((wn * 16 + bro) * 40 + kc * 16 + bco) * 2;
                uint32_t rh[4];
                LDSM4(rh, bH + off);
                b_h[0][0] = rh[0]; b_h[0][1] = rh[1];
                b_h[1][0] = rh[2]; b_h[1][1] = rh[3];
            }
#pragma unroll
            for (int mf = 0; mf < 2; mf++)
#pragma unroll
                for (int nf = 0; nf < 2; nf++)
                    MMA16816(acc[mf][nf], a_h[mf], b_h[nf][0], b_h[nf][1]);
            if (it >= 16) {
                uint32_t a_l[2][4], b_l[2][2];
#pragma unroll
                for (int mf = 0; mf < 2; mf++) {
                    uint32_t off = (uint32_t)((mf * 16 + ar) * 40 + kc * 16 + ah8) * 2;
                    LDSM4(a_l[mf], aL + off);
                }
                {
                    uint32_t off = (uint32_t)((wn * 16 + bro) * 40 + kc * 16 + bco) * 2;
                    uint32_t rl[4];
                    LDSM4(rl, bL + off);
                    b_l[0][0] = rl[0]; b_l[0][1] = rl[1];
                    b_l[1][0] = rl[2]; b_l[1][1] = rl[3];
                }
#pragma unroll
                for (int mf = 0; mf < 2; mf++)
#pragma unroll
                    for (int nf = 0; nf < 2; nf++) {
                        MMA16816(acc[mf][nf], a_h[mf], b_l[nf][0], b_l[nf][1]);
                        MMA16816(acc[mf][nf], a_l[mf], b_h[nf][0], b_h[nf][1]);
                    }
            }
        }
        if (it < 30) LOAD_STAGE32((it + 2) % 3, (it + 2) * 32);
        CP_COMMIT();
    }

    int g = lane >> 2, tig = lane & 3;
#pragma unroll
    for (int mf = 0; mf < 2; mf++) {
#pragma unroll
        for (int h = 0; h < 2; h++) {
            int m = row0 + mf * 16 + g + h * 8;
            int l = m % Lp;
            int bc = m / Lp;
            int co = bc & 15;
            float scale = s_scale[co], shift = s_shift[co], gb = s_gb[co];
            const float* idp  = idt + (size_t)m * 512;
            const float* resp = xprev + (size_t)(bc * Lprev + l + dil) * 512;
            float* op = xnew + (size_t)m * 512;
#pragma unroll
            for (int nf = 0; nf < 2; nf++) {
                int n = col0 + wn * 16 + nf * 8 + tig * 2;
                float v0 = acc[mf][nf][2 * h]     + idp[n]     + gb + resp[n];
                float v1 = acc[mf][nf][2 * h + 1] + idp[n + 1] + gb + resp[n + 1];
                op[n]     = v0 * scale + shift;
                op[n + 1] = v1 * scale + shift;
            }
        }
    }
}

// ---------------- K9: end convs ----------------
__global__ void k_end(const float* __restrict__ skip,
                      const float* __restrict__ w1, const float* __restrict__ b1,
                      const float* __restrict__ w2, const float* __restrict__ b2,
                      float* __restrict__ out)
{
    int tid = blockIdx.x * 128 + threadIdx.x;
    int b = tid >> 9, v = tid & 511;
    float s[16];
#pragma unroll
    for (int c = 0; c < 16; c++) s[c] = fmaxf(skip[(b * 16 + c) * 512 + v], 0.f);
    float e1[16];
#pragma unroll
    for (int c = 0; c < 16; c++) {
        float a = b1[c];
#pragma unroll
        for (int ci = 0; ci < 16; ci++) a += w1[c * 16 + ci] * s[ci];
        e1[c] = fmaxf(a, 0.f);
    }
#pragma unroll
    for (int h = 0; h < 12; h++) {
        float a = b2[h];
#pragma unroll
        for (int c = 0; c < 16; c++) a += w2[h * 16 + c] * e1[c];
        out[(b * 12 + h) * 512 + v] = a;
    }
}

// ======================== host orchestration ========================
extern "C" void kernel_launch(void* const* d_in, const int* in_sizes, int n_in,
                              void* d_out, int out_size)
{
    const float* input  = (const float*)d_in[0];
    const float* startW = (const float*)d_in[1];
    const float* startb = (const float*)d_in[2];
    const float* filtW  = (const float*)d_in[3];
    const float* filtb  = (const float*)d_in[4];
    const float* gateW  = (const float*)d_in[5];
    const float* gateb  = (const float*)d_in[6];
    const float* skipW  = (const float*)d_in[7];
    const float* skipb  = (const float*)d_in[8];
    const float* gconvW = (const float*)d_in[9];
    const float* gconvb = (const float*)d_in[10];
    const float* bng    = (const float*)d_in[11];
    const float* bnb    = (const float*)d_in[12];
    const float* bnm    = (const float*)d_in[13];
    const float* bnv    = (const float*)d_in[14];
    const float* e1W    = (const float*)d_in[15];
    const float* e1b    = (const float*)d_in[16];
    const float* e2W    = (const float*)d_in[17];
    const float* e2b    = (const float*)d_in[18];
    const float* linW   = (const float*)d_in[19];
    const float* linb   = (const float*)d_in[20];
    const float* f1W    = (const float*)d_in[21];
    const float* f1b    = (const float*)d_in[22];
    const float* f2W    = (const float*)d_in[23];
    const float* f2b    = (const float*)d_in[24];
    const float* f3W    = (const float*)d_in[25];
    const float* f3b    = (const float*)d_in[26];
    float* out = (float*)d_out;

    float *p_real, *p_img, *p_iffp, *p_AA2, *p_bs;
    float *p_xa, *p_xb, *p_idt, *p_skip;
    __nv_bfloat16 *p_Fh, *p_Fl, *p_Wh, *p_Wl, *p_Bth, *p_Btl, *p_PQh, *p_PQl;
    cudaGetSymbolAddress((void**)&p_real, g_real);
    cudaGetSymbolAddress((void**)&p_img,  g_img);
    cudaGetSymbolAddress((void**)&p_iffp, g_iffp);
    cudaGetSymbolAddress((void**)&p_AA2,  g_AA2);
    cudaGetSymbolAddress((void**)&p_Fh,   g_Fh);
    cudaGetSymbolAddress((void**)&p_Fl,   g_Fl);
    cudaGetSymbolAddress((void**)&p_Wh,   g_Wh);
    cudaGetSymbolAddress((void**)&p_Wl,   g_Wl);
    cudaGetSymbolAddress((void**)&p_bs,   g_bs);
    cudaGetSymbolAddress((void**)&p_Bth,  g_Bth);
    cudaGetSymbolAddress((void**)&p_Btl,  g_Btl);
    cudaGetSymbolAddress((void**)&p_xa,   g_xa);
    cudaGetSymbolAddress((void**)&p_xb,   g_xb);
    cudaGetSymbolAddress((void**)&p_PQh,  g_PQh);
    cudaGetSymbolAddress((void**)&p_PQl,  g_PQl);
    cudaGetSymbolAddress((void**)&p_idt,  g_idt);
    cudaGetSymbolAddress((void**)&p_skip, g_skip);

    static int smem_set = 0;
    if (!smem_set) {
        cudaFuncSetAttribute(k_mma, cudaFuncAttributeMaxDynamicSharedMemorySize, MMA_SMEM_BYTES);
        cudaFuncSetAttribute(k_mma32, cudaFuncAttributeMaxDynamicSharedMemorySize, MMA32_SMEM_BYTES);
        cudaFuncSetAttribute(k_adjmma, cudaFuncAttributeMaxDynamicSharedMemorySize, ADJ_SMEM);
        smem_set = 1;
    }

    // ---- graph learner ----
    k_dft<<<256, 64>>>(input, linW, linb, p_real, p_img, p_Fh, p_Fl);
    k_iff_part<<<dim3(32, 16), 512>>>(p_real, p_img, p_iffp);
    k_iff_red<<<1280, 256>>>(p_iffp, p_Fh, p_Fl);
    k_wprep<<<64, 256>>>(f1W, f1b, f2W, f2b, f3W, f3b, p_Wh, p_Wl, p_bs);
    float* adj_out = (out_size >= Bz * HORz * Vz + Vz * Vz) ? out + Bz * HORz * Vz : nullptr;
    k_adjmma<<<dim3(4, 128), 256, ADJ_SMEM>>>(p_Fh, p_Fl, p_Wh, p_Wl, p_bs, p_AA2, adj_out);
    k_gemm_plain<<<dim3(8, 8), 256>>>(p_AA2, p_AA2, p_AA2 + Vz * Vz, 512);
    k_prepB<<<dim3(16, 32), dim3(32, 8)>>>(p_AA2, p_Bth, p_Btl);

    // ---- trunk ----
    k_start<<<13312, 256>>>(input, startW, startb, p_xa);

    float* xc = p_xa;
    float* xn = p_xb;
    int L = RFz;
    const int dils[NLz] = {1, 2, 1, 2, 1, 2, 1, 2};
    for (int i = 0; i < NLz; i++) {
        int d = dils[i];
        int Lp = L - d;
        k_fused<<<Bz * Lp, 256>>>(xc, filtW + i * 512, filtb + i * 16,
                                  gateW + i * 512, gateb + i * 16,
                                  gconvW + i * 1024, skipW + i * 256, skipb + i * 16,
                                  p_PQh, p_PQl, p_idt, p_skip, L, d, (i == 0) ? 1 : 0);
        int M = Bz * CHz * Lp;
        if (Lp > 4) {
            k_mma<<<dim3(4, M / 64), 256, MMA_SMEM_BYTES>>>(p_PQh, p_PQl, p_Bth, p_Btl,
                                                            p_idt, xc, xn,
                                                            gconvb + i * 16, bng + i * 16, bnb + i * 16,
                                                            bnm + i * 16, bnv + i * 16, Lp, d, L);
        } else {
            k_mma32<<<dim3(4, M / 32), 256, MMA32_SMEM_BYTES>>>(p_PQh, p_PQl, p_Bth, p_Btl,
                                                                p_idt, xc, xn,
                                                                gconvb + i * 16, bng + i * 16, bnb + i * 16,
                                                                bnm + i * 16, bnv + i * 16, Lp, d, L);
        }
        float* tmp = xc; xc = xn; xn = tmp;
        L = Lp;
    }

    k_end<<<128, 128>>>(p_skip, e1W, e1b, e2W, e2b, out);
}

// round 17
// speedup vs baseline: 1.2425x; 1.0039x over previous
#include <cuda_runtime.h>
#include <cuda_bf16.h>
#include <math.h>
#include <stdint.h>

#define Bz   32
#define Vz   512
#define Tz   12
#define DGz  20
#define CHz  16
#define HORz 12
#define RFz  13
#define NLz  8
#define EPSz 0.3f

// ---------------- scratch ----------------
__device__ float g_real[Bz*Vz*DGz];
__device__ float g_img [Bz*Vz*DGz];
__device__ float g_iffp[16*Bz*Vz*DGz];
__device__ float g_AA2 [2*Vz*Vz];
__device__ __align__(16) __nv_bfloat16 g_Fh[Bz*Vz*64];
__device__ __align__(16) __nv_bfloat16 g_Fl[Bz*Vz*64];
__device__ __align__(16) __nv_bfloat16 g_Wh[Vz*64];
__device__ __align__(16) __nv_bfloat16 g_Wl[Vz*64];
__device__ float g_bs[Vz];
__device__ __align__(16) __nv_bfloat16 g_Bth[Vz*1024];   // centered Bt hi: R[n][k]
__device__ float g_xa  [Bz*CHz*RFz*Vz];
__device__ float g_xb  [Bz*CHz*RFz*Vz];
__device__ __align__(16) __nv_bfloat16 g_PQh[Bz*CHz*Tz*1024];
__device__ __align__(16) __nv_bfloat16 g_PQl[Bz*CHz*Tz*1024];
__device__ float g_idt [Bz*CHz*Tz*Vz];
__device__ float g_skip[Bz*CHz*Vz];
__device__ float g_rsp [Bz*CHz*Tz];     // row sums of p
__device__ float g_rsq [Bz*CHz*Tz];     // row sums of q
__device__ float g_partA[512];
__device__ float g_partB[64];
__device__ float g_mu[2];

// ---------------- PTX helpers ----------------
__device__ __forceinline__ void cpasync16(uint32_t s, const void* g) {
    asm volatile("cp.async.cg.shared.global [%0], [%1], 16;\n" :: "r"(s), "l"(g));
}
#define CP_COMMIT() asm volatile("cp.async.commit_group;\n" ::)
#define CP_WAIT0()  asm volatile("cp.async.wait_group 0;\n" ::)
#define CP_WAIT1()  asm volatile("cp.async.wait_group 1;\n" ::)

#define LDSM4(R, addr) \
    asm volatile("ldmatrix.sync.aligned.m8n8.x4.shared.b16 {%0,%1,%2,%3}, [%4];" \
        : "=r"((R)[0]), "=r"((R)[1]), "=r"((R)[2]), "=r"((R)[3]) : "r"(addr))

#define MMA16816(C, A, B0, B1) \
    asm volatile("mma.sync.aligned.m16n8k16.row.col.f32.bf16.bf16.f32 " \
        "{%0,%1,%2,%3},{%4,%5,%6,%7},{%8,%9},{%0,%1,%2,%3};" \
        : "+f"((C)[0]), "+f"((C)[1]), "+f"((C)[2]), "+f"((C)[3]) \
        : "r"((A)[0]), "r"((A)[1]), "r"((A)[2]), "r"((A)[3]), "r"(B0), "r"(B1))

// packed f32x2 fma: d = a*b + c (per 32-bit lane)
#define FMA2(D, A, B, C) \
    asm("fma.rn.f32x2 %0, %1, %2, %3;" : "=l"(D) : "l"(A), "l"(B), "l"(C))

__device__ __forceinline__ unsigned long long pack2(float a, float b) {
    unsigned long long r;
    asm("mov.b64 %0, {%1, %2};" : "=l"(r) : "f"(a), "f"(b));
    return r;
}
__device__ __forceinline__ void unpack2(unsigned long long p, float& a, float& b) {
    asm("mov.b64 {%0, %1}, %2;" : "=f"(a), "=f"(b) : "l"(p));
}

__device__ __forceinline__ void split2(float a, float b,
                                       __nv_bfloat162& hi, __nv_bfloat162& lo) {
    __nv_bfloat16 ha = __float2bfloat16(a), hb = __float2bfloat16(b);
    hi = __halves2bfloat162(ha, hb);
    lo = __floats2bfloat162_rn(a - __bfloat162float(ha), b - __bfloat162float(hb));
}

// ---------------- K0: DFT(24) + lin projection (f32x2 packed) ----------------
__global__ void __launch_bounds__(64) k_dft(
    const float* __restrict__ input, const float* __restrict__ lW,
    const float* __restrict__ lb, float* __restrict__ re, float* __restrict__ im,
    __nv_bfloat16* __restrict__ Fh, __nv_bfloat16* __restrict__ Fl)
{
    __shared__ unsigned long long cst[24];   // (cos, -sin) packed
    if (threadIdx.x < 24) {
        float c = cospif(threadIdx.x / 12.f);
        float s = sinpif(threadIdx.x / 12.f);
        cst[threadIdx.x] = pack2(c, -s);
    }
    __syncthreads();
    int tid = blockIdx.x * 64 + threadIdx.x;
    int b = tid >> 9, v = tid & 511;
    unsigned long long xrp[24];
#pragma unroll
    for (int t = 0; t < 12; t++) {
        int base = ((t * 32 + b) * 512 + v) * 2;
        float a0 = input[base], a1 = input[base + 1];
        xrp[2 * t]     = pack2(a0, a0);
        xrp[2 * t + 1] = pack2(a1, a1);
    }
    unsigned long long fri[24];   // (fr, fi) packed per harmonic
#pragma unroll
    for (int n = 0; n < 24; n++) {
        unsigned long long s = 0ull;
        int idx = 0;
#pragma unroll
        for (int k = 0; k < 24; k++) {
            FMA2(s, xrp[k], cst[idx], s);
            idx += n; if (idx >= 24) idx -= 24;
        }
        fri[n] = s;
    }
    int go = (b * 512 + v) * 20;
    int frow = (v * 32 + b) * 64;
#pragma unroll
    for (int d = 0; d < 20; d += 2) {
        unsigned long long rq0 = pack2(lb[d], lb[d]);
        unsigned long long rq1 = pack2(lb[d + 1], lb[d + 1]);
#pragma unroll
        for (int n = 0; n < 24; n++) {
            float w0 = lW[d * 24 + n], w1 = lW[(d + 1) * 24 + n];
            FMA2(rq0, pack2(w0, w0), fri[n], rq0);
            FMA2(rq1, pack2(w1, w1), fri[n], rq1);
        }
        float r0, q0, r1, q1;
        unpack2(rq0, r0, q0);
        unpack2(rq1, r1, q1);
        re[go + d] = r0; re[go + d + 1] = r1;
        im[go + d] = q0; im[go + d + 1] = q1;
        float am0 = sqrtf(r0 * r0 + q0 * q0), am1 = sqrtf(r1 * r1 + q1 * q1);
        float ss0 = atanf(r0 / (q0 + 1e-4f)), ss1 = atanf(r1 / (q1 + 1e-4f));
        __nv_bfloat162 h2, l2;
        split2(am0, am1, h2, l2);
        *reinterpret_cast<__nv_bfloat162*>(Fh + frow + 20 + d) = h2;
        *reinterpret_cast<__nv_bfloat162*>(Fl + frow + 20 + d) = l2;
        split2(ss0, ss1, h2, l2);
        *reinterpret_cast<__nv_bfloat162*>(Fh + frow + 40 + d) = h2;
        *reinterpret_cast<__nv_bfloat162*>(Fl + frow + 40 + d) = l2;
    }
    *reinterpret_cast<uint32_t*>(Fh + frow + 60) = 0u;
    *reinterpret_cast<uint32_t*>(Fh + frow + 62) = 0u;
    *reinterpret_cast<uint32_t*>(Fl + frow + 60) = 0u;
    *reinterpret_cast<uint32_t*>(Fl + frow + 62) = 0u;
}

// ---------------- K1a: irfft partials (f32x2 packed over d-pairs) ----------------
__global__ void __launch_bounds__(512) k_iff_part(
    const float* __restrict__ re, const float* __restrict__ im, float* __restrict__ iffp)
{
    __shared__ float ct[512], st[512];
    int m = threadIdx.x;
    ct[m] = cospif(m / 256.f);
    st[m] = sinpif(m / 256.f);
    __syncthreads();
    int b = blockIdx.x, c = blockIdx.y;
    const float* R = re + b * 512 * 20;
    const float* I = im + b * 512 * 20;
    unsigned long long acc[10];
    if (c == 0) {
        float sg = (m & 1) ? -1.f : 1.f;
        unsigned long long sgp = pack2(sg, sg);
#pragma unroll
        for (int d = 0; d < 10; d++) {
            unsigned long long r0 = *reinterpret_cast<const unsigned long long*>(R + 2 * d);
            unsigned long long rN = *reinterpret_cast<const unsigned long long*>(R + 256 * 20 + 2 * d);
            FMA2(acc[d], sgp, rN, r0);
        }
    } else {
#pragma unroll
        for (int d = 0; d < 10; d++) acc[d] = 0ull;
    }
    int k0 = (c == 0) ? 1 : c * 16;
    int k1 = c * 16 + 16;
    int idx = (k0 * m) & 511;
    for (int k = k0; k < k1; k++) {
        float cc = 2.f * ct[idx], ss = -2.f * st[idx];
        unsigned long long ccp = pack2(cc, cc), ssp = pack2(ss, ss);
        const unsigned long long* Rp = reinterpret_cast<const unsigned long long*>(R + k * 20);
        const unsigned long long* Ip = reinterpret_cast<const unsigned long long*>(I + k * 20);
#pragma unroll
        for (int d = 0; d < 10; d++) {
            FMA2(acc[d], ccp, Rp[d], acc[d]);
            FMA2(acc[d], ssp, Ip[d], acc[d]);
        }
        idx = (idx + m) & 511;
    }
    int go = ((c * 32 + b) * 512 + m) * 20;
    unsigned long long* op = reinterpret_cast<unsigned long long*>(iffp + go);
#pragma unroll
    for (int d = 0; d < 10; d++) op[d] = acc[d];
}

// ---------------- K1b: reduce -> feat cols 0..19 ----------------
__global__ void k_iff_red(const float* __restrict__ iffp,
                          __nv_bfloat16* __restrict__ Fh, __nv_bfloat16* __restrict__ Fl)
{
    int i = blockIdx.x * 256 + threadIdx.x;
    const int Sz = Bz * Vz * DGz;
    int d = i % 20;
    int r = i / 20;
    int v = r & 511, b = r >> 9;
    float s = 0.f;
#pragma unroll
    for (int c = 0; c < 16; c++) s += iffp[c * Sz + i];
    s *= (1.f / 512.f);
    __nv_bfloat16 h = __float2bfloat16(s);
    int o = (v * 32 + b) * 64 + d;
    Fh[o] = h;
    Fl[o] = __float2bfloat16(s - __bfloat162float(h));
}

// ---------------- Wprep (parallel: 16384 threads) ----------------
__global__ void k_wprep(const float* __restrict__ f1W, const float* __restrict__ f1b,
                        const float* __restrict__ f2W, const float* __restrict__ f2b,
                        const float* __restrict__ f3W, const float* __restrict__ f3b,
                        __nv_bfloat16* __restrict__ Wh, __nv_bfloat16* __restrict__ Wl,
                        float* __restrict__ bs)
{
    int t = blockIdx.x * 256 + threadIdx.x;   // 16384
    int w = t >> 5, d = t & 31;
    const float inv3 = 1.f / 3.f;
    if (d < 20) {
        float a = f1W[w * 20 + d] * inv3;
        __nv_bfloat16 h = __float2bfloat16(a);
        Wh[w * 64 + d] = h; Wl[w * 64 + d] = __float2bfloat16(a - __bfloat162float(h));
        a = f2W[w * 20 + d] * inv3;
        h = __float2bfloat16(a);
        Wh[w * 64 + 20 + d] = h; Wl[w * 64 + 20 + d] = __float2bfloat16(a - __bfloat162float(h));
        a = f3W[w * 20 + d] * inv3;
        h = __float2bfloat16(a);
        Wh[w * 64 + 40 + d] = h; Wl[w * 64 + 40 + d] = __float2bfloat16(a - __bfloat162float(h));
    } else if (d < 24) {
        Wh[w * 64 + 40 + d] = __float2bfloat16(0.f);
        Wl[w * 64 + 40 + d] = __float2bfloat16(0.f);
    } else if (d == 24) {
        bs[w] = (f1b[w] + f2b[w] + f3b[w]) * inv3;
    }
}

// ---------------- K2: adj via MMA + sigmoid + batch-reduce (+ block partial sum) ----------------
#define ADJ_SMEM 73728
__global__ void __launch_bounds__(256) k_adjmma(
    const __nv_bfloat16* __restrict__ Fh, const __nv_bfloat16* __restrict__ Fl,
    const __nv_bfloat16* __restrict__ Wh, const __nv_bfloat16* __restrict__ Wl,
    const float* __restrict__ bs, float* __restrict__ AA2, float* __restrict__ adj_out,
    float* __restrict__ partA)
{
    extern __shared__ __align__(16) char smem_raw[];
    __shared__ float sbs[128];
    __shared__ float ws2[8];
    uint32_t sbase = (uint32_t)__cvta_generic_to_shared(smem_raw);
    float* Stile = (float*)smem_raw;
    int t = threadIdx.x;
    int row0 = blockIdx.y * 128, col0 = blockIdx.x * 128;
    if (t < 128) sbs[t] = bs[col0 + t];
#pragma unroll
    for (int i = 0; i < 4; i++) {
        int c = t + i * 256;
        int row = c >> 3, col8 = (c & 7) * 8;
        uint32_t so = (uint32_t)(row * 72 + col8) * 2;
        const __nv_bfloat16* gA = Fh + (size_t)(row0 + row) * 64 + col8;
        const __nv_bfloat16* gB = Wh + (size_t)(col0 + row) * 64 + col8;
        cpasync16(sbase + so,           gA);
        cpasync16(sbase + 18432u + so,  Fl + (gA - Fh));
        cpasync16(sbase + 36864u + so,  gB);
        cpasync16(sbase + 55296u + so,  Wl + (gB - Wh));
    }
    CP_COMMIT();
    CP_WAIT0();
    __syncthreads();

    int warp = t >> 5, lane = t & 31;
    int wm = warp >> 2, wn = warp & 3;
    float acc[4][4][4];
#pragma unroll
    for (int i = 0; i < 4; i++)
#pragma unroll
        for (int j = 0; j < 4; j++)
#pragma unroll
            for (int r = 0; r < 4; r++) acc[i][j][r] = 0.f;

    int ar = lane & 15, ah8 = (lane >> 4) << 3;
    int bq = lane >> 3, br = lane & 7;
    int bro = ((bq >> 1) << 3) + br, bco = (bq & 1) << 3;
    uint32_t aH = sbase, aL = sbase + 18432u, bH = sbase + 36864u, bL = sbase + 55296u;
#pragma unroll
    for (int kc = 0; kc < 4; kc++) {
        uint32_t a_h[4][4], a_l[4][4], b_h[4][2], b_l[4][2];
#pragma unroll
        for (int mf = 0; mf < 4; mf++) {
            uint32_t off = (uint32_t)((wm * 64 + mf * 16 + ar) * 72 + kc * 16 + ah8) * 2;
            LDSM4(a_h[mf], aH + off);
            LDSM4(a_l[mf], aL + off);
        }
#pragma unroll
        for (int nb = 0; nb < 2; nb++) {
            uint32_t off = (uint32_t)((wn * 32 + nb * 16 + bro) * 72 + kc * 16 + bco) * 2;
            uint32_t rh[4], rl[4];
            LDSM4(rh, bH + off);
            LDSM4(rl, bL + off);
            b_h[2 * nb][0] = rh[0]; b_h[2 * nb][1] = rh[1];
            b_h[2 * nb + 1][0] = rh[2]; b_h[2 * nb + 1][1] = rh[3];
            b_l[2 * nb][0] = rl[0]; b_l[2 * nb][1] = rl[1];
            b_l[2 * nb + 1][0] = rl[2]; b_l[2 * nb + 1][1] = rl[3];
        }
#pragma unroll
        for (int mf = 0; mf < 4; mf++)
#pragma unroll
            for (int nf = 0; nf < 4; nf++) {
                MMA16816(acc[mf][nf], a_h[mf], b_h[nf][0], b_h[nf][1]);
                MMA16816(acc[mf][nf], a_h[mf], b_l[nf][0], b_l[nf][1]);
                MMA16816(acc[mf][nf], a_l[mf], b_h[nf][0], b_h[nf][1]);
            }
    }
    __syncthreads();

    int g = lane >> 2, tig = lane & 3;
#pragma unroll
    for (int mf = 0; mf < 4; mf++)
#pragma unroll
        for (int h = 0; h < 2; h++) {
            int r = wm * 64 + mf * 16 + g + h * 8;
#pragma unroll
            for (int nf = 0; nf < 4; nf++) {
                int cl = wn * 32 + nf * 8 + tig * 2;
                float l0 = acc[mf][nf][2 * h]     + sbs[cl];
                float l1 = acc[mf][nf][2 * h + 1] + sbs[cl + 1];
                Stile[r * 132 + cl]     = 1.f / (1.f + __expf(-l0));
                Stile[r * 132 + cl + 1] = 1.f / (1.f + __expf(-l1));
            }
        }
    __syncthreads();

    int v0 = row0 >> 5;
    float asum = 0.f;
#pragma unroll
    for (int o = t; o < 512; o += 256) {
        int vi = o >> 7, w = o & 127;
        float s = 0.f;
#pragma unroll
        for (int b2 = 0; b2 < 32; b2++) s += Stile[(vi * 32 + b2) * 132 + w];
        float a = 1.f / (1.f + __expf(-s * (1.f / 32.f)));
        int vv = v0 + vi, ww = col0 + w;
        AA2[vv * 512 + ww] = a;
        if (adj_out) adj_out[vv * 512 + ww] = a;
        asum += a;
    }
#pragma unroll
    for (int off = 16; off; off >>= 1)
        asum += __shfl_xor_sync(0xffffffffu, asum, off);
    if (lane == 0) ws2[warp] = asum;
    __syncthreads();
    if (t == 0) {
        float s = 0.f;
#pragma unroll
        for (int i = 0; i < 8; i++) s += ws2[i];
        partA[blockIdx.y * 4 + blockIdx.x] = s;
    }
}

// ---------------- SGEMM adj@adj (+ block partial sum) ----------------
__global__ void __launch_bounds__(256) k_gemm_plain(
    const float* __restrict__ Aq, const float* __restrict__ Bq, float* __restrict__ C, int K,
    float* __restrict__ partB)
{
    __shared__ float As[16][65];
    __shared__ float Bs[16][64];
    __shared__ float ws2[8];
    int t = threadIdx.x;
    int tx = t & 15, ty = t >> 4;
    int row0 = blockIdx.y * 64, col0 = blockIdx.x * 64;
    float acc[4][4] = {};
    int mA = t >> 2, kA = (t & 3) << 2;
    int kB = t >> 4, nB = (t & 15) << 2;
    const float* aptr = Aq + (row0 + mA) * K + kA;
    const float* bptr = Bq + kB * 512 + col0 + nB;
    for (int k0 = 0; k0 < K; k0 += 16) {
        float4 a4 = *reinterpret_cast<const float4*>(aptr + k0);
        float4 b4 = *reinterpret_cast<const float4*>(bptr + k0 * 512);
        As[kA + 0][mA] = a4.x; As[kA + 1][mA] = a4.y;
        As[kA + 2][mA] = a4.z; As[kA + 3][mA] = a4.w;
        *reinterpret_cast<float4*>(&Bs[kB][nB]) = b4;
        __syncthreads();
#pragma unroll
        for (int kk = 0; kk < 16; kk++) {
            float a0 = As[kk][ty * 4 + 0], a1 = As[kk][ty * 4 + 1];
            float a2 = As[kk][ty * 4 + 2], a3 = As[kk][ty * 4 + 3];
            float4 br = *reinterpret_cast<const float4*>(&Bs[kk][tx * 4]);
            acc[0][0] += a0 * br.x; acc[0][1] += a0 * br.y; acc[0][2] += a0 * br.z; acc[0][3] += a0 * br.w;
            acc[1][0] += a1 * br.x; acc[1][1] += a1 * br.y; acc[1][2] += a1 * br.z; acc[1][3] += a1 * br.w;
            acc[2][0] += a2 * br.x; acc[2][1] += a2 * br.y; acc[2][2] += a2 * br.z; acc[2][3] += a2 * br.w;
            acc[3][0] += a3 * br.x; acc[3][1] += a3 * br.y; acc[3][2] += a3 * br.z; acc[3][3] += a3 * br.w;
        }
        __syncthreads();
    }
    float asum = 0.f;
#pragma unroll
    for (int i = 0; i < 4; i++)
#pragma unroll
        for (int j = 0; j < 4; j++) {
            C[(row0 + ty * 4 + i) * 512 + col0 + tx * 4 + j] = acc[i][j];
            asum += acc[i][j];
        }
#pragma unroll
    for (int off = 16; off; off >>= 1)
        asum += __shfl_xor_sync(0xffffffffu, asum, off);
    if ((t & 31) == 0) ws2[t >> 5] = asum;
    __syncthreads();
    if (t == 0) {
        float s = 0.f;
#pragma unroll
        for (int i = 0; i < 8; i++) s += ws2[i];
        partB[blockIdx.y * 8 + blockIdx.x] = s;
    }
}

// ---------------- k_mean: reduce partials -> mu[0]=mean(adj), mu[1]=mean(A^2) ----------------
__global__ void __launch_bounds__(256) k_mean(const float* __restrict__ pa,
                                              const float* __restrict__ pb,
                                              float* __restrict__ mu)
{
    __shared__ float sm[256];
    int t = threadIdx.x;
    sm[t] = pa[t] + pa[t + 256];
    __syncthreads();
    for (int off = 128; off; off >>= 1) {
        if (t < off) sm[t] += sm[t + off];
        __syncthreads();
    }
    if (t == 0) mu[0] = sm[0] * (1.f / 262144.f);
    __syncthreads();
    sm[t] = (t < 64) ? pb[t] : 0.f;
    __syncthreads();
    for (int off = 128; off; off >>= 1) {
        if (t < off) sm[t] += sm[t + off];
        __syncthreads();
    }
    if (t == 0) mu[1] = sm[0] * (1.f / 262144.f);
}

// ---------------- prepB: transpose + CENTER AA2 -> Bt hi [512x1024] ----------------
__global__ void k_prepB(const float* __restrict__ AA2, const float* __restrict__ mu,
                        __nv_bfloat16* __restrict__ Bth)
{
    __shared__ float tile[32][33];
    int k0 = blockIdx.y * 32, n0 = blockIdx.x * 32;
    int tx = threadIdx.x, ty = threadIdx.y;
#pragma unroll
    for (int i = 0; i < 4; i++)
        tile[ty + i * 8][tx] = AA2[(k0 + ty + i * 8) * 512 + n0 + tx];
    __syncthreads();
    float mu_k = (k0 + tx < 512) ? mu[0] : mu[1];
#pragma unroll
    for (int i = 0; i < 4; i++) {
        int r = ty + i * 8;
        float v = tile[tx][r] - mu_k;
        int o = (n0 + r) * 1024 + k0 + tx;
        Bth[o] = __float2bfloat16(v);
    }
}

// ---------------- K4: pad + start 1x1 conv ----------------
__global__ void k_start(const float* __restrict__ input, const float* __restrict__ sW,
                        const float* __restrict__ sb, float* __restrict__ x0)
{
    int idx = blockIdx.x * 256 + threadIdx.x;
    int v = idx & 511;
    int r = idx >> 9;
    int l = r % 13; r /= 13;
    int c = r & 15; int b = r >> 4;
    float val = sb[c];
    if (l > 0) {
        int t = l - 1;
        const float* ip = input + ((t * 32 + b) * 512 + v) * 2;
        val += sW[c * 2] * ip[0] + sW[c * 2 + 1] * ip[1];
    }
    x0[idx] = val;
}

// ---------------- fused producer (f32x2 packed FMA + row sums) ----------------
__global__ void __launch_bounds__(256) k_fused(
    const float* __restrict__ x,
    const float* __restrict__ fW, const float* __restrict__ fb,
    const float* __restrict__ gW, const float* __restrict__ gb,
    const float* __restrict__ gcW,
    const float* __restrict__ sW, const float* __restrict__ sb,
    __nv_bfloat16* __restrict__ PQh, __nv_bfloat16* __restrict__ PQl,
    float* __restrict__ idt, float* __restrict__ skip,
    float* __restrict__ rsp, float* __restrict__ rsq,
    int L, int d, int first)
{
    __shared__ unsigned long long sfp[512], sgp[512];
    __shared__ unsigned long long Pwp[256], Qwp[256], Ewp[256];
    __shared__ float sWt[256], sfb[16], sgb[16], sbs2[16];
    __shared__ float wsp[16][8], wsq[16][8];
    int tid = threadIdx.x;
    for (int i = tid; i < 512; i += 256) {
        float w = fW[i]; sfp[i] = pack2(w, w);
        float u = gW[i]; sgp[i] = pack2(u, u);
    }
    {
        int i = tid;
        int co = i >> 4, ci = i & 15;
        float a0 = gcW[co * 64 + ci];
        float a1 = gcW[co * 64 + 16 + ci];
        float a2 = gcW[co * 64 + 32 + ci];
        float a3 = gcW[co * 64 + 48 + ci];
        float pw = a0 + 2.f * EPSz * a1 - a2 - 2.f * EPSz * a3;
        float qw = a1 + a3;
        float ew = EPSz * (a0 + a2) + EPSz * EPSz * (a1 + a3);
        Pwp[i] = pack2(pw, pw);
        Qwp[i] = pack2(qw, qw);
        Ewp[i] = pack2(ew, ew);
        sWt[i] = sW[i];
    }
    if (tid < 16) { sfb[tid] = fb[tid]; sgb[tid] = gb[tid]; sbs2[tid] = sb[tid]; }
    __syncthreads();
    int Lp = L - d;
    int b = blockIdx.x / Lp, l = blockIdx.x % Lp;
    int v = tid * 2;
    unsigned long long x0p[16], x1p[16];
#pragma unroll
    for (int ci = 0; ci < 16; ci++) {
        const float* xp = x + (size_t)((b * 16 + ci) * L + l) * 512 + v;
        x0p[ci] = *reinterpret_cast<const unsigned long long*>(xp);
        x1p[ci] = *reinterpret_cast<const unsigned long long*>(xp + d * 512);
    }
    unsigned long long xgp[16];
#pragma unroll
    for (int co = 0; co < 16; co++) {
        unsigned long long f = pack2(sfb[co], sfb[co]);
        unsigned long long g = pack2(sgb[co], sgb[co]);
#pragma unroll
        for (int ci = 0; ci < 16; ci++) {
            int wi = (co * 16 + ci) * 2;
            FMA2(f, sfp[wi],     x0p[ci], f);
            FMA2(f, sfp[wi + 1], x1p[ci], f);
            FMA2(g, sgp[wi],     x0p[ci], g);
            FMA2(g, sgp[wi + 1], x1p[ci], g);
        }
        float f0, f1, g0, g1;
        unpack2(f, f0, f1);
        unpack2(g, g0, g1);
        float xg0 = tanhf(f0) * (1.f / (1.f + __expf(-g0)));
        float xg1 = tanhf(f1) * (1.f / (1.f + __expf(-g1)));
        xgp[co] = pack2(xg0, xg1);
    }
    if (l == Lp - 1) {
#pragma unroll
        for (int co = 0; co < 16; co++) {
            unsigned long long a = pack2(sbs2[co], sbs2[co]);
#pragma unroll
            for (int ci = 0; ci < 16; ci++) {
                unsigned long long wv = pack2(sWt[co * 16 + ci], sWt[co * 16 + ci]);
                FMA2(a, wv, xgp[ci], a);
            }
            float a0, a1;
            unpack2(a, a0, a1);
            int si = (b * 16 + co) * 512 + v;
            if (first) { skip[si] = a0; skip[si + 1] = a1; }
            else       { skip[si] += a0; skip[si + 1] += a1; }
        }
    }
#pragma unroll
    for (int co = 0; co < 16; co++) {
        unsigned long long p = 0ull, q = 0ull, e = 0ull;
#pragma unroll
        for (int ci = 0; ci < 16; ci++) {
            int wi = co * 16 + ci;
            FMA2(p, Pwp[wi], xgp[ci], p);
            FMA2(q, Qwp[wi], xgp[ci], q);
            FMA2(e, Ewp[wi], xgp[ci], e);
        }
        float p0, p1, q0, q1, e0, e1;
        unpack2(p, p0, p1);
        unpack2(q, q0, q1);
        unpack2(e, e0, e1);
        // row sums (deterministic warp reduce)
        float ps = p0 + p1, qs = q0 + q1;
#pragma unroll
        for (int off = 16; off; off >>= 1) {
            ps += __shfl_xor_sync(0xffffffffu, ps, off);
            qs += __shfl_xor_sync(0xffffffffu, qs, off);
        }
        if ((tid & 31) == 0) { wsp[co][tid >> 5] = ps; wsq[co][tid >> 5] = qs; }
        int row = (b * 16 + co) * Lp + l;
        __nv_bfloat162 h2, l2;
        split2(p0, p1, h2, l2);
        *reinterpret_cast<__nv_bfloat162*>(PQh + row * 1024 + v) = h2;
        *reinterpret_cast<__nv_bfloat162*>(PQl + row * 1024 + v) = l2;
        split2(q0, q1, h2, l2);
        *reinterpret_cast<__nv_bfloat162*>(PQh + row * 1024 + 512 + v) = h2;
        *reinterpret_cast<__nv_bfloat162*>(PQl + row * 1024 + 512 + v) = l2;
        *reinterpret_cast<float2*>(idt + row * 512 + v) = make_float2(e0, e1);
    }
    __syncthreads();
    if (tid < 16) {
        float sp = 0.f, sq = 0.f;
#pragma unroll
        for (int w2 = 0; w2 < 8; w2++) { sp += wsp[tid][w2]; sq += wsq[tid][w2]; }
        int row = (b * 16 + tid) * Lp + l;
        rsp[row] = sp;
        rsq[row] = sq;
    }
}

// ---------------- main MMA GEMM (big layers): 64x128 tiles, centered B, 3-stage ----------------
// it<16 (adj R): 1 term (Ah*Rh). it>=16 (adj^2 R): 2 terms (Ah*Rh + Al*Rh).
// Stage: Ahi[64x80B]=5120 | Alo=5120 | Bhi[128x80B]=10240 => 20480B
#define MMA_SMEM_BYTES 61440

__global__ void __launch_bounds__(256) k_mma(
    const __nv_bfloat16* __restrict__ Ah, const __nv_bfloat16* __restrict__ Al,
    const __nv_bfloat16* __restrict__ Bh,
    const float* __restrict__ idt, const float* __restrict__ xprev, float* __restrict__ xnew,
    const float* __restrict__ rsp, const float* __restrict__ rsq, const float* __restrict__ mu,
    const float* __restrict__ gcb, const float* __restrict__ bng, const float* __restrict__ bnb,
    const float* __restrict__ bnm, const float* __restrict__ bnv,
    int Lp, int dil, int Lprev)
{
    extern __shared__ __align__(16) char smem_raw[];
    __shared__ float s_scale[16], s_shift[16], s_gb[16];
    uint32_t sbase = (uint32_t)__cvta_generic_to_shared(smem_raw);

    int t = threadIdx.x;
    if (t < 16) {
        float sc = bng[t] * rsqrtf(bnv[t] + 1e-5f);
        s_scale[t] = sc;
        s_shift[t] = bnb[t] - bnm[t] * sc;
        s_gb[t] = gcb[t];
    }

    int row0 = blockIdx.y * 64, col0 = blockIdx.x * 128;
    int warp = t >> 5, lane = t & 31;
    int wm = warp >> 2, wn = warp & 3;

    float acc[2][4][4];
#pragma unroll
    for (int i = 0; i < 2; i++)
#pragma unroll
        for (int j = 0; j < 4; j++)
#pragma unroll
            for (int r = 0; r < 4; r++) acc[i][j][r] = 0.f;

    int rA = t >> 2, kA = (t & 3) * 8;
    int rB0 = t >> 2, kB0 = (t & 3) * 8;
    int rB1 = 64 + (t >> 2), kB1 = (t & 3) * 8;

#define LOAD_STAGE(S, K0)                                                          \
    do {                                                                           \
        uint32_t sb_ = sbase + (uint32_t)(S) * 20480u;                             \
        const __nv_bfloat16* ga  = Ah + (size_t)(row0 + rA) * 1024 + (K0) + kA;    \
        const __nv_bfloat16* gb0 = Bh + (size_t)(col0 + rB0) * 1024 + (K0) + kB0;  \
        const __nv_bfloat16* gb1 = Bh + (size_t)(col0 + rB1) * 1024 + (K0) + kB1;  \
        uint32_t sa  = sb_ + (uint32_t)(rA * 40 + kA) * 2;                         \
        cpasync16(sa, ga);                                                         \
        if ((K0) >= 512) cpasync16(sa + 5120u, Al + (ga - Ah));                    \
        cpasync16(sb_ + 10240u + (uint32_t)(rB0 * 40 + kB0) * 2, gb0);             \
        cpasync16(sb_ + 10240u + (uint32_t)(rB1 * 40 + kB1) * 2, gb1);             \
    } while (0)

    LOAD_STAGE(0, 0);
    CP_COMMIT();
    LOAD_STAGE(1, 32);
    CP_COMMIT();

    int ar = lane & 15, ah8 = (lane >> 4) << 3;
    int bq = lane >> 3, br = lane & 7;
    int bro = ((bq >> 1) << 3) + br, bco = (bq & 1) << 3;

    for (int it = 0; it < 32; it++) {
        CP_WAIT1();
        __syncthreads();
        int p = it % 3;
        uint32_t aH = sbase + (uint32_t)p * 20480u;
        uint32_t aL = aH + 5120u;
        uint32_t bH = aH + 10240u;
#pragma unroll
        for (int kc = 0; kc < 2; kc++) {
            uint32_t a_h[2][4], b_h[4][2];
#pragma unroll
            for (int mf = 0; mf < 2; mf++) {
                uint32_t off = (uint32_t)((wm * 32 + mf * 16 + ar) * 40 + kc * 16 + ah8) * 2;
                LDSM4(a_h[mf], aH + off);
            }
#pragma unroll
            for (int nb = 0; nb < 2; nb++) {
                uint32_t off = (uint32_t)((wn * 32 + nb * 16 + bro) * 40 + kc * 16 + bco) * 2;
                uint32_t rh[4];
                LDSM4(rh, bH + off);
                b_h[2 * nb][0] = rh[0]; b_h[2 * nb][1] = rh[1];
                b_h[2 * nb + 1][0] = rh[2]; b_h[2 * nb + 1][1] = rh[3];
            }
#pragma unroll
            for (int mf = 0; mf < 2; mf++)
#pragma unroll
                for (int nf = 0; nf < 4; nf++)
                    MMA16816(acc[mf][nf], a_h[mf], b_h[nf][0], b_h[nf][1]);
            if (it >= 16) {   // adj^2 half: A-lo correction term
                uint32_t a_l[2][4];
#pragma unroll
                for (int mf = 0; mf < 2; mf++) {
                    uint32_t off = (uint32_t)((wm * 32 + mf * 16 + ar) * 40 + kc * 16 + ah8) * 2;
                    LDSM4(a_l[mf], aL + off);
                }
#pragma unroll
                for (int mf = 0; mf < 2; mf++)
#pragma unroll
                    for (int nf = 0; nf < 4; nf++)
                        MMA16816(acc[mf][nf], a_l[mf], b_h[nf][0], b_h[nf][1]);
            }
        }
        if (it < 30) LOAD_STAGE((it + 2) % 3, (it + 2) * 32);
        CP_COMMIT();
    }

    float mu0 = mu[0], mu1 = mu[1];
    int g = lane >> 2, tig = lane & 3;
#pragma unroll
    for (int mf = 0; mf < 2; mf++) {
#pragma unroll
        for (int h = 0; h < 2; h++) {
            int m = row0 + wm * 32 + mf * 16 + g + h * 8;
            int l = m % Lp;
            int bc = m / Lp;
            int co = bc & 15;
            float scale = s_scale[co], shift = s_shift[co], gb = s_gb[co];
            float r1 = mu0 * rsp[m] + mu1 * rsq[m];
            const float* idp  = idt + (size_t)m * 512;
            const float* resp = xprev + (size_t)(bc * Lprev + l + dil) * 512;
            float* op = xnew + (size_t)m * 512;
#pragma unroll
            for (int nf = 0; nf < 4; nf++) {
                int n = col0 + wn * 32 + nf * 8 + tig * 2;
                float v0 = acc[mf][nf][2 * h]     + r1 + idp[n]     + gb + resp[n];
                float v1 = acc[mf][nf][2 * h + 1] + r1 + idp[n + 1] + gb + resp[n + 1];
                op[n]     = v0 * scale + shift;
                op[n + 1] = v1 * scale + shift;
            }
        }
    }
}

// ---------------- tail MMA GEMM (Lp<=4): 32x128 tiles, centered B, 3-stage ----------------
// Stage: Ahi 2560 | Alo 2560 | Bhi 10240 => 15360B
#define MMA32_SMEM_BYTES 46080

__global__ void __launch_bounds__(256) k_mma32(
    const __nv_bfloat16* __restrict__ Ah, const __nv_bfloat16* __restrict__ Al,
    const __nv_bfloat16* __restrict__ Bh,
    const float* __restrict__ idt, const float* __restrict__ xprev, float* __restrict__ xnew,
    const float* __restrict__ rsp, const float* __restrict__ rsq, const float* __restrict__ mu,
    const float* __restrict__ gcb, const float* __restrict__ bng, const float* __restrict__ bnb,
    const float* __restrict__ bnm, const float* __restrict__ bnv,
    int Lp, int dil, int Lprev)
{
    extern __shared__ __align__(16) char smem_raw[];
    __shared__ float s_scale[16], s_shift[16], s_gb[16];
    uint32_t sbase = (uint32_t)__cvta_generic_to_shared(smem_raw);

    int t = threadIdx.x;
    if (t < 16) {
        float sc = bng[t] * rsqrtf(bnv[t] + 1e-5f);
        s_scale[t] = sc;
        s_shift[t] = bnb[t] - bnm[t] * sc;
        s_gb[t] = gcb[t];
    }

    int row0 = blockIdx.y * 32, col0 = blockIdx.x * 128;
    int warp = t >> 5, lane = t & 31;
    int wn = warp;

    float acc[2][2][4];
#pragma unroll
    for (int i = 0; i < 2; i++)
#pragma unroll
        for (int j = 0; j < 2; j++)
#pragma unroll
            for (int r = 0; r < 4; r++) acc[i][j][r] = 0.f;

    int tA = t & 127;
    int rA = tA >> 2, kA = (tA & 3) * 8;
    uint32_t aSel = (t < 128) ? 0u : 2560u;
    int rB0 = t >> 2, kB0 = (t & 3) * 8;
    int rB1 = 64 + (t >> 2), kB1 = (t & 3) * 8;

#define LOAD_STAGE32(S, K0)                                                        \
    do {                                                                           \
        uint32_t sb_ = sbase + (uint32_t)(S) * 15360u;                             \
        const __nv_bfloat16* gsrcA = (t < 128) ? Ah : Al;                          \
        if (t < 128 || (K0) >= 512)                                                \
            cpasync16(sb_ + aSel + (uint32_t)(rA * 40 + kA) * 2,                   \
                      gsrcA + (size_t)(row0 + rA) * 1024 + (K0) + kA);             \
        const __nv_bfloat16* gb0 = Bh + (size_t)(col0 + rB0) * 1024 + (K0) + kB0;  \
        const __nv_bfloat16* gb1 = Bh + (size_t)(col0 + rB1) * 1024 + (K0) + kB1;  \
        cpasync16(sb_ + 5120u + (uint32_t)(rB0 * 40 + kB0) * 2, gb0);              \
        cpasync16(sb_ + 5120u + (uint32_t)(rB1 * 40 + kB1) * 2, gb1);              \
    } while (0)

    LOAD_STAGE32(0, 0);
    CP_COMMIT();
    LOAD_STAGE32(1, 32);
    CP_COMMIT();

    int ar = lane & 15, ah8 = (lane >> 4) << 3;
    int bq = lane >> 3, br = lane & 7;
    int bro = ((bq >> 1) << 3) + br, bco = (bq & 1) << 3;

    for (int it = 0; it < 32; it++) {
        CP_WAIT1();
        __syncthreads();
        int p = it % 3;
        uint32_t aH = sbase + (uint32_t)p * 15360u;
        uint32_t aL = aH + 2560u;
        uint32_t bH = aH + 5120u;
#pragma unroll
        for (int kc = 0; kc < 2; kc++) {
            uint32_t a_h[2][4], b_h[2][2];
#pragma unroll
            for (int mf = 0; mf < 2; mf++) {
                uint32_t off = (uint32_t)((mf * 16 + ar) * 40 + kc * 16 + ah8) * 2;
                LDSM4(a_h[mf], aH + off);
            }
            {
                uint32_t off = (uint32_t)((wn * 16 + bro) * 40 + kc * 16 + bco) * 2;
                uint32_t rh[4];
                LDSM4(rh, bH + off);
                b_h[0][0] = rh[0]; b_h[0][1] = rh[1];
                b_h[1][0] = rh[2]; b_h[1][1] = rh[3];
            }
#pragma unroll
            for (int mf = 0; mf < 2; mf++)
#pragma unroll
                for (int nf = 0; nf < 2; nf++)
                    MMA16816(acc[mf][nf], a_h[mf], b_h[nf][0], b_h[nf][1]);
            if (it >= 16) {
                uint32_t a_l[2][4];
#pragma unroll
                for (int mf = 0; mf < 2; mf++) {
                    uint32_t off = (uint32_t)((mf * 16 + ar) * 40 + kc * 16 + ah8) * 2;
                    LDSM4(a_l[mf], aL + off);
                }
#pragma unroll
                for (int mf = 0; mf < 2; mf++)
#pragma unroll
                    for (int nf = 0; nf < 2; nf++)
                        MMA16816(acc[mf][nf], a_l[mf], b_h[nf][0], b_h[nf][1]);
            }
        }
        if (it < 30) LOAD_STAGE32((it + 2) % 3, (it + 2) * 32);
        CP_COMMIT();
    }

    float mu0 = mu[0], mu1 = mu[1];
    int g = lane >> 2, tig = lane & 3;
#pragma unroll
    for (int mf = 0; mf < 2; mf++) {
#pragma unroll
        for (int h = 0; h < 2; h++) {
            int m = row0 + mf * 16 + g + h * 8;
            int l = m % Lp;
            int bc = m / Lp;
            int co = bc & 15;
            float scale = s_scale[co], shift = s_shift[co], gb = s_gb[co];
            float r1 = mu0 * rsp[m] + mu1 * rsq[m];
            const float* idp  = idt + (size_t)m * 512;
            const float* resp = xprev + (size_t)(bc * Lprev + l + dil) * 512;
            float* op = xnew + (size_t)m * 512;
#pragma unroll
            for (int nf = 0; nf < 2; nf++) {
                int n = col0 + wn * 16 + nf * 8 + tig * 2;
                float v0 = acc[mf][nf][2 * h]     + r1 + idp[n]     + gb + resp[n];
                float v1 = acc[mf][nf][2 * h + 1] + r1 + idp[n + 1] + gb + resp[n + 1];
                op[n]     = v0 * scale + shift;
                op[n + 1] = v1 * scale + shift;
            }
        }
    }
}

// ---------------- K9: end convs ----------------
__global__ void k_end(const float* __restrict__ skip,
                      const float* __restrict__ w1, const float* __restrict__ b1,
                      const float* __restrict__ w2, const float* __restrict__ b2,
                      float* __restrict__ out)
{
    int tid = blockIdx.x * 128 + threadIdx.x;
    int b = tid >> 9, v = tid & 511;
    float s[16];
#pragma unroll
    for (int c = 0; c < 16; c++) s[c] = fmaxf(skip[(b * 16 + c) * 512 + v], 0.f);
    float e1[16];
#pragma unroll
    for (int c = 0; c < 16; c++) {
        float a = b1[c];
#pragma unroll
        for (int ci = 0; ci < 16; ci++) a += w1[c * 16 + ci] * s[ci];
        e1[c] = fmaxf(a, 0.f);
    }
#pragma unroll
    for (int h = 0; h < 12; h++) {
        float a = b2[h];
#pragma unroll
        for (int c = 0; c < 16; c++) a += w2[h * 16 + c] * e1[c];
        out[(b * 12 + h) * 512 + v] = a;
    }
}

// ======================== host orchestration ========================
extern "C" void kernel_launch(void* const* d_in, const int* in_sizes, int n_in,
                              void* d_out, int out_size)
{
    const float* input  = (const float*)d_in[0];
    const float* startW = (const float*)d_in[1];
    const float* startb = (const float*)d_in[2];
    const float* filtW  = (const float*)d_in[3];
    const float* filtb  = (const float*)d_in[4];
    const float* gateW  = (const float*)d_in[5];
    const float* gateb  = (const float*)d_in[6];
    const float* skipW  = (const float*)d_in[7];
    const float* skipb  = (const float*)d_in[8];
    const float* gconvW = (const float*)d_in[9];
    const float* gconvb = (const float*)d_in[10];
    const float* bng    = (const float*)d_in[11];
    const float* bnb    = (const float*)d_in[12];
    const float* bnm    = (const float*)d_in[13];
    const float* bnv    = (const float*)d_in[14];
    const float* e1W    = (const float*)d_in[15];
    const float* e1b    = (const float*)d_in[16];
    const float* e2W    = (const float*)d_in[17];
    const float* e2b    = (const float*)d_in[18];
    const float* linW   = (const float*)d_in[19];
    const float* linb   = (const float*)d_in[20];
    const float* f1W    = (const float*)d_in[21];
    const float* f1b    = (const float*)d_in[22];
    const float* f2W    = (const float*)d_in[23];
    const float* f2b    = (const float*)d_in[24];
    const float* f3W    = (const float*)d_in[25];
    const float* f3b    = (const float*)d_in[26];
    float* out = (float*)d_out;

    float *p_real, *p_img, *p_iffp, *p_AA2, *p_bs;
    float *p_xa, *p_xb, *p_idt, *p_skip, *p_rsp, *p_rsq, *p_partA, *p_partB, *p_mu;
    __nv_bfloat16 *p_Fh, *p_Fl, *p_Wh, *p_Wl, *p_Bth, *p_PQh, *p_PQl;
    cudaGetSymbolAddress((void**)&p_real, g_real);
    cudaGetSymbolAddress((void**)&p_img,  g_img);
    cudaGetSymbolAddress((void**)&p_iffp, g_iffp);
    cudaGetSymbolAddress((void**)&p_AA2,  g_AA2);
    cudaGetSymbolAddress((void**)&p_Fh,   g_Fh);
    cudaGetSymbolAddress((void**)&p_Fl,   g_Fl);
    cudaGetSymbolAddress((void**)&p_Wh,   g_Wh);
    cudaGetSymbolAddress((void**)&p_Wl,   g_Wl);
    cudaGetSymbolAddress((void**)&p_bs,   g_bs);
    cudaGetSymbolAddress((void**)&p_Bth,  g_Bth);
    cudaGetSymbolAddress((void**)&p_xa,   g_xa);
    cudaGetSymbolAddress((void**)&p_xb,   g_xb);
    cudaGetSymbolAddress((void**)&p_PQh,  g_PQh);
    cudaGetSymbolAddress((void**)&p_PQl,  g_PQl);
    cudaGetSymbolAddress((void**)&p_idt,  g_idt);
    cudaGetSymbolAddress((void**)&p_skip, g_skip);
    cudaGetSymbolAddress((void**)&p_rsp,  g_rsp);
    cudaGetSymbolAddress((void**)&p_rsq,  g_rsq);
    cudaGetSymbolAddress((void**)&p_partA, g_partA);
    cudaGetSymbolAddress((void**)&p_partB, g_partB);
    cudaGetSymbolAddress((void**)&p_mu,   g_mu);

    static int smem_set = 0;
    if (!smem_set) {
        cudaFuncSetAttribute(k_mma, cudaFuncAttributeMaxDynamicSharedMemorySize, MMA_SMEM_BYTES);
        cudaFuncSetAttribute(k_mma32, cudaFuncAttributeMaxDynamicSharedMemorySize, MMA32_SMEM_BYTES);
        cudaFuncSetAttribute(k_adjmma, cudaFuncAttributeMaxDynamicSharedMemorySize, ADJ_SMEM);
        smem_set = 1;
    }

    // ---- graph learner ----
    k_dft<<<256, 64>>>(input, linW, linb, p_real, p_img, p_Fh, p_Fl);
    k_iff_part<<<dim3(32, 16), 512>>>(p_real, p_img, p_iffp);
    k_iff_red<<<1280, 256>>>(p_iffp, p_Fh, p_Fl);
    k_wprep<<<64, 256>>>(f1W, f1b, f2W, f2b, f3W, f3b, p_Wh, p_Wl, p_bs);
    float* adj_out = (out_size >= Bz * HORz * Vz + Vz * Vz) ? out + Bz * HORz * Vz : nullptr;
    k_adjmma<<<dim3(4, 128), 256, ADJ_SMEM>>>(p_Fh, p_Fl, p_Wh, p_Wl, p_bs, p_AA2, adj_out, p_partA);
    k_gemm_plain<<<dim3(8, 8), 256>>>(p_AA2, p_AA2, p_AA2 + Vz * Vz, 512, p_partB);
    k_mean<<<1, 256>>>(p_partA, p_partB, p_mu);
    k_prepB<<<dim3(16, 32), dim3(32, 8)>>>(p_AA2, p_mu, p_Bth);

    // ---- trunk ----
    k_start<<<13312, 256>>>(input, startW, startb, p_xa);

    float* xc = p_xa;
    float* xn = p_xb;
    int L = RFz;
    const int dils[NLz] = {1, 2, 1, 2, 1, 2, 1, 2};
    for (int i = 0; i < NLz; i++) {
        int d = dils[i];
        int Lp = L - d;
        k_fused<<<Bz * Lp, 256>>>(xc, filtW + i * 512, filtb + i * 16,
                                  gateW + i * 512, gateb + i * 16,
                                  gconvW + i * 1024, skipW + i * 256, skipb + i * 16,
                                  p_PQh, p_PQl, p_idt, p_skip, p_rsp, p_rsq, L, d, (i == 0) ? 1 : 0);
        int M = Bz * CHz * Lp;
        if (Lp > 4) {
            k_mma<<<dim3(4, M / 64), 256, MMA_SMEM_BYTES>>>(p_PQh, p_PQl, p_Bth,
                                                            p_idt, xc, xn, p_rsp, p_rsq, p_mu,
                                                            gconvb + i * 16, bng + i * 16, bnb + i * 16,
                                                            bnm + i * 16, bnv + i * 16, Lp, d, L);
        } else {
            k_mma32<<<dim3(4, M / 32), 256, MMA32_SMEM_BYTES>>>(p_PQh, p_PQl, p_Bth,
                                                                p_idt, xc, xn, p_rsp, p_rsq, p_mu,
                                                                gconvb + i * 16, bng + i * 16, bnb + i * 16,
                                                                bnm + i * 16, bnv + i * 16, Lp, d, L);
        }
        float* tmp = xc; xc = xn; xn = tmp;
        L = Lp;
    }

    k_end<<<128, 128>>>(p_skip, e1W, e1b, e2W, e2b, out);
}